// round 11
// baseline (speedup 1.0000x reference)
#include <cuda_runtime.h>
#include <math.h>
#include <stdint.h>

// Problem dims
#define Dm   1024
#define Sseq 1024
#define Bb   2
#define Hh   16
#define Ee   8
#define Vv   4096
#define TOK  (Bb*Sseq)
#define EPSV 1e-5f

// ---------------- device scratch ------------------------------------------------
__device__ float g_qkv[3*TOK*Dm];
__device__ float g_attn[TOK*Dm];
__device__ float g_proj[TOK*Dm];
__device__ float g_normed[TOK*Dm];
__device__ float g_h[(size_t)Ee*TOK*Vv];
__device__ float g_eo[(size_t)Ee*TOK*Dm];
__device__ float g_coef[TOK*Ee];
// transposed weights (N-major: Wt[n][k])
__device__ float g_wqkvt[3*Dm*Dm];
__device__ float g_bqkv[3*Dm];
__device__ float g_wot[Dm*Dm];
__device__ float g_w1t[(size_t)Ee*Vv*Dm];
__device__ float g_w2t[(size_t)Ee*Dm*Vv];

// ---------------- helpers -------------------------------------------------------
__device__ __forceinline__ uint32_t f2tf(float f) {
    uint32_t u; asm("cvt.rna.tf32.f32 %0, %1;" : "=r"(u) : "f"(f)); return u;
}
__device__ __forceinline__ void mma_tf32(float* c, const uint32_t* a, const uint32_t* b) {
    asm volatile("mma.sync.aligned.m16n8k8.row.col.f32.tf32.tf32.f32 "
        "{%0,%1,%2,%3}, {%4,%5,%6,%7}, {%8,%9}, {%0,%1,%2,%3};"
        : "+f"(c[0]), "+f"(c[1]), "+f"(c[2]), "+f"(c[3])
        : "r"(a[0]), "r"(a[1]), "r"(a[2]), "r"(a[3]), "r"(b[0]), "r"(b[1]));
}

// SMEM geometry for mma_gemm: padded stride 36 words per 32-float row.
#define LDS_STRIDE 36
#define TILE_WORDS (128 * LDS_STRIDE)            // 4608 words per buffer
#define SMEM_GEMM_BYTES (4 * TILE_WORDS * 4 * 2) // 73728

// ---------------- tensor-core tf32 GEMM: C[M,N] = A[M,K] @ Bt[N,K]^T + bias -----
// R5 pipeline (register-staged prefetch, double-buffered smem),
// now at 2 CTAs/SM via __launch_bounds__ minBlocksPerMultiprocessor.
template<bool RELU>
__global__ __launch_bounds__(256, 2) void mma_gemm(
    const float* __restrict__ A, const float* __restrict__ Bt,
    const float* __restrict__ bias, float* __restrict__ C,
    int M, int N, int K,
    long long sA, long long sB, long long sBias, long long sC)
{
    extern __shared__ uint32_t sh[];
    uint32_t* Asm = sh;                    // [2][TILE_WORDS]
    uint32_t* Bsm = sh + 2 * TILE_WORDS;   // [2][TILE_WORDS]

    const int t = threadIdx.x;
    const int lane = t & 31, w = t >> 5;
    const int warp_m = w >> 2;
    const int warp_n = w & 3;
    const int lr = lane >> 2;
    const int lc = lane & 3;

    const int eb = blockIdx.z;
    A    += (size_t)eb * sA;
    Bt   += (size_t)eb * sB;
    bias += (size_t)eb * sBias;
    C    += (size_t)eb * sC;
    const int n0 = blockIdx.x * 128, m0 = blockIdx.y * 128;

    const int kc = (t & 7) * 4;
    const int r0 = t >> 3;
    const float* Ag = A  + (size_t)(m0 + r0) * K + kc;
    const float* Bg = Bt + (size_t)(n0 + r0) * K + kc;
    const int sts_base = r0 * LDS_STRIDE + kc;

    float acc[4][4][4];
    #pragma unroll
    for (int mt = 0; mt < 4; mt++)
        #pragma unroll
        for (int nt = 0; nt < 4; nt++)
            #pragma unroll
            for (int i = 0; i < 4; i++) acc[mt][nt][i] = 0.f;

    const int nst = K >> 5;

    {
        float4 pa[4], pb[4];
        #pragma unroll
        for (int i = 0; i < 4; i++) {
            pa[i] = *(const float4*)(Ag + (size_t)(32 * i) * K);
            pb[i] = *(const float4*)(Bg + (size_t)(32 * i) * K);
        }
        #pragma unroll
        for (int i = 0; i < 4; i++) {
            uint32_t* da = Asm + sts_base + i * 32 * LDS_STRIDE;
            uint32_t* db = Bsm + sts_base + i * 32 * LDS_STRIDE;
            da[0] = f2tf(pa[i].x); da[1] = f2tf(pa[i].y);
            da[2] = f2tf(pa[i].z); da[3] = f2tf(pa[i].w);
            db[0] = f2tf(pb[i].x); db[1] = f2tf(pb[i].y);
            db[2] = f2tf(pb[i].z); db[3] = f2tf(pb[i].w);
        }
    }
    __syncthreads();

    const int a_off = (warp_m * 64 + lr) * LDS_STRIDE + lc;
    const int b_off = (warp_n * 32 + lr) * LDS_STRIDE + lc;

    for (int s = 0; s < nst; s++) {
        const int buf = s & 1;
        const bool more = (s + 1) < nst;
        float4 pa[4], pb[4];
        if (more) {
            const float* ag = Ag + (size_t)(32 * (s + 1));
            const float* bg = Bg + (size_t)(32 * (s + 1));
            #pragma unroll
            for (int i = 0; i < 4; i++) {
                pa[i] = *(const float4*)(ag + (size_t)(32 * i) * K);
                pb[i] = *(const float4*)(bg + (size_t)(32 * i) * K);
            }
        }

        const uint32_t* Apt = Asm + buf * TILE_WORDS + a_off;
        const uint32_t* Bpt = Bsm + buf * TILE_WORDS + b_off;
        #pragma unroll
        for (int kk = 0; kk < 4; kk++) {
            const int k = kk * 8;
            uint32_t af[4][4], bf[4][2];
            #pragma unroll
            for (int mt = 0; mt < 4; mt++) {
                af[mt][0] = Apt[(mt * 16    ) * LDS_STRIDE + k];
                af[mt][1] = Apt[(mt * 16 + 8) * LDS_STRIDE + k];
                af[mt][2] = Apt[(mt * 16    ) * LDS_STRIDE + k + 4];
                af[mt][3] = Apt[(mt * 16 + 8) * LDS_STRIDE + k + 4];
            }
            #pragma unroll
            for (int nt = 0; nt < 4; nt++) {
                bf[nt][0] = Bpt[(nt * 8) * LDS_STRIDE + k];
                bf[nt][1] = Bpt[(nt * 8) * LDS_STRIDE + k + 4];
            }
            #pragma unroll
            for (int mt = 0; mt < 4; mt++)
                #pragma unroll
                for (int nt = 0; nt < 4; nt++)
                    mma_tf32(acc[mt][nt], af[mt], bf[nt]);
        }

        if (more) {
            const int nb = (s + 1) & 1;
            #pragma unroll
            for (int i = 0; i < 4; i++) {
                uint32_t* da = Asm + nb * TILE_WORDS + sts_base + i * 32 * LDS_STRIDE;
                uint32_t* db = Bsm + nb * TILE_WORDS + sts_base + i * 32 * LDS_STRIDE;
                da[0] = f2tf(pa[i].x); da[1] = f2tf(pa[i].y);
                da[2] = f2tf(pa[i].z); da[3] = f2tf(pa[i].w);
                db[0] = f2tf(pb[i].x); db[1] = f2tf(pb[i].y);
                db[2] = f2tf(pb[i].z); db[3] = f2tf(pb[i].w);
            }
        }
        __syncthreads();
    }

    #pragma unroll
    for (int mt = 0; mt < 4; mt++) {
        const int m = m0 + warp_m * 64 + mt * 16 + lr;
        #pragma unroll
        for (int nt = 0; nt < 4; nt++) {
            const int n = n0 + warp_n * 32 + nt * 8 + lc * 2;
            const float b0 = bias[n], b1 = bias[n + 1];
            float o0 = acc[mt][nt][0] + b0, o1 = acc[mt][nt][1] + b1;
            float o2 = acc[mt][nt][2] + b0, o3 = acc[mt][nt][3] + b1;
            if (RELU) {
                o0 = fmaxf(o0, 0.f); o1 = fmaxf(o1, 0.f);
                o2 = fmaxf(o2, 0.f); o3 = fmaxf(o3, 0.f);
            }
            *(float2*)(C + (size_t)m * N + n)       = make_float2(o0, o1);
            *(float2*)(C + (size_t)(m + 8) * N + n) = make_float2(o2, o3);
        }
    }
}

// ---------------- fast transpose: out[C,R] = in[R,C]^T, float4 both sides --------
__global__ __launch_bounds__(256) void transpose64(
    const float* __restrict__ in, float* __restrict__ out, int R, int C)
{
    __shared__ float s[64][68];
    const size_t eoff = (size_t)blockIdx.z * (size_t)R * C;
    in += eoff; out += eoff;
    const int c0 = blockIdx.x * 64, r0 = blockIdx.y * 64;
    const int t = threadIdx.x;
    #pragma unroll
    for (int i = 0; i < 4; i++) {
        int idx = t + 256 * i;
        int row = idx >> 4, cx = (idx & 15) * 4;
        float4 v = *(const float4*)(in + (size_t)(r0 + row) * C + c0 + cx);
        s[cx + 0][row] = v.x; s[cx + 1][row] = v.y;
        s[cx + 2][row] = v.z; s[cx + 3][row] = v.w;
    }
    __syncthreads();
    #pragma unroll
    for (int i = 0; i < 4; i++) {
        int idx = t + 256 * i;
        int orow = idx >> 4, rx = (idx & 15) * 4;
        float4 o = *(float4*)&s[orow][rx];
        *(float4*)(out + (size_t)(c0 + orow) * R + r0 + rx) = o;
    }
}

// ---------------- concat 3 bias vectors ------------------------------------------
__global__ void concat3(const float* __restrict__ a, const float* __restrict__ b,
                        const float* __restrict__ c, float* __restrict__ o, int n)
{
    int i = blockIdx.x * 256 + threadIdx.x;
    if (i < n) { o[i] = a[i]; o[i + n] = b[i]; o[i + 2 * n] = c[i]; }
}

// ---------------- fused flash attention (tf32 mma) -------------------------------
#define FA_QS   0                  // [128][68]
#define FA_KS   8704               // [128][68]
#define FA_VS   17408              // [128][72]
#define FA_PS   26624              // [128][132]
#define FA_RED  43520              // [128][4]
#define FA_MS   44032
#define FA_LS   44160
#define FA_AL   44288
#define FA_WORDS 44416
#define FA_BYTES (FA_WORDS * 4)

__global__ __launch_bounds__(256) void fused_attn(
    const float* __restrict__ q, const float* __restrict__ k,
    const float* __restrict__ v, float* __restrict__ out)
{
    extern __shared__ float fsh[];
    uint32_t* Qs = (uint32_t*)(fsh + FA_QS);
    uint32_t* Ks = (uint32_t*)(fsh + FA_KS);
    uint32_t* Vs = (uint32_t*)(fsh + FA_VS);
    uint32_t* Ps = (uint32_t*)(fsh + FA_PS);
    float* red   = fsh + FA_RED;
    float* m_s   = fsh + FA_MS;
    float* l_s   = fsh + FA_LS;
    float* al_s  = fsh + FA_AL;

    const int t = threadIdx.x;
    const int lane = t & 31, w = t >> 5;
    const int warp_m = w >> 2;
    const int warp_n = w & 3;
    const int ow_m = w >> 1;
    const int ow_n = w & 1;
    const int lr = lane >> 2, lc = lane & 3;

    const int q0 = blockIdx.x * 128;
    const int bh = blockIdx.y, b = bh >> 4, h = bh & 15;
    const size_t qbase = (size_t)(b * Sseq + q0) * Dm + h * 64;
    const size_t kvbase = (size_t)(b * Sseq) * Dm + h * 64;

    #pragma unroll
    for (int i = 0; i < 8; i++) {
        int idx = t + 256 * i;
        int row = idx >> 4, c4 = (idx & 15) * 4;
        float4 qv = *(const float4*)(q + qbase + (size_t)row * Dm + c4);
        uint32_t* d = Qs + row * 68 + c4;
        d[0] = f2tf(qv.x); d[1] = f2tf(qv.y); d[2] = f2tf(qv.z); d[3] = f2tf(qv.w);
    }
    if (t < 128) { m_s[t] = -1e30f; l_s[t] = 0.f; }

    float acc_o[2][4][4];
    #pragma unroll
    for (int mt = 0; mt < 2; mt++)
        #pragma unroll
        for (int nt = 0; nt < 4; nt++)
            #pragma unroll
            for (int i = 0; i < 4; i++) acc_o[mt][nt][i] = 0.f;

    const int a_off = (warp_m * 64 + lr) * 68 + lc;
    const int b_off = (warp_n * 32 + lr) * 68 + lc;
    const int p_off = (ow_m * 32 + lr) * 132 + lc;

    for (int kt = 0; kt < 8; kt++) {
        const size_t kb = kvbase + (size_t)(kt * 128) * Dm;
        #pragma unroll
        for (int i = 0; i < 8; i++) {
            int idx = t + 256 * i;
            int row = idx >> 4, c4 = (idx & 15) * 4;
            float4 kv = *(const float4*)(k + kb + (size_t)row * Dm + c4);
            float4 vv = *(const float4*)(v + kb + (size_t)row * Dm + c4);
            uint32_t* dk = Ks + row * 68 + c4;
            uint32_t* dv = Vs + row * 72 + c4;
            dk[0] = f2tf(kv.x); dk[1] = f2tf(kv.y); dk[2] = f2tf(kv.z); dk[3] = f2tf(kv.w);
            dv[0] = f2tf(vv.x); dv[1] = f2tf(vv.y); dv[2] = f2tf(vv.z); dv[3] = f2tf(vv.w);
        }
        __syncthreads();

        float acc_s[4][4][4];
        #pragma unroll
        for (int mt = 0; mt < 4; mt++)
            #pragma unroll
            for (int nt = 0; nt < 4; nt++)
                #pragma unroll
                for (int i = 0; i < 4; i++) acc_s[mt][nt][i] = 0.f;
        #pragma unroll
        for (int kk = 0; kk < 8; kk++) {
            const int kx = kk * 8;
            uint32_t af[4][4], bf[4][2];
            #pragma unroll
            for (int mt = 0; mt < 4; mt++) {
                af[mt][0] = Qs[a_off + (mt * 16    ) * 68 + kx];
                af[mt][1] = Qs[a_off + (mt * 16 + 8) * 68 + kx];
                af[mt][2] = Qs[a_off + (mt * 16    ) * 68 + kx + 4];
                af[mt][3] = Qs[a_off + (mt * 16 + 8) * 68 + kx + 4];
            }
            #pragma unroll
            for (int nt = 0; nt < 4; nt++) {
                bf[nt][0] = Ks[b_off + (nt * 8) * 68 + kx];
                bf[nt][1] = Ks[b_off + (nt * 8) * 68 + kx + 4];
            }
            #pragma unroll
            for (int mt = 0; mt < 4; mt++)
                #pragma unroll
                for (int nt = 0; nt < 4; nt++)
                    mma_tf32(acc_s[mt][nt], af[mt], bf[nt]);
        }

        #pragma unroll
        for (int mt = 0; mt < 4; mt++) {
            #pragma unroll
            for (int half = 0; half < 2; half++) {
                float pm = -1e30f;
                #pragma unroll
                for (int nt = 0; nt < 4; nt++) {
                    pm = fmaxf(pm, acc_s[mt][nt][half * 2]);
                    pm = fmaxf(pm, acc_s[mt][nt][half * 2 + 1]);
                }
                pm = fmaxf(pm, __shfl_xor_sync(0xffffffffu, pm, 1));
                pm = fmaxf(pm, __shfl_xor_sync(0xffffffffu, pm, 2));
                if (lc == 0)
                    red[(warp_m * 64 + mt * 16 + half * 8 + lr) * 4 + warp_n] = pm;
            }
        }
        __syncthreads();

        if (t < 128) {
            float tm = fmaxf(fmaxf(red[t * 4 + 0], red[t * 4 + 1]),
                             fmaxf(red[t * 4 + 2], red[t * 4 + 3])) * 0.125f;
            float mo = m_s[t];
            float mn = fmaxf(mo, tm);
            al_s[t] = __expf(mo - mn);
            m_s[t]  = mn;
        }
        __syncthreads();

        #pragma unroll
        for (int mt = 0; mt < 4; mt++) {
            #pragma unroll
            for (int half = 0; half < 2; half++) {
                const int row = warp_m * 64 + mt * 16 + half * 8 + lr;
                const float mrow = m_s[row];
                float ps = 0.f;
                #pragma unroll
                for (int nt = 0; nt < 4; nt++) {
                    const int col = warp_n * 32 + nt * 8 + lc * 2;
                    float p0 = __expf(acc_s[mt][nt][half * 2]     * 0.125f - mrow);
                    float p1 = __expf(acc_s[mt][nt][half * 2 + 1] * 0.125f - mrow);
                    ps += p0 + p1;
                    Ps[row * 132 + col]     = f2tf(p0);
                    Ps[row * 132 + col + 1] = f2tf(p1);
                }
                ps += __shfl_xor_sync(0xffffffffu, ps, 1);
                ps += __shfl_xor_sync(0xffffffffu, ps, 2);
                if (lc == 0) red[row * 4 + warp_n] = ps;
            }
        }
        #pragma unroll
        for (int mt = 0; mt < 2; mt++) {
            const int row0 = ow_m * 32 + mt * 16 + lr;
            const float a0 = al_s[row0], a1 = al_s[row0 + 8];
            #pragma unroll
            for (int nt = 0; nt < 4; nt++) {
                acc_o[mt][nt][0] *= a0; acc_o[mt][nt][1] *= a0;
                acc_o[mt][nt][2] *= a1; acc_o[mt][nt][3] *= a1;
            }
        }
        __syncthreads();

        if (t < 128)
            l_s[t] = l_s[t] * al_s[t]
                   + red[t * 4 + 0] + red[t * 4 + 1] + red[t * 4 + 2] + red[t * 4 + 3];

        #pragma unroll
        for (int kk = 0; kk < 16; kk++) {
            const int kx = kk * 8;
            uint32_t af[2][4], bf[4][2];
            #pragma unroll
            for (int mt = 0; mt < 2; mt++) {
                af[mt][0] = Ps[p_off + (mt * 16    ) * 132 + kx];
                af[mt][1] = Ps[p_off + (mt * 16 + 8) * 132 + kx];
                af[mt][2] = Ps[p_off + (mt * 16    ) * 132 + kx + 4];
                af[mt][3] = Ps[p_off + (mt * 16 + 8) * 132 + kx + 4];
            }
            #pragma unroll
            for (int nt = 0; nt < 4; nt++) {
                const int n = ow_n * 32 + nt * 8 + lr;
                bf[nt][0] = Vs[(kx + lc) * 72 + n];
                bf[nt][1] = Vs[(kx + lc + 4) * 72 + n];
            }
            #pragma unroll
            for (int mt = 0; mt < 2; mt++)
                #pragma unroll
                for (int nt = 0; nt < 4; nt++)
                    mma_tf32(acc_o[mt][nt], af[mt], bf[nt]);
        }
        __syncthreads();
    }

    #pragma unroll
    for (int mt = 0; mt < 2; mt++) {
        const int row0 = ow_m * 32 + mt * 16 + lr;
        const float i0 = 1.f / l_s[row0], i1 = 1.f / l_s[row0 + 8];
        #pragma unroll
        for (int nt = 0; nt < 4; nt++) {
            const int col = ow_n * 32 + nt * 8 + lc * 2;
            float* o0 = out + (size_t)(b * Sseq + q0 + row0) * Dm + h * 64 + col;
            float* o1 = out + (size_t)(b * Sseq + q0 + row0 + 8) * Dm + h * 64 + col;
            *(float2*)o0 = make_float2(acc_o[mt][nt][0] * i0, acc_o[mt][nt][1] * i0);
            *(float2*)o1 = make_float2(acc_o[mt][nt][2] * i1, acc_o[mt][nt][3] * i1);
        }
    }
}

// ---------------- block reduction helper -----------------------------------------
__device__ __forceinline__ float block_sum256(float v, float* red) {
    #pragma unroll
    for (int o = 16; o > 0; o >>= 1) v += __shfl_xor_sync(0xffffffffu, v, o);
    if ((threadIdx.x & 31) == 0) red[threadIdx.x >> 5] = v;
    __syncthreads();
    float s = red[0];
    #pragma unroll
    for (int i = 1; i < 8; i++) s += red[i];
    __syncthreads();
    return s;
}

// ---------------- residual add + layernorm ---------------------------------------
__global__ __launch_bounds__(256) void add_ln(
    const float* __restrict__ a, const float* __restrict__ b,
    const float* __restrict__ gamma, const float* __restrict__ beta,
    float* __restrict__ out)
{
    __shared__ float red[8];
    const int t = threadIdx.x;
    const size_t base = (size_t)blockIdx.x * Dm;
    float4 va = ((const float4*)(a + base))[t];
    float4 vb = ((const float4*)(b + base))[t];
    float4 s = make_float4(va.x+vb.x, va.y+vb.y, va.z+vb.z, va.w+vb.w);
    float tot = block_sum256(s.x + s.y + s.z + s.w, red);
    float mu = tot * (1.f / Dm);
    float lq = (s.x-mu)*(s.x-mu) + (s.y-mu)*(s.y-mu) + (s.z-mu)*(s.z-mu) + (s.w-mu)*(s.w-mu);
    float var = block_sum256(lq, red) * (1.f / Dm);
    float rstd = rsqrtf(var + EPSV);
    float4 gg = ((const float4*)gamma)[t];
    float4 bt = ((const float4*)beta)[t];
    float4 o;
    o.x = (s.x - mu) * rstd * gg.x + bt.x;
    o.y = (s.y - mu) * rstd * gg.y + bt.y;
    o.z = (s.z - mu) * rstd * gg.z + bt.z;
    o.w = (s.w - mu) * rstd * gg.w + bt.w;
    ((float4*)(out + base))[t] = o;
}

// ---------------- gate coefficients ----------------------------------------------
__global__ __launch_bounds__(256) void gate_coef(
    const float* __restrict__ xn, const float* __restrict__ gw, float* __restrict__ coef)
{
    __shared__ float red[16][9];
    const int t = threadIdx.x, tkn = blockIdx.x;
    float acc[16];
    #pragma unroll
    for (int ge = 0; ge < 16; ge++) acc[ge] = 0.f;
    for (int d = t; d < Dm; d += 256) {
        float xv = xn[(size_t)tkn*Dm + d];
        #pragma unroll
        for (int ge = 0; ge < 16; ge++)
            acc[ge] = fmaf(xv, gw[(size_t)(ge >> 3)*Dm*Ee + (size_t)d*Ee + (ge & 7)], acc[ge]);
    }
    #pragma unroll
    for (int ge = 0; ge < 16; ge++) {
        float v = acc[ge];
        #pragma unroll
        for (int o = 16; o > 0; o >>= 1) v += __shfl_xor_sync(0xffffffffu, v, o);
        if ((t & 31) == 0) red[ge][t >> 5] = v;
    }
    __syncthreads();
    if (t == 0) {
        float logits[16];
        #pragma unroll
        for (int ge = 0; ge < 16; ge++) {
            float s = 0.f;
            #pragma unroll
            for (int w2 = 0; w2 < 8; w2++) s += red[ge][w2];
            logits[ge] = s;
        }
        float c[8];
        #pragma unroll
        for (int e2 = 0; e2 < 8; e2++) c[e2] = 0.f;
        #pragma unroll
        for (int g = 0; g < 2; g++) {
            float m = logits[g*8];
            #pragma unroll
            for (int e2 = 1; e2 < 8; e2++) m = fmaxf(m, logits[g*8+e2]);
            float s = 0.f, pe[8];
            #pragma unroll
            for (int e2 = 0; e2 < 8; e2++) { pe[e2] = __expf(logits[g*8+e2] - m); s += pe[e2]; }
            float inv = 1.f / s;
            #pragma unroll
            for (int e2 = 0; e2 < 8; e2++) c[e2] += pe[e2] * inv;
        }
        #pragma unroll
        for (int e2 = 0; e2 < 8; e2++) coef[(size_t)tkn*8 + e2] = c[e2] * 0.5f;
    }
}

// ---------------- combine + residual + LN2 ---------------------------------------
__global__ __launch_bounds__(256) void combine_ln(
    const float* __restrict__ eo, const float* __restrict__ coef,
    const float* __restrict__ xn,
    const float* __restrict__ gamma, const float* __restrict__ beta,
    float* __restrict__ out)
{
    __shared__ float red[8];
    __shared__ float cf[8];
    const int t = threadIdx.x, tkn = blockIdx.x;
    if (t < 8) cf[t] = coef[(size_t)tkn*8 + t];
    __syncthreads();
    const size_t base = (size_t)tkn * Dm;
    float4 s = ((const float4*)(xn + base))[t];
    #pragma unroll
    for (int e2 = 0; e2 < 8; e2++) {
        float4 v = ((const float4*)(eo + ((size_t)e2*TOK + tkn)*Dm))[t];
        float c = cf[e2];
        s.x = fmaf(c, v.x, s.x); s.y = fmaf(c, v.y, s.y);
        s.z = fmaf(c, v.z, s.z); s.w = fmaf(c, v.w, s.w);
    }
    float tot = block_sum256(s.x + s.y + s.z + s.w, red);
    float mu = tot * (1.f / Dm);
    float lq = (s.x-mu)*(s.x-mu) + (s.y-mu)*(s.y-mu) + (s.z-mu)*(s.z-mu) + (s.w-mu)*(s.w-mu);
    float var = block_sum256(lq, red) * (1.f / Dm);
    float rstd = rsqrtf(var + EPSV);
    float4 gg = ((const float4*)gamma)[t];
    float4 bt = ((const float4*)beta)[t];
    float4 o;
    o.x = (s.x - mu) * rstd * gg.x + bt.x;
    o.y = (s.y - mu) * rstd * gg.y + bt.y;
    o.z = (s.z - mu) * rstd * gg.z + bt.z;
    o.w = (s.w - mu) * rstd * gg.w + bt.w;
    ((float4*)(out + base))[t] = o;
}

// ---------------- launch ----------------------------------------------------------
extern "C" void kernel_launch(void* const* d_in, const int* in_sizes, int n_in,
                              void* d_out, int out_size)
{
    const float* x     = (const float*)d_in[0];
    const float* wq    = (const float*)d_in[1];
    const float* bq    = (const float*)d_in[2];
    const float* wk    = (const float*)d_in[3];
    const float* bk    = (const float*)d_in[4];
    const float* wv    = (const float*)d_in[5];
    const float* bv    = (const float*)d_in[6];
    const float* wo    = (const float*)d_in[7];
    const float* bo    = (const float*)d_in[8];
    const float* ln1g  = (const float*)d_in[9];
    const float* ln1b  = (const float*)d_in[10];
    const float* ln2g  = (const float*)d_in[11];
    const float* ln2b  = (const float*)d_in[12];
    const float* gatew = (const float*)d_in[13];
    const float* ew1   = (const float*)d_in[14];
    const float* eb1   = (const float*)d_in[15];
    const float* ew2   = (const float*)d_in[16];
    const float* eb2   = (const float*)d_in[17];
    float* out = (float*)d_out;

    float *qkv, *attn, *proj, *normed, *h, *eo, *coef;
    float *wqkvt, *bqkv, *wot, *w1t, *w2t;
    cudaGetSymbolAddress((void**)&qkv,    g_qkv);
    cudaGetSymbolAddress((void**)&attn,   g_attn);
    cudaGetSymbolAddress((void**)&proj,   g_proj);
    cudaGetSymbolAddress((void**)&normed, g_normed);
    cudaGetSymbolAddress((void**)&h,      g_h);
    cudaGetSymbolAddress((void**)&eo,     g_eo);
    cudaGetSymbolAddress((void**)&coef,   g_coef);
    cudaGetSymbolAddress((void**)&wqkvt,  g_wqkvt);
    cudaGetSymbolAddress((void**)&bqkv,   g_bqkv);
    cudaGetSymbolAddress((void**)&wot,    g_wot);
    cudaGetSymbolAddress((void**)&w1t,    g_w1t);
    cudaGetSymbolAddress((void**)&w2t,    g_w2t);

    cudaFuncSetAttribute(mma_gemm<false>, cudaFuncAttributeMaxDynamicSharedMemorySize, SMEM_GEMM_BYTES);
    cudaFuncSetAttribute(mma_gemm<true>,  cudaFuncAttributeMaxDynamicSharedMemorySize, SMEM_GEMM_BYTES);
    cudaFuncSetAttribute(fused_attn,      cudaFuncAttributeMaxDynamicSharedMemorySize, FA_BYTES);

    dim3 blk(256);

    // weight transposes + bias concat
    transpose64<<<dim3(16, 16, 1), blk>>>(wq, wqkvt,           Dm, Dm);
    transpose64<<<dim3(16, 16, 1), blk>>>(wk, wqkvt + Dm*Dm,   Dm, Dm);
    transpose64<<<dim3(16, 16, 1), blk>>>(wv, wqkvt + 2*Dm*Dm, Dm, Dm);
    transpose64<<<dim3(16, 16, 1), blk>>>(wo, wot,             Dm, Dm);
    transpose64<<<dim3(Vv/64, Dm/64, Ee), blk>>>(ew1, w1t, Dm, Vv);
    transpose64<<<dim3(Dm/64, Vv/64, Ee), blk>>>(ew2, w2t, Vv, Dm);
    concat3<<<4, 256>>>(bq, bk, bv, bqkv, Dm);

    // QKV projections in ONE batched launch
    mma_gemm<false><<<dim3(8, 16, 3), blk, SMEM_GEMM_BYTES>>>(
        x, wqkvt, bqkv, qkv, TOK, Dm, Dm,
        0, (long long)Dm*Dm, (long long)Dm, (long long)TOK*Dm);

    // fused flash attention
    fused_attn<<<dim3(8, 32), blk, FA_BYTES>>>(
        qkv, qkv + (size_t)TOK*Dm, qkv + (size_t)2*TOK*Dm, attn);

    // output projection + residual + LN1
    mma_gemm<false><<<dim3(8, 16, 1), blk, SMEM_GEMM_BYTES>>>(
        attn, wot, bo, proj, TOK, Dm, Dm, 0, 0, 0, 0);
    add_ln<<<TOK, blk>>>(proj, x, ln1g, ln1b, normed);

    // MoE
    gate_coef<<<TOK, blk>>>(normed, gatew, coef);
    mma_gemm<true><<<dim3(32, 16, Ee), blk, SMEM_GEMM_BYTES>>>(
        normed, w1t, eb1, h, TOK, Vv, Dm,
        0, (long long)Vv*Dm, (long long)Vv, (long long)TOK*Vv);
    mma_gemm<false><<<dim3(8, 16, Ee), blk, SMEM_GEMM_BYTES>>>(
        h, w2t, eb2, eo, TOK, Dm, Vv,
        (long long)TOK*Vv, (long long)Dm*Vv, (long long)Dm, (long long)TOK*Dm);

    // combine + residual + LN2
    combine_ln<<<TOK, blk>>>(eo, coef, normed, ln2g, ln2b, out);
}

// round 12
// speedup vs baseline: 1.0686x; 1.0686x over previous
#include <cuda_runtime.h>
#include <math.h>
#include <stdint.h>

// Problem dims
#define Dm   1024
#define Sseq 1024
#define Bb   2
#define Hh   16
#define Ee   8
#define Vv   4096
#define TOK  (Bb*Sseq)
#define EPSV 1e-5f

// ---------------- device scratch ------------------------------------------------
__device__ float g_qkv[3*TOK*Dm];
__device__ float g_attn[TOK*Dm];
__device__ float g_proj[TOK*Dm];
__device__ float g_normed[TOK*Dm];
__device__ float g_h[(size_t)Ee*TOK*Vv];
__device__ float g_eo[(size_t)Ee*TOK*Dm];
__device__ float g_coef[TOK*Ee];
// transposed weights (N-major: Wt[n][k])
__device__ float g_wqkvt[3*Dm*Dm];
__device__ float g_bqkv[3*Dm];
__device__ float g_wot[Dm*Dm];
__device__ float g_w1t[(size_t)Ee*Vv*Dm];
__device__ float g_w2t[(size_t)Ee*Dm*Vv];

// ---------------- helpers -------------------------------------------------------
__device__ __forceinline__ uint32_t f2tf(float f) {
    uint32_t u; asm("cvt.rna.tf32.f32 %0, %1;" : "=r"(u) : "f"(f)); return u;
}
__device__ __forceinline__ void mma_tf32(float* c, const uint32_t* a, const uint32_t* b) {
    asm volatile("mma.sync.aligned.m16n8k8.row.col.f32.tf32.tf32.f32 "
        "{%0,%1,%2,%3}, {%4,%5,%6,%7}, {%8,%9}, {%0,%1,%2,%3};"
        : "+f"(c[0]), "+f"(c[1]), "+f"(c[2]), "+f"(c[3])
        : "r"(a[0]), "r"(a[1]), "r"(a[2]), "r"(a[3]), "r"(b[0]), "r"(b[1]));
}

// SMEM geometry for mma_gemm: padded stride 36 words per 32-float row.
#define LDS_STRIDE 36
#define TILE_WORDS (128 * LDS_STRIDE)            // 4608 words per buffer
#define SMEM_GEMM_BYTES (4 * TILE_WORDS * 4 * 2) // 73728

// ---------------- tensor-core tf32 GEMM: C[M,N] = A[M,K] @ Bt[N,K]^T + bias -----
// R5 pipeline: register-staged prefetch, double-buffered smem, 1 CTA/SM.
template<bool RELU>
__global__ __launch_bounds__(256) void mma_gemm(
    const float* __restrict__ A, const float* __restrict__ Bt,
    const float* __restrict__ bias, float* __restrict__ C,
    int M, int N, int K,
    long long sA, long long sB, long long sBias, long long sC)
{
    extern __shared__ uint32_t sh[];
    uint32_t* Asm = sh;                    // [2][TILE_WORDS]
    uint32_t* Bsm = sh + 2 * TILE_WORDS;   // [2][TILE_WORDS]

    const int t = threadIdx.x;
    const int lane = t & 31, w = t >> 5;
    const int warp_m = w >> 2;
    const int warp_n = w & 3;
    const int lr = lane >> 2;
    const int lc = lane & 3;

    const int eb = blockIdx.z;
    A    += (size_t)eb * sA;
    Bt   += (size_t)eb * sB;
    bias += (size_t)eb * sBias;
    C    += (size_t)eb * sC;
    const int n0 = blockIdx.x * 128, m0 = blockIdx.y * 128;

    const int kc = (t & 7) * 4;
    const int r0 = t >> 3;
    const float* Ag = A  + (size_t)(m0 + r0) * K + kc;
    const float* Bg = Bt + (size_t)(n0 + r0) * K + kc;
    const int sts_base = r0 * LDS_STRIDE + kc;

    float acc[4][4][4];
    #pragma unroll
    for (int mt = 0; mt < 4; mt++)
        #pragma unroll
        for (int nt = 0; nt < 4; nt++)
            #pragma unroll
            for (int i = 0; i < 4; i++) acc[mt][nt][i] = 0.f;

    const int nst = K >> 5;

    {
        float4 pa[4], pb[4];
        #pragma unroll
        for (int i = 0; i < 4; i++) {
            pa[i] = *(const float4*)(Ag + (size_t)(32 * i) * K);
            pb[i] = *(const float4*)(Bg + (size_t)(32 * i) * K);
        }
        #pragma unroll
        for (int i = 0; i < 4; i++) {
            uint4 ca = make_uint4(f2tf(pa[i].x), f2tf(pa[i].y), f2tf(pa[i].z), f2tf(pa[i].w));
            uint4 cb = make_uint4(f2tf(pb[i].x), f2tf(pb[i].y), f2tf(pb[i].z), f2tf(pb[i].w));
            *(uint4*)(Asm + sts_base + i * 32 * LDS_STRIDE) = ca;
            *(uint4*)(Bsm + sts_base + i * 32 * LDS_STRIDE) = cb;
        }
    }
    __syncthreads();

    const int a_off = (warp_m * 64 + lr) * LDS_STRIDE + lc;
    const int b_off = (warp_n * 32 + lr) * LDS_STRIDE + lc;

    for (int s = 0; s < nst; s++) {
        const int buf = s & 1;
        const bool more = (s + 1) < nst;
        float4 pa[4], pb[4];
        if (more) {
            const float* ag = Ag + (size_t)(32 * (s + 1));
            const float* bg = Bg + (size_t)(32 * (s + 1));
            #pragma unroll
            for (int i = 0; i < 4; i++) {
                pa[i] = *(const float4*)(ag + (size_t)(32 * i) * K);
                pb[i] = *(const float4*)(bg + (size_t)(32 * i) * K);
            }
        }

        const uint32_t* Apt = Asm + buf * TILE_WORDS + a_off;
        const uint32_t* Bpt = Bsm + buf * TILE_WORDS + b_off;
        #pragma unroll
        for (int kk = 0; kk < 4; kk++) {
            const int k = kk * 8;
            uint32_t af[4][4], bf[4][2];
            #pragma unroll
            for (int mt = 0; mt < 4; mt++) {
                af[mt][0] = Apt[(mt * 16    ) * LDS_STRIDE + k];
                af[mt][1] = Apt[(mt * 16 + 8) * LDS_STRIDE + k];
                af[mt][2] = Apt[(mt * 16    ) * LDS_STRIDE + k + 4];
                af[mt][3] = Apt[(mt * 16 + 8) * LDS_STRIDE + k + 4];
            }
            #pragma unroll
            for (int nt = 0; nt < 4; nt++) {
                bf[nt][0] = Bpt[(nt * 8) * LDS_STRIDE + k];
                bf[nt][1] = Bpt[(nt * 8) * LDS_STRIDE + k + 4];
            }
            #pragma unroll
            for (int mt = 0; mt < 4; mt++)
                #pragma unroll
                for (int nt = 0; nt < 4; nt++)
                    mma_tf32(acc[mt][nt], af[mt], bf[nt]);
        }

        if (more) {
            const int nb = (s + 1) & 1;
            #pragma unroll
            for (int i = 0; i < 4; i++) {
                uint4 ca = make_uint4(f2tf(pa[i].x), f2tf(pa[i].y), f2tf(pa[i].z), f2tf(pa[i].w));
                uint4 cb = make_uint4(f2tf(pb[i].x), f2tf(pb[i].y), f2tf(pb[i].z), f2tf(pb[i].w));
                *(uint4*)(Asm + nb * TILE_WORDS + sts_base + i * 32 * LDS_STRIDE) = ca;
                *(uint4*)(Bsm + nb * TILE_WORDS + sts_base + i * 32 * LDS_STRIDE) = cb;
            }
        }
        __syncthreads();
    }

    #pragma unroll
    for (int mt = 0; mt < 4; mt++) {
        const int m = m0 + warp_m * 64 + mt * 16 + lr;
        #pragma unroll
        for (int nt = 0; nt < 4; nt++) {
            const int n = n0 + warp_n * 32 + nt * 8 + lc * 2;
            const float b0 = bias[n], b1 = bias[n + 1];
            float o0 = acc[mt][nt][0] + b0, o1 = acc[mt][nt][1] + b1;
            float o2 = acc[mt][nt][2] + b0, o3 = acc[mt][nt][3] + b1;
            if (RELU) {
                o0 = fmaxf(o0, 0.f); o1 = fmaxf(o1, 0.f);
                o2 = fmaxf(o2, 0.f); o3 = fmaxf(o3, 0.f);
            }
            *(float2*)(C + (size_t)m * N + n)       = make_float2(o0, o1);
            *(float2*)(C + (size_t)(m + 8) * N + n) = make_float2(o2, o3);
        }
    }
}

// ---------------- fast transpose: out[C,R] = in[R,C]^T, float4 both sides --------
__global__ __launch_bounds__(256) void transpose64(
    const float* __restrict__ in, float* __restrict__ out, int R, int C)
{
    __shared__ float s[64][68];
    const size_t eoff = (size_t)blockIdx.z * (size_t)R * C;
    in += eoff; out += eoff;
    const int c0 = blockIdx.x * 64, r0 = blockIdx.y * 64;
    const int t = threadIdx.x;
    #pragma unroll
    for (int i = 0; i < 4; i++) {
        int idx = t + 256 * i;
        int row = idx >> 4, cx = (idx & 15) * 4;
        float4 v = *(const float4*)(in + (size_t)(r0 + row) * C + c0 + cx);
        s[cx + 0][row] = v.x; s[cx + 1][row] = v.y;
        s[cx + 2][row] = v.z; s[cx + 3][row] = v.w;
    }
    __syncthreads();
    #pragma unroll
    for (int i = 0; i < 4; i++) {
        int idx = t + 256 * i;
        int orow = idx >> 4, rx = (idx & 15) * 4;
        float4 o = *(float4*)&s[orow][rx];
        *(float4*)(out + (size_t)(c0 + orow) * R + r0 + rx) = o;
    }
}

// ---------------- concat 3 bias vectors ------------------------------------------
__global__ void concat3(const float* __restrict__ a, const float* __restrict__ b,
                        const float* __restrict__ c, float* __restrict__ o, int n)
{
    int i = blockIdx.x * 256 + threadIdx.x;
    if (i < n) { o[i] = a[i]; o[i + n] = b[i]; o[i + 2 * n] = c[i]; }
}

// ---------------- fused flash attention (tf32 mma) -------------------------------
#define FA_QS   0                  // [128][68]
#define FA_KS   8704               // [128][68]
#define FA_VS   17408              // [128][72]
#define FA_PS   26624              // [128][132]
#define FA_RED  43520              // [128][4]
#define FA_MS   44032
#define FA_LS   44160
#define FA_AL   44288
#define FA_WORDS 44416
#define FA_BYTES (FA_WORDS * 4)

__global__ __launch_bounds__(256) void fused_attn(
    const float* __restrict__ q, const float* __restrict__ k,
    const float* __restrict__ v, float* __restrict__ out)
{
    extern __shared__ float fsh[];
    uint32_t* Qs = (uint32_t*)(fsh + FA_QS);
    uint32_t* Ks = (uint32_t*)(fsh + FA_KS);
    uint32_t* Vs = (uint32_t*)(fsh + FA_VS);
    uint32_t* Ps = (uint32_t*)(fsh + FA_PS);
    float* red   = fsh + FA_RED;
    float* m_s   = fsh + FA_MS;
    float* l_s   = fsh + FA_LS;
    float* al_s  = fsh + FA_AL;

    const int t = threadIdx.x;
    const int lane = t & 31, w = t >> 5;
    const int warp_m = w >> 2;
    const int warp_n = w & 3;
    const int ow_m = w >> 1;
    const int ow_n = w & 1;
    const int lr = lane >> 2, lc = lane & 3;

    const int q0 = blockIdx.x * 128;
    const int bh = blockIdx.y, b = bh >> 4, h = bh & 15;
    const size_t qbase = (size_t)(b * Sseq + q0) * Dm + h * 64;
    const size_t kvbase = (size_t)(b * Sseq) * Dm + h * 64;

    #pragma unroll
    for (int i = 0; i < 8; i++) {
        int idx = t + 256 * i;
        int row = idx >> 4, c4 = (idx & 15) * 4;
        float4 qv = *(const float4*)(q + qbase + (size_t)row * Dm + c4);
        uint32_t* d = Qs + row * 68 + c4;
        d[0] = f2tf(qv.x); d[1] = f2tf(qv.y); d[2] = f2tf(qv.z); d[3] = f2tf(qv.w);
    }
    if (t < 128) { m_s[t] = -1e30f; l_s[t] = 0.f; }

    float acc_o[2][4][4];
    #pragma unroll
    for (int mt = 0; mt < 2; mt++)
        #pragma unroll
        for (int nt = 0; nt < 4; nt++)
            #pragma unroll
            for (int i = 0; i < 4; i++) acc_o[mt][nt][i] = 0.f;

    const int a_off = (warp_m * 64 + lr) * 68 + lc;
    const int b_off = (warp_n * 32 + lr) * 68 + lc;
    const int p_off = (ow_m * 32 + lr) * 132 + lc;

    for (int kt = 0; kt < 8; kt++) {
        const size_t kb = kvbase + (size_t)(kt * 128) * Dm;
        #pragma unroll
        for (int i = 0; i < 8; i++) {
            int idx = t + 256 * i;
            int row = idx >> 4, c4 = (idx & 15) * 4;
            float4 kv = *(const float4*)(k + kb + (size_t)row * Dm + c4);
            float4 vv = *(const float4*)(v + kb + (size_t)row * Dm + c4);
            uint32_t* dk = Ks + row * 68 + c4;
            uint32_t* dv = Vs + row * 72 + c4;
            dk[0] = f2tf(kv.x); dk[1] = f2tf(kv.y); dk[2] = f2tf(kv.z); dk[3] = f2tf(kv.w);
            dv[0] = f2tf(vv.x); dv[1] = f2tf(vv.y); dv[2] = f2tf(vv.z); dv[3] = f2tf(vv.w);
        }
        __syncthreads();

        float acc_s[4][4][4];
        #pragma unroll
        for (int mt = 0; mt < 4; mt++)
            #pragma unroll
            for (int nt = 0; nt < 4; nt++)
                #pragma unroll
                for (int i = 0; i < 4; i++) acc_s[mt][nt][i] = 0.f;
        #pragma unroll
        for (int kk = 0; kk < 8; kk++) {
            const int kx = kk * 8;
            uint32_t af[4][4], bf[4][2];
            #pragma unroll
            for (int mt = 0; mt < 4; mt++) {
                af[mt][0] = Qs[a_off + (mt * 16    ) * 68 + kx];
                af[mt][1] = Qs[a_off + (mt * 16 + 8) * 68 + kx];
                af[mt][2] = Qs[a_off + (mt * 16    ) * 68 + kx + 4];
                af[mt][3] = Qs[a_off + (mt * 16 + 8) * 68 + kx + 4];
            }
            #pragma unroll
            for (int nt = 0; nt < 4; nt++) {
                bf[nt][0] = Ks[b_off + (nt * 8) * 68 + kx];
                bf[nt][1] = Ks[b_off + (nt * 8) * 68 + kx + 4];
            }
            #pragma unroll
            for (int mt = 0; mt < 4; mt++)
                #pragma unroll
                for (int nt = 0; nt < 4; nt++)
                    mma_tf32(acc_s[mt][nt], af[mt], bf[nt]);
        }

        #pragma unroll
        for (int mt = 0; mt < 4; mt++) {
            #pragma unroll
            for (int half = 0; half < 2; half++) {
                float pm = -1e30f;
                #pragma unroll
                for (int nt = 0; nt < 4; nt++) {
                    pm = fmaxf(pm, acc_s[mt][nt][half * 2]);
                    pm = fmaxf(pm, acc_s[mt][nt][half * 2 + 1]);
                }
                pm = fmaxf(pm, __shfl_xor_sync(0xffffffffu, pm, 1));
                pm = fmaxf(pm, __shfl_xor_sync(0xffffffffu, pm, 2));
                if (lc == 0)
                    red[(warp_m * 64 + mt * 16 + half * 8 + lr) * 4 + warp_n] = pm;
            }
        }
        __syncthreads();

        if (t < 128) {
            float tm = fmaxf(fmaxf(red[t * 4 + 0], red[t * 4 + 1]),
                             fmaxf(red[t * 4 + 2], red[t * 4 + 3])) * 0.125f;
            float mo = m_s[t];
            float mn = fmaxf(mo, tm);
            al_s[t] = __expf(mo - mn);
            m_s[t]  = mn;
        }
        __syncthreads();

        #pragma unroll
        for (int mt = 0; mt < 4; mt++) {
            #pragma unroll
            for (int half = 0; half < 2; half++) {
                const int row = warp_m * 64 + mt * 16 + half * 8 + lr;
                const float mrow = m_s[row];
                float ps = 0.f;
                #pragma unroll
                for (int nt = 0; nt < 4; nt++) {
                    const int col = warp_n * 32 + nt * 8 + lc * 2;
                    float p0 = __expf(acc_s[mt][nt][half * 2]     * 0.125f - mrow);
                    float p1 = __expf(acc_s[mt][nt][half * 2 + 1] * 0.125f - mrow);
                    ps += p0 + p1;
                    Ps[row * 132 + col]     = f2tf(p0);
                    Ps[row * 132 + col + 1] = f2tf(p1);
                }
                ps += __shfl_xor_sync(0xffffffffu, ps, 1);
                ps += __shfl_xor_sync(0xffffffffu, ps, 2);
                if (lc == 0) red[row * 4 + warp_n] = ps;
            }
        }
        #pragma unroll
        for (int mt = 0; mt < 2; mt++) {
            const int row0 = ow_m * 32 + mt * 16 + lr;
            const float a0 = al_s[row0], a1 = al_s[row0 + 8];
            #pragma unroll
            for (int nt = 0; nt < 4; nt++) {
                acc_o[mt][nt][0] *= a0; acc_o[mt][nt][1] *= a0;
                acc_o[mt][nt][2] *= a1; acc_o[mt][nt][3] *= a1;
            }
        }
        __syncthreads();

        if (t < 128)
            l_s[t] = l_s[t] * al_s[t]
                   + red[t * 4 + 0] + red[t * 4 + 1] + red[t * 4 + 2] + red[t * 4 + 3];

        #pragma unroll
        for (int kk = 0; kk < 16; kk++) {
            const int kx = kk * 8;
            uint32_t af[2][4], bf[4][2];
            #pragma unroll
            for (int mt = 0; mt < 2; mt++) {
                af[mt][0] = Ps[p_off + (mt * 16    ) * 132 + kx];
                af[mt][1] = Ps[p_off + (mt * 16 + 8) * 132 + kx];
                af[mt][2] = Ps[p_off + (mt * 16    ) * 132 + kx + 4];
                af[mt][3] = Ps[p_off + (mt * 16 + 8) * 132 + kx + 4];
            }
            #pragma unroll
            for (int nt = 0; nt < 4; nt++) {
                const int n = ow_n * 32 + nt * 8 + lr;
                bf[nt][0] = Vs[(kx + lc) * 72 + n];
                bf[nt][1] = Vs[(kx + lc + 4) * 72 + n];
            }
            #pragma unroll
            for (int mt = 0; mt < 2; mt++)
                #pragma unroll
                for (int nt = 0; nt < 4; nt++)
                    mma_tf32(acc_o[mt][nt], af[mt], bf[nt]);
        }
        __syncthreads();
    }

    #pragma unroll
    for (int mt = 0; mt < 2; mt++) {
        const int row0 = ow_m * 32 + mt * 16 + lr;
        const float i0 = 1.f / l_s[row0], i1 = 1.f / l_s[row0 + 8];
        #pragma unroll
        for (int nt = 0; nt < 4; nt++) {
            const int col = ow_n * 32 + nt * 8 + lc * 2;
            float* o0 = out + (size_t)(b * Sseq + q0 + row0) * Dm + h * 64 + col;
            float* o1 = out + (size_t)(b * Sseq + q0 + row0 + 8) * Dm + h * 64 + col;
            *(float2*)o0 = make_float2(acc_o[mt][nt][0] * i0, acc_o[mt][nt][1] * i0);
            *(float2*)o1 = make_float2(acc_o[mt][nt][2] * i1, acc_o[mt][nt][3] * i1);
        }
    }
}

// ---------------- block reduction helper -----------------------------------------
__device__ __forceinline__ float block_sum256(float v, float* red) {
    #pragma unroll
    for (int o = 16; o > 0; o >>= 1) v += __shfl_xor_sync(0xffffffffu, v, o);
    if ((threadIdx.x & 31) == 0) red[threadIdx.x >> 5] = v;
    __syncthreads();
    float s = red[0];
    #pragma unroll
    for (int i = 1; i < 8; i++) s += red[i];
    __syncthreads();
    return s;
}

// ---------------- residual add + layernorm ---------------------------------------
__global__ __launch_bounds__(256) void add_ln(
    const float* __restrict__ a, const float* __restrict__ b,
    const float* __restrict__ gamma, const float* __restrict__ beta,
    float* __restrict__ out)
{
    __shared__ float red[8];
    const int t = threadIdx.x;
    const size_t base = (size_t)blockIdx.x * Dm;
    float4 va = ((const float4*)(a + base))[t];
    float4 vb = ((const float4*)(b + base))[t];
    float4 s = make_float4(va.x+vb.x, va.y+vb.y, va.z+vb.z, va.w+vb.w);
    float tot = block_sum256(s.x + s.y + s.z + s.w, red);
    float mu = tot * (1.f / Dm);
    float lq = (s.x-mu)*(s.x-mu) + (s.y-mu)*(s.y-mu) + (s.z-mu)*(s.z-mu) + (s.w-mu)*(s.w-mu);
    float var = block_sum256(lq, red) * (1.f / Dm);
    float rstd = rsqrtf(var + EPSV);
    float4 gg = ((const float4*)gamma)[t];
    float4 bt = ((const float4*)beta)[t];
    float4 o;
    o.x = (s.x - mu) * rstd * gg.x + bt.x;
    o.y = (s.y - mu) * rstd * gg.y + bt.y;
    o.z = (s.z - mu) * rstd * gg.z + bt.z;
    o.w = (s.w - mu) * rstd * gg.w + bt.w;
    ((float4*)(out + base))[t] = o;
}

// ---------------- gate coefficients ----------------------------------------------
__global__ __launch_bounds__(256) void gate_coef(
    const float* __restrict__ xn, const float* __restrict__ gw, float* __restrict__ coef)
{
    __shared__ float red[16][9];
    const int t = threadIdx.x, tkn = blockIdx.x;
    float acc[16];
    #pragma unroll
    for (int ge = 0; ge < 16; ge++) acc[ge] = 0.f;
    for (int d = t; d < Dm; d += 256) {
        float xv = xn[(size_t)tkn*Dm + d];
        #pragma unroll
        for (int ge = 0; ge < 16; ge++)
            acc[ge] = fmaf(xv, gw[(size_t)(ge >> 3)*Dm*Ee + (size_t)d*Ee + (ge & 7)], acc[ge]);
    }
    #pragma unroll
    for (int ge = 0; ge < 16; ge++) {
        float v = acc[ge];
        #pragma unroll
        for (int o = 16; o > 0; o >>= 1) v += __shfl_xor_sync(0xffffffffu, v, o);
        if ((t & 31) == 0) red[ge][t >> 5] = v;
    }
    __syncthreads();
    if (t == 0) {
        float logits[16];
        #pragma unroll
        for (int ge = 0; ge < 16; ge++) {
            float s = 0.f;
            #pragma unroll
            for (int w2 = 0; w2 < 8; w2++) s += red[ge][w2];
            logits[ge] = s;
        }
        float c[8];
        #pragma unroll
        for (int e2 = 0; e2 < 8; e2++) c[e2] = 0.f;
        #pragma unroll
        for (int g = 0; g < 2; g++) {
            float m = logits[g*8];
            #pragma unroll
            for (int e2 = 1; e2 < 8; e2++) m = fmaxf(m, logits[g*8+e2]);
            float s = 0.f, pe[8];
            #pragma unroll
            for (int e2 = 0; e2 < 8; e2++) { pe[e2] = __expf(logits[g*8+e2] - m); s += pe[e2]; }
            float inv = 1.f / s;
            #pragma unroll
            for (int e2 = 0; e2 < 8; e2++) c[e2] += pe[e2] * inv;
        }
        #pragma unroll
        for (int e2 = 0; e2 < 8; e2++) coef[(size_t)tkn*8 + e2] = c[e2] * 0.5f;
    }
}

// ---------------- combine + residual + LN2 ---------------------------------------
__global__ __launch_bounds__(256) void combine_ln(
    const float* __restrict__ eo, const float* __restrict__ coef,
    const float* __restrict__ xn,
    const float* __restrict__ gamma, const float* __restrict__ beta,
    float* __restrict__ out)
{
    __shared__ float red[8];
    __shared__ float cf[8];
    const int t = threadIdx.x, tkn = blockIdx.x;
    if (t < 8) cf[t] = coef[(size_t)tkn*8 + t];
    __syncthreads();
    const size_t base = (size_t)tkn * Dm;
    float4 s = ((const float4*)(xn + base))[t];
    #pragma unroll
    for (int e2 = 0; e2 < 8; e2++) {
        float4 v = ((const float4*)(eo + ((size_t)e2*TOK + tkn)*Dm))[t];
        float c = cf[e2];
        s.x = fmaf(c, v.x, s.x); s.y = fmaf(c, v.y, s.y);
        s.z = fmaf(c, v.z, s.z); s.w = fmaf(c, v.w, s.w);
    }
    float tot = block_sum256(s.x + s.y + s.z + s.w, red);
    float mu = tot * (1.f / Dm);
    float lq = (s.x-mu)*(s.x-mu) + (s.y-mu)*(s.y-mu) + (s.z-mu)*(s.z-mu) + (s.w-mu)*(s.w-mu);
    float var = block_sum256(lq, red) * (1.f / Dm);
    float rstd = rsqrtf(var + EPSV);
    float4 gg = ((const float4*)gamma)[t];
    float4 bt = ((const float4*)beta)[t];
    float4 o;
    o.x = (s.x - mu) * rstd * gg.x + bt.x;
    o.y = (s.y - mu) * rstd * gg.y + bt.y;
    o.z = (s.z - mu) * rstd * gg.z + bt.z;
    o.w = (s.w - mu) * rstd * gg.w + bt.w;
    ((float4*)(out + base))[t] = o;
}

// ---------------- launch ----------------------------------------------------------
extern "C" void kernel_launch(void* const* d_in, const int* in_sizes, int n_in,
                              void* d_out, int out_size)
{
    const float* x     = (const float*)d_in[0];
    const float* wq    = (const float*)d_in[1];
    const float* bq    = (const float*)d_in[2];
    const float* wk    = (const float*)d_in[3];
    const float* bk    = (const float*)d_in[4];
    const float* wv    = (const float*)d_in[5];
    const float* bv    = (const float*)d_in[6];
    const float* wo    = (const float*)d_in[7];
    const float* bo    = (const float*)d_in[8];
    const float* ln1g  = (const float*)d_in[9];
    const float* ln1b  = (const float*)d_in[10];
    const float* ln2g  = (const float*)d_in[11];
    const float* ln2b  = (const float*)d_in[12];
    const float* gatew = (const float*)d_in[13];
    const float* ew1   = (const float*)d_in[14];
    const float* eb1   = (const float*)d_in[15];
    const float* ew2   = (const float*)d_in[16];
    const float* eb2   = (const float*)d_in[17];
    float* out = (float*)d_out;

    float *qkv, *attn, *proj, *normed, *h, *eo, *coef;
    float *wqkvt, *bqkv, *wot, *w1t, *w2t;
    cudaGetSymbolAddress((void**)&qkv,    g_qkv);
    cudaGetSymbolAddress((void**)&attn,   g_attn);
    cudaGetSymbolAddress((void**)&proj,   g_proj);
    cudaGetSymbolAddress((void**)&normed, g_normed);
    cudaGetSymbolAddress((void**)&h,      g_h);
    cudaGetSymbolAddress((void**)&eo,     g_eo);
    cudaGetSymbolAddress((void**)&coef,   g_coef);
    cudaGetSymbolAddress((void**)&wqkvt,  g_wqkvt);
    cudaGetSymbolAddress((void**)&bqkv,   g_bqkv);
    cudaGetSymbolAddress((void**)&wot,    g_wot);
    cudaGetSymbolAddress((void**)&w1t,    g_w1t);
    cudaGetSymbolAddress((void**)&w2t,    g_w2t);

    cudaFuncSetAttribute(mma_gemm<false>, cudaFuncAttributeMaxDynamicSharedMemorySize, SMEM_GEMM_BYTES);
    cudaFuncSetAttribute(mma_gemm<true>,  cudaFuncAttributeMaxDynamicSharedMemorySize, SMEM_GEMM_BYTES);
    cudaFuncSetAttribute(fused_attn,      cudaFuncAttributeMaxDynamicSharedMemorySize, FA_BYTES);

    dim3 blk(256);

    // launches 0-4: QKV-prep (ordered so launch index 5 = batched QKV GEMM,
    // which is what the profiler's -s 5 -c 1 will capture)
    transpose64<<<dim3(16, 16, 1), blk>>>(wq, wqkvt,           Dm, Dm);   // 0
    transpose64<<<dim3(16, 16, 1), blk>>>(wk, wqkvt + Dm*Dm,   Dm, Dm);   // 1
    transpose64<<<dim3(16, 16, 1), blk>>>(wv, wqkvt + 2*Dm*Dm, Dm, Dm);   // 2
    concat3<<<4, 256>>>(bq, bk, bv, bqkv, Dm);                            // 3
    transpose64<<<dim3(16, 16, 1), blk>>>(wo, wot,             Dm, Dm);   // 4

    // launch 5: batched QKV GEMM  <-- profiled
    mma_gemm<false><<<dim3(8, 16, 3), blk, SMEM_GEMM_BYTES>>>(
        x, wqkvt, bqkv, qkv, TOK, Dm, Dm,
        0, (long long)Dm*Dm, (long long)Dm, (long long)TOK*Dm);

    // MoE weight transposes (independent; must precede MoE GEMMs only)
    transpose64<<<dim3(Vv/64, Dm/64, Ee), blk>>>(ew1, w1t, Dm, Vv);
    transpose64<<<dim3(Dm/64, Vv/64, Ee), blk>>>(ew2, w2t, Vv, Dm);

    // fused flash attention
    fused_attn<<<dim3(8, 32), blk, FA_BYTES>>>(
        qkv, qkv + (size_t)TOK*Dm, qkv + (size_t)2*TOK*Dm, attn);

    // output projection + residual + LN1
    mma_gemm<false><<<dim3(8, 16, 1), blk, SMEM_GEMM_BYTES>>>(
        attn, wot, bo, proj, TOK, Dm, Dm, 0, 0, 0, 0);
    add_ln<<<TOK, blk>>>(proj, x, ln1g, ln1b, normed);

    // MoE
    gate_coef<<<TOK, blk>>>(normed, gatew, coef);
    mma_gemm<true><<<dim3(32, 16, Ee), blk, SMEM_GEMM_BYTES>>>(
        normed, w1t, eb1, h, TOK, Vv, Dm,
        0, (long long)Vv*Dm, (long long)Vv, (long long)TOK*Vv);
    mma_gemm<false><<<dim3(8, 16, Ee), blk, SMEM_GEMM_BYTES>>>(
        h, w2t, eb2, eo, TOK, Dm, Vv,
        (long long)TOK*Vv, (long long)Dm*Vv, (long long)Dm, (long long)TOK*Dm);

    // combine + residual + LN2
    combine_ln<<<TOK, blk>>>(eo, coef, normed, ln2g, ln2b, out);
}

// round 13
// speedup vs baseline: 1.0880x; 1.0182x over previous
#include <cuda_runtime.h>
#include <math.h>
#include <stdint.h>

// Problem dims
#define Dm   1024
#define Sseq 1024
#define Bb   2
#define Hh   16
#define Ee   8
#define Vv   4096
#define TOK  (Bb*Sseq)
#define EPSV 1e-5f

// ---------------- device scratch ------------------------------------------------
__device__ float g_qkv[3*TOK*Dm];
__device__ float g_attn[TOK*Dm];
__device__ float g_proj[TOK*Dm];
__device__ float g_normed[TOK*Dm];
__device__ float g_h[(size_t)Ee*TOK*Vv];
__device__ float g_eo[(size_t)Ee*TOK*Dm];
__device__ float g_coef[TOK*Ee];
// transposed weights (N-major: Wt[n][k])
__device__ float g_wqkvt[3*Dm*Dm];
__device__ float g_bqkv[3*Dm];
__device__ float g_wot[Dm*Dm];
__device__ float g_w1t[(size_t)Ee*Vv*Dm];
__device__ float g_w2t[(size_t)Ee*Dm*Vv];

// ---------------- helpers -------------------------------------------------------
__device__ __forceinline__ uint32_t f2tf(float f) {
    uint32_t u; asm("cvt.rna.tf32.f32 %0, %1;" : "=r"(u) : "f"(f)); return u;
}
__device__ __forceinline__ void mma_tf32(float* c, const uint32_t* a, const uint32_t* b) {
    asm volatile("mma.sync.aligned.m16n8k8.row.col.f32.tf32.tf32.f32 "
        "{%0,%1,%2,%3}, {%4,%5,%6,%7}, {%8,%9}, {%0,%1,%2,%3};"
        : "+f"(c[0]), "+f"(c[1]), "+f"(c[2]), "+f"(c[3])
        : "r"(a[0]), "r"(a[1]), "r"(a[2]), "r"(a[3]), "r"(b[0]), "r"(b[1]));
}

// SMEM geometry: K-chunk 64, padded row stride 68 words.
#define LDS_STRIDE 68
#define TILE_WORDS (128 * LDS_STRIDE)            // 8704 words per matrix buffer
#define SMEM_GEMM_BYTES (4 * TILE_WORDS * 4)     // 2 bufs x (A+B) = 139264

// ---------------- tensor-core tf32 GEMM: C[M,N] = A[M,K] @ Bt[N,K]^T + bias -----
// 128x128 tile, K-chunk 64 (halved stage count vs R5), register-staged
// prefetch, double-buffered smem, 256 threads.
template<bool RELU>
__global__ __launch_bounds__(256) void mma_gemm(
    const float* __restrict__ A, const float* __restrict__ Bt,
    const float* __restrict__ bias, float* __restrict__ C,
    int M, int N, int K,
    long long sA, long long sB, long long sBias, long long sC)
{
    extern __shared__ uint32_t sh[];
    uint32_t* Asm = sh;                    // [2][TILE_WORDS]
    uint32_t* Bsm = sh + 2 * TILE_WORDS;   // [2][TILE_WORDS]

    const int t = threadIdx.x;
    const int lane = t & 31, w = t >> 5;
    const int warp_m = w >> 2;
    const int warp_n = w & 3;
    const int lr = lane >> 2;
    const int lc = lane & 3;

    const int eb = blockIdx.z;
    A    += (size_t)eb * sA;
    Bt   += (size_t)eb * sB;
    bias += (size_t)eb * sBias;
    C    += (size_t)eb * sC;
    const int n0 = blockIdx.x * 128, m0 = blockIdx.y * 128;

    // copy mapping: 16 threads per row, 4 floats each -> 64 k-cols; rows r0+16i
    const int kc = (t & 15) * 4;
    const int r0 = t >> 4;
    const float* Ag = A  + (size_t)(m0 + r0) * K + kc;
    const float* Bg = Bt + (size_t)(n0 + r0) * K + kc;
    const int sts_base = r0 * LDS_STRIDE + kc;

    float acc[4][4][4];
    #pragma unroll
    for (int mt = 0; mt < 4; mt++)
        #pragma unroll
        for (int nt = 0; nt < 4; nt++)
            #pragma unroll
            for (int i = 0; i < 4; i++) acc[mt][nt][i] = 0.f;

    const int nst = K >> 6;

    // stage 0 -> buf 0
    {
        float4 pa[8], pb[8];
        #pragma unroll
        for (int i = 0; i < 8; i++) {
            pa[i] = *(const float4*)(Ag + (size_t)(16 * i) * K);
            pb[i] = *(const float4*)(Bg + (size_t)(16 * i) * K);
        }
        #pragma unroll
        for (int i = 0; i < 8; i++) {
            uint4 ca = make_uint4(f2tf(pa[i].x), f2tf(pa[i].y), f2tf(pa[i].z), f2tf(pa[i].w));
            uint4 cb = make_uint4(f2tf(pb[i].x), f2tf(pb[i].y), f2tf(pb[i].z), f2tf(pb[i].w));
            *(uint4*)(Asm + sts_base + i * 16 * LDS_STRIDE) = ca;
            *(uint4*)(Bsm + sts_base + i * 16 * LDS_STRIDE) = cb;
        }
    }
    __syncthreads();

    const int a_off = (warp_m * 64 + lr) * LDS_STRIDE + lc;
    const int b_off = (warp_n * 32 + lr) * LDS_STRIDE + lc;

    for (int s = 0; s < nst; s++) {
        const int buf = s & 1;
        const bool more = (s + 1) < nst;
        float4 pa[8], pb[8];
        if (more) {
            const float* ag = Ag + (size_t)(64 * (s + 1));
            const float* bg = Bg + (size_t)(64 * (s + 1));
            #pragma unroll
            for (int i = 0; i < 8; i++) {
                pa[i] = *(const float4*)(ag + (size_t)(16 * i) * K);
                pb[i] = *(const float4*)(bg + (size_t)(16 * i) * K);
            }
        }

        const uint32_t* Apt = Asm + buf * TILE_WORDS + a_off;
        const uint32_t* Bpt = Bsm + buf * TILE_WORDS + b_off;
        #pragma unroll
        for (int kk = 0; kk < 8; kk++) {
            const int k = kk * 8;
            uint32_t af[4][4], bf[4][2];
            #pragma unroll
            for (int mt = 0; mt < 4; mt++) {
                af[mt][0] = Apt[(mt * 16    ) * LDS_STRIDE + k];
                af[mt][1] = Apt[(mt * 16 + 8) * LDS_STRIDE + k];
                af[mt][2] = Apt[(mt * 16    ) * LDS_STRIDE + k + 4];
                af[mt][3] = Apt[(mt * 16 + 8) * LDS_STRIDE + k + 4];
            }
            #pragma unroll
            for (int nt = 0; nt < 4; nt++) {
                bf[nt][0] = Bpt[(nt * 8) * LDS_STRIDE + k];
                bf[nt][1] = Bpt[(nt * 8) * LDS_STRIDE + k + 4];
            }
            #pragma unroll
            for (int mt = 0; mt < 4; mt++)
                #pragma unroll
                for (int nt = 0; nt < 4; nt++)
                    mma_tf32(acc[mt][nt], af[mt], bf[nt]);
        }

        if (more) {
            const int nb = (s + 1) & 1;
            #pragma unroll
            for (int i = 0; i < 8; i++) {
                uint4 ca = make_uint4(f2tf(pa[i].x), f2tf(pa[i].y), f2tf(pa[i].z), f2tf(pa[i].w));
                uint4 cb = make_uint4(f2tf(pb[i].x), f2tf(pb[i].y), f2tf(pb[i].z), f2tf(pb[i].w));
                *(uint4*)(Asm + nb * TILE_WORDS + sts_base + i * 16 * LDS_STRIDE) = ca;
                *(uint4*)(Bsm + nb * TILE_WORDS + sts_base + i * 16 * LDS_STRIDE) = cb;
            }
        }
        __syncthreads();
    }

    #pragma unroll
    for (int mt = 0; mt < 4; mt++) {
        const int m = m0 + warp_m * 64 + mt * 16 + lr;
        #pragma unroll
        for (int nt = 0; nt < 4; nt++) {
            const int n = n0 + warp_n * 32 + nt * 8 + lc * 2;
            const float b0 = bias[n], b1 = bias[n + 1];
            float o0 = acc[mt][nt][0] + b0, o1 = acc[mt][nt][1] + b1;
            float o2 = acc[mt][nt][2] + b0, o3 = acc[mt][nt][3] + b1;
            if (RELU) {
                o0 = fmaxf(o0, 0.f); o1 = fmaxf(o1, 0.f);
                o2 = fmaxf(o2, 0.f); o3 = fmaxf(o3, 0.f);
            }
            *(float2*)(C + (size_t)m * N + n)       = make_float2(o0, o1);
            *(float2*)(C + (size_t)(m + 8) * N + n) = make_float2(o2, o3);
        }
    }
}

// ---------------- fast transpose: out[C,R] = in[R,C]^T, float4 both sides --------
__global__ __launch_bounds__(256) void transpose64(
    const float* __restrict__ in, float* __restrict__ out, int R, int C)
{
    __shared__ float s[64][68];
    const size_t eoff = (size_t)blockIdx.z * (size_t)R * C;
    in += eoff; out += eoff;
    const int c0 = blockIdx.x * 64, r0 = blockIdx.y * 64;
    const int t = threadIdx.x;
    #pragma unroll
    for (int i = 0; i < 4; i++) {
        int idx = t + 256 * i;
        int row = idx >> 4, cx = (idx & 15) * 4;
        float4 v = *(const float4*)(in + (size_t)(r0 + row) * C + c0 + cx);
        s[cx + 0][row] = v.x; s[cx + 1][row] = v.y;
        s[cx + 2][row] = v.z; s[cx + 3][row] = v.w;
    }
    __syncthreads();
    #pragma unroll
    for (int i = 0; i < 4; i++) {
        int idx = t + 256 * i;
        int orow = idx >> 4, rx = (idx & 15) * 4;
        float4 o = *(float4*)&s[orow][rx];
        *(float4*)(out + (size_t)(c0 + orow) * R + r0 + rx) = o;
    }
}

// ---------------- concat 3 bias vectors ------------------------------------------
__global__ void concat3(const float* __restrict__ a, const float* __restrict__ b,
                        const float* __restrict__ c, float* __restrict__ o, int n)
{
    int i = blockIdx.x * 256 + threadIdx.x;
    if (i < n) { o[i] = a[i]; o[i + n] = b[i]; o[i + 2 * n] = c[i]; }
}

// ---------------- fused flash attention (tf32 mma) -------------------------------
#define FA_QS   0                  // [128][68]
#define FA_KS   8704               // [128][68]
#define FA_VS   17408              // [128][72]
#define FA_PS   26624              // [128][132]
#define FA_RED  43520              // [128][4]
#define FA_MS   44032
#define FA_LS   44160
#define FA_AL   44288
#define FA_WORDS 44416
#define FA_BYTES (FA_WORDS * 4)

__global__ __launch_bounds__(256) void fused_attn(
    const float* __restrict__ q, const float* __restrict__ k,
    const float* __restrict__ v, float* __restrict__ out)
{
    extern __shared__ float fsh[];
    uint32_t* Qs = (uint32_t*)(fsh + FA_QS);
    uint32_t* Ks = (uint32_t*)(fsh + FA_KS);
    uint32_t* Vs = (uint32_t*)(fsh + FA_VS);
    uint32_t* Ps = (uint32_t*)(fsh + FA_PS);
    float* red   = fsh + FA_RED;
    float* m_s   = fsh + FA_MS;
    float* l_s   = fsh + FA_LS;
    float* al_s  = fsh + FA_AL;

    const int t = threadIdx.x;
    const int lane = t & 31, w = t >> 5;
    const int warp_m = w >> 2;
    const int warp_n = w & 3;
    const int ow_m = w >> 1;
    const int ow_n = w & 1;
    const int lr = lane >> 2, lc = lane & 3;

    const int q0 = blockIdx.x * 128;
    const int bh = blockIdx.y, b = bh >> 4, h = bh & 15;
    const size_t qbase = (size_t)(b * Sseq + q0) * Dm + h * 64;
    const size_t kvbase = (size_t)(b * Sseq) * Dm + h * 64;

    #pragma unroll
    for (int i = 0; i < 8; i++) {
        int idx = t + 256 * i;
        int row = idx >> 4, c4 = (idx & 15) * 4;
        float4 qv = *(const float4*)(q + qbase + (size_t)row * Dm + c4);
        uint32_t* d = Qs + row * 68 + c4;
        d[0] = f2tf(qv.x); d[1] = f2tf(qv.y); d[2] = f2tf(qv.z); d[3] = f2tf(qv.w);
    }
    if (t < 128) { m_s[t] = -1e30f; l_s[t] = 0.f; }

    float acc_o[2][4][4];
    #pragma unroll
    for (int mt = 0; mt < 2; mt++)
        #pragma unroll
        for (int nt = 0; nt < 4; nt++)
            #pragma unroll
            for (int i = 0; i < 4; i++) acc_o[mt][nt][i] = 0.f;

    const int a_off = (warp_m * 64 + lr) * 68 + lc;
    const int b_off = (warp_n * 32 + lr) * 68 + lc;
    const int p_off = (ow_m * 32 + lr) * 132 + lc;

    for (int kt = 0; kt < 8; kt++) {
        const size_t kb = kvbase + (size_t)(kt * 128) * Dm;
        #pragma unroll
        for (int i = 0; i < 8; i++) {
            int idx = t + 256 * i;
            int row = idx >> 4, c4 = (idx & 15) * 4;
            float4 kv = *(const float4*)(k + kb + (size_t)row * Dm + c4);
            float4 vv = *(const float4*)(v + kb + (size_t)row * Dm + c4);
            uint32_t* dk = Ks + row * 68 + c4;
            uint32_t* dv = Vs + row * 72 + c4;
            dk[0] = f2tf(kv.x); dk[1] = f2tf(kv.y); dk[2] = f2tf(kv.z); dk[3] = f2tf(kv.w);
            dv[0] = f2tf(vv.x); dv[1] = f2tf(vv.y); dv[2] = f2tf(vv.z); dv[3] = f2tf(vv.w);
        }
        __syncthreads();

        float acc_s[4][4][4];
        #pragma unroll
        for (int mt = 0; mt < 4; mt++)
            #pragma unroll
            for (int nt = 0; nt < 4; nt++)
                #pragma unroll
                for (int i = 0; i < 4; i++) acc_s[mt][nt][i] = 0.f;
        #pragma unroll
        for (int kk = 0; kk < 8; kk++) {
            const int kx = kk * 8;
            uint32_t af[4][4], bf[4][2];
            #pragma unroll
            for (int mt = 0; mt < 4; mt++) {
                af[mt][0] = Qs[a_off + (mt * 16    ) * 68 + kx];
                af[mt][1] = Qs[a_off + (mt * 16 + 8) * 68 + kx];
                af[mt][2] = Qs[a_off + (mt * 16    ) * 68 + kx + 4];
                af[mt][3] = Qs[a_off + (mt * 16 + 8) * 68 + kx + 4];
            }
            #pragma unroll
            for (int nt = 0; nt < 4; nt++) {
                bf[nt][0] = Ks[b_off + (nt * 8) * 68 + kx];
                bf[nt][1] = Ks[b_off + (nt * 8) * 68 + kx + 4];
            }
            #pragma unroll
            for (int mt = 0; mt < 4; mt++)
                #pragma unroll
                for (int nt = 0; nt < 4; nt++)
                    mma_tf32(acc_s[mt][nt], af[mt], bf[nt]);
        }

        #pragma unroll
        for (int mt = 0; mt < 4; mt++) {
            #pragma unroll
            for (int half = 0; half < 2; half++) {
                float pm = -1e30f;
                #pragma unroll
                for (int nt = 0; nt < 4; nt++) {
                    pm = fmaxf(pm, acc_s[mt][nt][half * 2]);
                    pm = fmaxf(pm, acc_s[mt][nt][half * 2 + 1]);
                }
                pm = fmaxf(pm, __shfl_xor_sync(0xffffffffu, pm, 1));
                pm = fmaxf(pm, __shfl_xor_sync(0xffffffffu, pm, 2));
                if (lc == 0)
                    red[(warp_m * 64 + mt * 16 + half * 8 + lr) * 4 + warp_n] = pm;
            }
        }
        __syncthreads();

        if (t < 128) {
            float tm = fmaxf(fmaxf(red[t * 4 + 0], red[t * 4 + 1]),
                             fmaxf(red[t * 4 + 2], red[t * 4 + 3])) * 0.125f;
            float mo = m_s[t];
            float mn = fmaxf(mo, tm);
            al_s[t] = __expf(mo - mn);
            m_s[t]  = mn;
        }
        __syncthreads();

        #pragma unroll
        for (int mt = 0; mt < 4; mt++) {
            #pragma unroll
            for (int half = 0; half < 2; half++) {
                const int row = warp_m * 64 + mt * 16 + half * 8 + lr;
                const float mrow = m_s[row];
                float ps = 0.f;
                #pragma unroll
                for (int nt = 0; nt < 4; nt++) {
                    const int col = warp_n * 32 + nt * 8 + lc * 2;
                    float p0 = __expf(acc_s[mt][nt][half * 2]     * 0.125f - mrow);
                    float p1 = __expf(acc_s[mt][nt][half * 2 + 1] * 0.125f - mrow);
                    ps += p0 + p1;
                    Ps[row * 132 + col]     = f2tf(p0);
                    Ps[row * 132 + col + 1] = f2tf(p1);
                }
                ps += __shfl_xor_sync(0xffffffffu, ps, 1);
                ps += __shfl_xor_sync(0xffffffffu, ps, 2);
                if (lc == 0) red[row * 4 + warp_n] = ps;
            }
        }
        #pragma unroll
        for (int mt = 0; mt < 2; mt++) {
            const int row0 = ow_m * 32 + mt * 16 + lr;
            const float a0 = al_s[row0], a1 = al_s[row0 + 8];
            #pragma unroll
            for (int nt = 0; nt < 4; nt++) {
                acc_o[mt][nt][0] *= a0; acc_o[mt][nt][1] *= a0;
                acc_o[mt][nt][2] *= a1; acc_o[mt][nt][3] *= a1;
            }
        }
        __syncthreads();

        if (t < 128)
            l_s[t] = l_s[t] * al_s[t]
                   + red[t * 4 + 0] + red[t * 4 + 1] + red[t * 4 + 2] + red[t * 4 + 3];

        #pragma unroll
        for (int kk = 0; kk < 16; kk++) {
            const int kx = kk * 8;
            uint32_t af[2][4], bf[4][2];
            #pragma unroll
            for (int mt = 0; mt < 2; mt++) {
                af[mt][0] = Ps[p_off + (mt * 16    ) * 132 + kx];
                af[mt][1] = Ps[p_off + (mt * 16 + 8) * 132 + kx];
                af[mt][2] = Ps[p_off + (mt * 16    ) * 132 + kx + 4];
                af[mt][3] = Ps[p_off + (mt * 16 + 8) * 132 + kx + 4];
            }
            #pragma unroll
            for (int nt = 0; nt < 4; nt++) {
                const int n = ow_n * 32 + nt * 8 + lr;
                bf[nt][0] = Vs[(kx + lc) * 72 + n];
                bf[nt][1] = Vs[(kx + lc + 4) * 72 + n];
            }
            #pragma unroll
            for (int mt = 0; mt < 2; mt++)
                #pragma unroll
                for (int nt = 0; nt < 4; nt++)
                    mma_tf32(acc_o[mt][nt], af[mt], bf[nt]);
        }
        __syncthreads();
    }

    #pragma unroll
    for (int mt = 0; mt < 2; mt++) {
        const int row0 = ow_m * 32 + mt * 16 + lr;
        const float i0 = 1.f / l_s[row0], i1 = 1.f / l_s[row0 + 8];
        #pragma unroll
        for (int nt = 0; nt < 4; nt++) {
            const int col = ow_n * 32 + nt * 8 + lc * 2;
            float* o0 = out + (size_t)(b * Sseq + q0 + row0) * Dm + h * 64 + col;
            float* o1 = out + (size_t)(b * Sseq + q0 + row0 + 8) * Dm + h * 64 + col;
            *(float2*)o0 = make_float2(acc_o[mt][nt][0] * i0, acc_o[mt][nt][1] * i0);
            *(float2*)o1 = make_float2(acc_o[mt][nt][2] * i1, acc_o[mt][nt][3] * i1);
        }
    }
}

// ---------------- block reduction helper -----------------------------------------
__device__ __forceinline__ float block_sum256(float v, float* red) {
    #pragma unroll
    for (int o = 16; o > 0; o >>= 1) v += __shfl_xor_sync(0xffffffffu, v, o);
    if ((threadIdx.x & 31) == 0) red[threadIdx.x >> 5] = v;
    __syncthreads();
    float s = red[0];
    #pragma unroll
    for (int i = 1; i < 8; i++) s += red[i];
    __syncthreads();
    return s;
}

// ---------------- residual add + layernorm ---------------------------------------
__global__ __launch_bounds__(256) void add_ln(
    const float* __restrict__ a, const float* __restrict__ b,
    const float* __restrict__ gamma, const float* __restrict__ beta,
    float* __restrict__ out)
{
    __shared__ float red[8];
    const int t = threadIdx.x;
    const size_t base = (size_t)blockIdx.x * Dm;
    float4 va = ((const float4*)(a + base))[t];
    float4 vb = ((const float4*)(b + base))[t];
    float4 s = make_float4(va.x+vb.x, va.y+vb.y, va.z+vb.z, va.w+vb.w);
    float tot = block_sum256(s.x + s.y + s.z + s.w, red);
    float mu = tot * (1.f / Dm);
    float lq = (s.x-mu)*(s.x-mu) + (s.y-mu)*(s.y-mu) + (s.z-mu)*(s.z-mu) + (s.w-mu)*(s.w-mu);
    float var = block_sum256(lq, red) * (1.f / Dm);
    float rstd = rsqrtf(var + EPSV);
    float4 gg = ((const float4*)gamma)[t];
    float4 bt = ((const float4*)beta)[t];
    float4 o;
    o.x = (s.x - mu) * rstd * gg.x + bt.x;
    o.y = (s.y - mu) * rstd * gg.y + bt.y;
    o.z = (s.z - mu) * rstd * gg.z + bt.z;
    o.w = (s.w - mu) * rstd * gg.w + bt.w;
    ((float4*)(out + base))[t] = o;
}

// ---------------- gate coefficients ----------------------------------------------
__global__ __launch_bounds__(256) void gate_coef(
    const float* __restrict__ xn, const float* __restrict__ gw, float* __restrict__ coef)
{
    __shared__ float red[16][9];
    const int t = threadIdx.x, tkn = blockIdx.x;
    float acc[16];
    #pragma unroll
    for (int ge = 0; ge < 16; ge++) acc[ge] = 0.f;
    for (int d = t; d < Dm; d += 256) {
        float xv = xn[(size_t)tkn*Dm + d];
        #pragma unroll
        for (int ge = 0; ge < 16; ge++)
            acc[ge] = fmaf(xv, gw[(size_t)(ge >> 3)*Dm*Ee + (size_t)d*Ee + (ge & 7)], acc[ge]);
    }
    #pragma unroll
    for (int ge = 0; ge < 16; ge++) {
        float v = acc[ge];
        #pragma unroll
        for (int o = 16; o > 0; o >>= 1) v += __shfl_xor_sync(0xffffffffu, v, o);
        if ((t & 31) == 0) red[ge][t >> 5] = v;
    }
    __syncthreads();
    if (t == 0) {
        float logits[16];
        #pragma unroll
        for (int ge = 0; ge < 16; ge++) {
            float s = 0.f;
            #pragma unroll
            for (int w2 = 0; w2 < 8; w2++) s += red[ge][w2];
            logits[ge] = s;
        }
        float c[8];
        #pragma unroll
        for (int e2 = 0; e2 < 8; e2++) c[e2] = 0.f;
        #pragma unroll
        for (int g = 0; g < 2; g++) {
            float m = logits[g*8];
            #pragma unroll
            for (int e2 = 1; e2 < 8; e2++) m = fmaxf(m, logits[g*8+e2]);
            float s = 0.f, pe[8];
            #pragma unroll
            for (int e2 = 0; e2 < 8; e2++) { pe[e2] = __expf(logits[g*8+e2] - m); s += pe[e2]; }
            float inv = 1.f / s;
            #pragma unroll
            for (int e2 = 0; e2 < 8; e2++) c[e2] += pe[e2] * inv;
        }
        #pragma unroll
        for (int e2 = 0; e2 < 8; e2++) coef[(size_t)tkn*8 + e2] = c[e2] * 0.5f;
    }
}

// ---------------- combine + residual + LN2 ---------------------------------------
__global__ __launch_bounds__(256) void combine_ln(
    const float* __restrict__ eo, const float* __restrict__ coef,
    const float* __restrict__ xn,
    const float* __restrict__ gamma, const float* __restrict__ beta,
    float* __restrict__ out)
{
    __shared__ float red[8];
    __shared__ float cf[8];
    const int t = threadIdx.x, tkn = blockIdx.x;
    if (t < 8) cf[t] = coef[(size_t)tkn*8 + t];
    __syncthreads();
    const size_t base = (size_t)tkn * Dm;
    float4 s = ((const float4*)(xn + base))[t];
    #pragma unroll
    for (int e2 = 0; e2 < 8; e2++) {
        float4 v = ((const float4*)(eo + ((size_t)e2*TOK + tkn)*Dm))[t];
        float c = cf[e2];
        s.x = fmaf(c, v.x, s.x); s.y = fmaf(c, v.y, s.y);
        s.z = fmaf(c, v.z, s.z); s.w = fmaf(c, v.w, s.w);
    }
    float tot = block_sum256(s.x + s.y + s.z + s.w, red);
    float mu = tot * (1.f / Dm);
    float lq = (s.x-mu)*(s.x-mu) + (s.y-mu)*(s.y-mu) + (s.z-mu)*(s.z-mu) + (s.w-mu)*(s.w-mu);
    float var = block_sum256(lq, red) * (1.f / Dm);
    float rstd = rsqrtf(var + EPSV);
    float4 gg = ((const float4*)gamma)[t];
    float4 bt = ((const float4*)beta)[t];
    float4 o;
    o.x = (s.x - mu) * rstd * gg.x + bt.x;
    o.y = (s.y - mu) * rstd * gg.y + bt.y;
    o.z = (s.z - mu) * rstd * gg.z + bt.z;
    o.w = (s.w - mu) * rstd * gg.w + bt.w;
    ((float4*)(out + base))[t] = o;
}

// ---------------- launch ----------------------------------------------------------
extern "C" void kernel_launch(void* const* d_in, const int* in_sizes, int n_in,
                              void* d_out, int out_size)
{
    const float* x     = (const float*)d_in[0];
    const float* wq    = (const float*)d_in[1];
    const float* bq    = (const float*)d_in[2];
    const float* wk    = (const float*)d_in[3];
    const float* bk    = (const float*)d_in[4];
    const float* wv    = (const float*)d_in[5];
    const float* bv    = (const float*)d_in[6];
    const float* wo    = (const float*)d_in[7];
    const float* bo    = (const float*)d_in[8];
    const float* ln1g  = (const float*)d_in[9];
    const float* ln1b  = (const float*)d_in[10];
    const float* ln2g  = (const float*)d_in[11];
    const float* ln2b  = (const float*)d_in[12];
    const float* gatew = (const float*)d_in[13];
    const float* ew1   = (const float*)d_in[14];
    const float* eb1   = (const float*)d_in[15];
    const float* ew2   = (const float*)d_in[16];
    const float* eb2   = (const float*)d_in[17];
    float* out = (float*)d_out;

    float *qkv, *attn, *proj, *normed, *h, *eo, *coef;
    float *wqkvt, *bqkv, *wot, *w1t, *w2t;
    cudaGetSymbolAddress((void**)&qkv,    g_qkv);
    cudaGetSymbolAddress((void**)&attn,   g_attn);
    cudaGetSymbolAddress((void**)&proj,   g_proj);
    cudaGetSymbolAddress((void**)&normed, g_normed);
    cudaGetSymbolAddress((void**)&h,      g_h);
    cudaGetSymbolAddress((void**)&eo,     g_eo);
    cudaGetSymbolAddress((void**)&coef,   g_coef);
    cudaGetSymbolAddress((void**)&wqkvt,  g_wqkvt);
    cudaGetSymbolAddress((void**)&bqkv,   g_bqkv);
    cudaGetSymbolAddress((void**)&wot,    g_wot);
    cudaGetSymbolAddress((void**)&w1t,    g_w1t);
    cudaGetSymbolAddress((void**)&w2t,    g_w2t);

    cudaFuncSetAttribute(mma_gemm<false>, cudaFuncAttributeMaxDynamicSharedMemorySize, SMEM_GEMM_BYTES);
    cudaFuncSetAttribute(mma_gemm<true>,  cudaFuncAttributeMaxDynamicSharedMemorySize, SMEM_GEMM_BYTES);
    cudaFuncSetAttribute(fused_attn,      cudaFuncAttributeMaxDynamicSharedMemorySize, FA_BYTES);

    dim3 blk(256);

    // weight transposes + bias concat
    transpose64<<<dim3(16, 16, 1), blk>>>(wq, wqkvt,           Dm, Dm);
    transpose64<<<dim3(16, 16, 1), blk>>>(wk, wqkvt + Dm*Dm,   Dm, Dm);
    transpose64<<<dim3(16, 16, 1), blk>>>(wv, wqkvt + 2*Dm*Dm, Dm, Dm);
    concat3<<<4, 256>>>(bq, bk, bv, bqkv, Dm);
    transpose64<<<dim3(16, 16, 1), blk>>>(wo, wot,             Dm, Dm);

    // batched QKV GEMM
    mma_gemm<false><<<dim3(8, 16, 3), blk, SMEM_GEMM_BYTES>>>(
        x, wqkvt, bqkv, qkv, TOK, Dm, Dm,
        0, (long long)Dm*Dm, (long long)Dm, (long long)TOK*Dm);

    // MoE weight transposes (independent)
    transpose64<<<dim3(Vv/64, Dm/64, Ee), blk>>>(ew1, w1t, Dm, Vv);
    transpose64<<<dim3(Dm/64, Vv/64, Ee), blk>>>(ew2, w2t, Vv, Dm);

    // fused flash attention
    fused_attn<<<dim3(8, 32), blk, FA_BYTES>>>(
        qkv, qkv + (size_t)TOK*Dm, qkv + (size_t)2*TOK*Dm, attn);

    // output projection + residual + LN1
    mma_gemm<false><<<dim3(8, 16, 1), blk, SMEM_GEMM_BYTES>>>(
        attn, wot, bo, proj, TOK, Dm, Dm, 0, 0, 0, 0);
    add_ln<<<TOK, blk>>>(proj, x, ln1g, ln1b, normed);

    // MoE
    gate_coef<<<TOK, blk>>>(normed, gatew, coef);
    mma_gemm<true><<<dim3(32, 16, Ee), blk, SMEM_GEMM_BYTES>>>(
        normed, w1t, eb1, h, TOK, Vv, Dm,
        0, (long long)Vv*Dm, (long long)Vv, (long long)TOK*Vv);
    mma_gemm<false><<<dim3(8, 16, Ee), blk, SMEM_GEMM_BYTES>>>(
        h, w2t, eb2, eo, TOK, Dm, Vv,
        (long long)TOK*Vv, (long long)Dm*Vv, (long long)Dm, (long long)TOK*Dm);

    // combine + residual + LN2
    combine_ln<<<TOK, blk>>>(eo, coef, normed, ln2g, ln2b, out);
}

// round 14
// speedup vs baseline: 1.6974x; 1.5601x over previous
#include <cuda_runtime.h>
#include <math.h>
#include <stdint.h>

// Problem dims
#define Dm   1024
#define Sseq 1024
#define Bb   2
#define Hh   16
#define Ee   8
#define Vv   4096
#define TOK  (Bb*Sseq)
#define EPSV 1e-5f

// ---------------- device scratch ------------------------------------------------
__device__ float g_qkv[3*TOK*Dm];
__device__ float g_attn[TOK*Dm];
__device__ float g_proj[TOK*Dm];
__device__ float g_normed[TOK*Dm];
__device__ float g_h[(size_t)Ee*TOK*Vv];
__device__ float g_eo[(size_t)Ee*TOK*Dm];
__device__ float g_coef[TOK*Ee];
// transposed weights (N-major: Wt[n][k])
__device__ float g_wqkvt[3*Dm*Dm];
__device__ float g_bqkv[3*Dm];
__device__ float g_wot[Dm*Dm];
__device__ float g_w1t[(size_t)Ee*Vv*Dm];
__device__ float g_w2t[(size_t)Ee*Dm*Vv];

// ---------------- helpers -------------------------------------------------------
__device__ __forceinline__ uint32_t f2tf(float f) {
    uint32_t u; asm("cvt.rna.tf32.f32 %0, %1;" : "=r"(u) : "f"(f)); return u;
}
// pack (lo, hi) floats into f16x2 (lo in low half)
__device__ __forceinline__ uint32_t f2h2(float lo, float hi) {
    uint32_t u; asm("cvt.rn.f16x2.f32 %0, %1, %2;" : "=r"(u) : "f"(hi), "f"(lo)); return u;
}
__device__ __forceinline__ void mma_tf32(float* c, const uint32_t* a, const uint32_t* b) {
    asm volatile("mma.sync.aligned.m16n8k8.row.col.f32.tf32.tf32.f32 "
        "{%0,%1,%2,%3}, {%4,%5,%6,%7}, {%8,%9}, {%0,%1,%2,%3};"
        : "+f"(c[0]), "+f"(c[1]), "+f"(c[2]), "+f"(c[3])
        : "r"(a[0]), "r"(a[1]), "r"(a[2]), "r"(a[3]), "r"(b[0]), "r"(b[1]));
}
__device__ __forceinline__ void mma_f16(float* c, const uint32_t* a, const uint32_t* b) {
    asm volatile("mma.sync.aligned.m16n8k16.row.col.f32.f16.f16.f32 "
        "{%0,%1,%2,%3}, {%4,%5,%6,%7}, {%8,%9}, {%0,%1,%2,%3};"
        : "+f"(c[0]), "+f"(c[1]), "+f"(c[2]), "+f"(c[3])
        : "r"(a[0]), "r"(a[1]), "r"(a[2]), "r"(a[3]), "r"(b[0]), "r"(b[1]));
}

// SMEM geometry for fp16 mma_gemm: K-chunk 64 halves = 32 words + pad -> stride 36.
#define LDS_STRIDE 36
#define TILE_WORDS (128 * LDS_STRIDE)            // 4608 words per matrix buffer
#define SMEM_GEMM_BYTES (4 * TILE_WORDS * 4)     // 2 bufs x (A+B) = 73728

// ---------------- tensor-core fp16 GEMM: C[M,N] = A[M,K] @ Bt[N,K]^T + bias -----
// 128x128 tile, K-chunk 64, m16n8k16 f16 mma (fp32 accum), register-staged
// prefetch, double-buffered smem, 256 threads.
template<bool RELU>
__global__ __launch_bounds__(256) void mma_gemm(
    const float* __restrict__ A, const float* __restrict__ Bt,
    const float* __restrict__ bias, float* __restrict__ C,
    int M, int N, int K,
    long long sA, long long sB, long long sBias, long long sC)
{
    extern __shared__ uint32_t sh[];
    uint32_t* Asm = sh;                    // [2][TILE_WORDS]
    uint32_t* Bsm = sh + 2 * TILE_WORDS;   // [2][TILE_WORDS]

    const int t = threadIdx.x;
    const int lane = t & 31, w = t >> 5;
    const int warp_m = w >> 2;
    const int warp_n = w & 3;
    const int lr = lane >> 2;
    const int lc = lane & 3;

    const int eb = blockIdx.z;
    A    += (size_t)eb * sA;
    Bt   += (size_t)eb * sB;
    bias += (size_t)eb * sBias;
    C    += (size_t)eb * sC;
    const int n0 = blockIdx.x * 128, m0 = blockIdx.y * 128;

    // copy mapping: 16 threads/row, 4 floats each -> 64 k-floats; rows r0+16i
    const int kc = (t & 15) * 4;          // float col within 64-chunk
    const int r0 = t >> 4;
    const float* Ag = A  + (size_t)(m0 + r0) * K + kc;
    const float* Bg = Bt + (size_t)(n0 + r0) * K + kc;
    const int sts_base = r0 * LDS_STRIDE + (t & 15) * 2;   // word offset (2 words per thread)

    float acc[4][4][4];
    #pragma unroll
    for (int mt = 0; mt < 4; mt++)
        #pragma unroll
        for (int nt = 0; nt < 4; nt++)
            #pragma unroll
            for (int i = 0; i < 4; i++) acc[mt][nt][i] = 0.f;

    const int nst = K >> 6;

    // stage 0 -> buf 0
    {
        float4 pa[8], pb[8];
        #pragma unroll
        for (int i = 0; i < 8; i++) {
            pa[i] = *(const float4*)(Ag + (size_t)(16 * i) * K);
            pb[i] = *(const float4*)(Bg + (size_t)(16 * i) * K);
        }
        #pragma unroll
        for (int i = 0; i < 8; i++) {
            uint2 ha = make_uint2(f2h2(pa[i].x, pa[i].y), f2h2(pa[i].z, pa[i].w));
            uint2 hb = make_uint2(f2h2(pb[i].x, pb[i].y), f2h2(pb[i].z, pb[i].w));
            *(uint2*)(Asm + sts_base + i * 16 * LDS_STRIDE) = ha;
            *(uint2*)(Bsm + sts_base + i * 16 * LDS_STRIDE) = hb;
        }
    }
    __syncthreads();

    const int a_off = (warp_m * 64 + lr) * LDS_STRIDE + lc;
    const int b_off = (warp_n * 32 + lr) * LDS_STRIDE + lc;

    for (int s = 0; s < nst; s++) {
        const int buf = s & 1;
        const bool more = (s + 1) < nst;
        float4 pa[8], pb[8];
        if (more) {
            const float* ag = Ag + (size_t)(64 * (s + 1));
            const float* bg = Bg + (size_t)(64 * (s + 1));
            #pragma unroll
            for (int i = 0; i < 8; i++) {
                pa[i] = *(const float4*)(ag + (size_t)(16 * i) * K);
                pb[i] = *(const float4*)(bg + (size_t)(16 * i) * K);
            }
        }

        const uint32_t* Apt = Asm + buf * TILE_WORDS + a_off;
        const uint32_t* Bpt = Bsm + buf * TILE_WORDS + b_off;
        #pragma unroll
        for (int ks = 0; ks < 4; ks++) {
            const int k = ks * 8;
            uint32_t af[4][4], bf[4][2];
            #pragma unroll
            for (int mt = 0; mt < 4; mt++) {
                af[mt][0] = Apt[(mt * 16    ) * LDS_STRIDE + k];
                af[mt][1] = Apt[(mt * 16 + 8) * LDS_STRIDE + k];
                af[mt][2] = Apt[(mt * 16    ) * LDS_STRIDE + k + 4];
                af[mt][3] = Apt[(mt * 16 + 8) * LDS_STRIDE + k + 4];
            }
            #pragma unroll
            for (int nt = 0; nt < 4; nt++) {
                bf[nt][0] = Bpt[(nt * 8) * LDS_STRIDE + k];
                bf[nt][1] = Bpt[(nt * 8) * LDS_STRIDE + k + 4];
            }
            #pragma unroll
            for (int mt = 0; mt < 4; mt++)
                #pragma unroll
                for (int nt = 0; nt < 4; nt++)
                    mma_f16(acc[mt][nt], af[mt], bf[nt]);
        }

        if (more) {
            const int nb = (s + 1) & 1;
            #pragma unroll
            for (int i = 0; i < 8; i++) {
                uint2 ha = make_uint2(f2h2(pa[i].x, pa[i].y), f2h2(pa[i].z, pa[i].w));
                uint2 hb = make_uint2(f2h2(pb[i].x, pb[i].y), f2h2(pb[i].z, pb[i].w));
                *(uint2*)(Asm + nb * TILE_WORDS + sts_base + i * 16 * LDS_STRIDE) = ha;
                *(uint2*)(Bsm + nb * TILE_WORDS + sts_base + i * 16 * LDS_STRIDE) = hb;
            }
        }
        __syncthreads();
    }

    #pragma unroll
    for (int mt = 0; mt < 4; mt++) {
        const int m = m0 + warp_m * 64 + mt * 16 + lr;
        #pragma unroll
        for (int nt = 0; nt < 4; nt++) {
            const int n = n0 + warp_n * 32 + nt * 8 + lc * 2;
            const float b0 = bias[n], b1 = bias[n + 1];
            float o0 = acc[mt][nt][0] + b0, o1 = acc[mt][nt][1] + b1;
            float o2 = acc[mt][nt][2] + b0, o3 = acc[mt][nt][3] + b1;
            if (RELU) {
                o0 = fmaxf(o0, 0.f); o1 = fmaxf(o1, 0.f);
                o2 = fmaxf(o2, 0.f); o3 = fmaxf(o3, 0.f);
            }
            *(float2*)(C + (size_t)m * N + n)       = make_float2(o0, o1);
            *(float2*)(C + (size_t)(m + 8) * N + n) = make_float2(o2, o3);
        }
    }
}

// ---------------- fast transpose: out[C,R] = in[R,C]^T, float4 both sides --------
__global__ __launch_bounds__(256) void transpose64(
    const float* __restrict__ in, float* __restrict__ out, int R, int C)
{
    __shared__ float s[64][68];
    const size_t eoff = (size_t)blockIdx.z * (size_t)R * C;
    in += eoff; out += eoff;
    const int c0 = blockIdx.x * 64, r0 = blockIdx.y * 64;
    const int t = threadIdx.x;
    #pragma unroll
    for (int i = 0; i < 4; i++) {
        int idx = t + 256 * i;
        int row = idx >> 4, cx = (idx & 15) * 4;
        float4 v = *(const float4*)(in + (size_t)(r0 + row) * C + c0 + cx);
        s[cx + 0][row] = v.x; s[cx + 1][row] = v.y;
        s[cx + 2][row] = v.z; s[cx + 3][row] = v.w;
    }
    __syncthreads();
    #pragma unroll
    for (int i = 0; i < 4; i++) {
        int idx = t + 256 * i;
        int orow = idx >> 4, rx = (idx & 15) * 4;
        float4 o = *(float4*)&s[orow][rx];
        *(float4*)(out + (size_t)(c0 + orow) * R + r0 + rx) = o;
    }
}

// ---------------- concat 3 bias vectors ------------------------------------------
__global__ void concat3(const float* __restrict__ a, const float* __restrict__ b,
                        const float* __restrict__ c, float* __restrict__ o, int n)
{
    int i = blockIdx.x * 256 + threadIdx.x;
    if (i < n) { o[i] = a[i]; o[i + n] = b[i]; o[i + 2 * n] = c[i]; }
}

// ---------------- fused flash attention (tf32 mma, unchanged) --------------------
#define FA_QS   0                  // [128][68]
#define FA_KS   8704               // [128][68]
#define FA_VS   17408              // [128][72]
#define FA_PS   26624              // [128][132]
#define FA_RED  43520              // [128][4]
#define FA_MS   44032
#define FA_LS   44160
#define FA_AL   44288
#define FA_WORDS 44416
#define FA_BYTES (FA_WORDS * 4)

__global__ __launch_bounds__(256) void fused_attn(
    const float* __restrict__ q, const float* __restrict__ k,
    const float* __restrict__ v, float* __restrict__ out)
{
    extern __shared__ float fsh[];
    uint32_t* Qs = (uint32_t*)(fsh + FA_QS);
    uint32_t* Ks = (uint32_t*)(fsh + FA_KS);
    uint32_t* Vs = (uint32_t*)(fsh + FA_VS);
    uint32_t* Ps = (uint32_t*)(fsh + FA_PS);
    float* red   = fsh + FA_RED;
    float* m_s   = fsh + FA_MS;
    float* l_s   = fsh + FA_LS;
    float* al_s  = fsh + FA_AL;

    const int t = threadIdx.x;
    const int lane = t & 31, w = t >> 5;
    const int warp_m = w >> 2;
    const int warp_n = w & 3;
    const int ow_m = w >> 1;
    const int ow_n = w & 1;
    const int lr = lane >> 2, lc = lane & 3;

    const int q0 = blockIdx.x * 128;
    const int bh = blockIdx.y, b = bh >> 4, h = bh & 15;
    const size_t qbase = (size_t)(b * Sseq + q0) * Dm + h * 64;
    const size_t kvbase = (size_t)(b * Sseq) * Dm + h * 64;

    #pragma unroll
    for (int i = 0; i < 8; i++) {
        int idx = t + 256 * i;
        int row = idx >> 4, c4 = (idx & 15) * 4;
        float4 qv = *(const float4*)(q + qbase + (size_t)row * Dm + c4);
        uint32_t* d = Qs + row * 68 + c4;
        d[0] = f2tf(qv.x); d[1] = f2tf(qv.y); d[2] = f2tf(qv.z); d[3] = f2tf(qv.w);
    }
    if (t < 128) { m_s[t] = -1e30f; l_s[t] = 0.f; }

    float acc_o[2][4][4];
    #pragma unroll
    for (int mt = 0; mt < 2; mt++)
        #pragma unroll
        for (int nt = 0; nt < 4; nt++)
            #pragma unroll
            for (int i = 0; i < 4; i++) acc_o[mt][nt][i] = 0.f;

    const int a_off = (warp_m * 64 + lr) * 68 + lc;
    const int b_off = (warp_n * 32 + lr) * 68 + lc;
    const int p_off = (ow_m * 32 + lr) * 132 + lc;

    for (int kt = 0; kt < 8; kt++) {
        const size_t kb = kvbase + (size_t)(kt * 128) * Dm;
        #pragma unroll
        for (int i = 0; i < 8; i++) {
            int idx = t + 256 * i;
            int row = idx >> 4, c4 = (idx & 15) * 4;
            float4 kv = *(const float4*)(k + kb + (size_t)row * Dm + c4);
            float4 vv = *(const float4*)(v + kb + (size_t)row * Dm + c4);
            uint32_t* dk = Ks + row * 68 + c4;
            uint32_t* dv = Vs + row * 72 + c4;
            dk[0] = f2tf(kv.x); dk[1] = f2tf(kv.y); dk[2] = f2tf(kv.z); dk[3] = f2tf(kv.w);
            dv[0] = f2tf(vv.x); dv[1] = f2tf(vv.y); dv[2] = f2tf(vv.z); dv[3] = f2tf(vv.w);
        }
        __syncthreads();

        float acc_s[4][4][4];
        #pragma unroll
        for (int mt = 0; mt < 4; mt++)
            #pragma unroll
            for (int nt = 0; nt < 4; nt++)
                #pragma unroll
                for (int i = 0; i < 4; i++) acc_s[mt][nt][i] = 0.f;
        #pragma unroll
        for (int kk = 0; kk < 8; kk++) {
            const int kx = kk * 8;
            uint32_t af[4][4], bf[4][2];
            #pragma unroll
            for (int mt = 0; mt < 4; mt++) {
                af[mt][0] = Qs[a_off + (mt * 16    ) * 68 + kx];
                af[mt][1] = Qs[a_off + (mt * 16 + 8) * 68 + kx];
                af[mt][2] = Qs[a_off + (mt * 16    ) * 68 + kx + 4];
                af[mt][3] = Qs[a_off + (mt * 16 + 8) * 68 + kx + 4];
            }
            #pragma unroll
            for (int nt = 0; nt < 4; nt++) {
                bf[nt][0] = Ks[b_off + (nt * 8) * 68 + kx];
                bf[nt][1] = Ks[b_off + (nt * 8) * 68 + kx + 4];
            }
            #pragma unroll
            for (int mt = 0; mt < 4; mt++)
                #pragma unroll
                for (int nt = 0; nt < 4; nt++)
                    mma_tf32(acc_s[mt][nt], af[mt], bf[nt]);
        }

        #pragma unroll
        for (int mt = 0; mt < 4; mt++) {
            #pragma unroll
            for (int half = 0; half < 2; half++) {
                float pm = -1e30f;
                #pragma unroll
                for (int nt = 0; nt < 4; nt++) {
                    pm = fmaxf(pm, acc_s[mt][nt][half * 2]);
                    pm = fmaxf(pm, acc_s[mt][nt][half * 2 + 1]);
                }
                pm = fmaxf(pm, __shfl_xor_sync(0xffffffffu, pm, 1));
                pm = fmaxf(pm, __shfl_xor_sync(0xffffffffu, pm, 2));
                if (lc == 0)
                    red[(warp_m * 64 + mt * 16 + half * 8 + lr) * 4 + warp_n] = pm;
            }
        }
        __syncthreads();

        if (t < 128) {
            float tm = fmaxf(fmaxf(red[t * 4 + 0], red[t * 4 + 1]),
                             fmaxf(red[t * 4 + 2], red[t * 4 + 3])) * 0.125f;
            float mo = m_s[t];
            float mn = fmaxf(mo, tm);
            al_s[t] = __expf(mo - mn);
            m_s[t]  = mn;
        }
        __syncthreads();

        #pragma unroll
        for (int mt = 0; mt < 4; mt++) {
            #pragma unroll
            for (int half = 0; half < 2; half++) {
                const int row = warp_m * 64 + mt * 16 + half * 8 + lr;
                const float mrow = m_s[row];
                float ps = 0.f;
                #pragma unroll
                for (int nt = 0; nt < 4; nt++) {
                    const int col = warp_n * 32 + nt * 8 + lc * 2;
                    float p0 = __expf(acc_s[mt][nt][half * 2]     * 0.125f - mrow);
                    float p1 = __expf(acc_s[mt][nt][half * 2 + 1] * 0.125f - mrow);
                    ps += p0 + p1;
                    Ps[row * 132 + col]     = f2tf(p0);
                    Ps[row * 132 + col + 1] = f2tf(p1);
                }
                ps += __shfl_xor_sync(0xffffffffu, ps, 1);
                ps += __shfl_xor_sync(0xffffffffu, ps, 2);
                if (lc == 0) red[row * 4 + warp_n] = ps;
            }
        }
        #pragma unroll
        for (int mt = 0; mt < 2; mt++) {
            const int row0 = ow_m * 32 + mt * 16 + lr;
            const float a0 = al_s[row0], a1 = al_s[row0 + 8];
            #pragma unroll
            for (int nt = 0; nt < 4; nt++) {
                acc_o[mt][nt][0] *= a0; acc_o[mt][nt][1] *= a0;
                acc_o[mt][nt][2] *= a1; acc_o[mt][nt][3] *= a1;
            }
        }
        __syncthreads();

        if (t < 128)
            l_s[t] = l_s[t] * al_s[t]
                   + red[t * 4 + 0] + red[t * 4 + 1] + red[t * 4 + 2] + red[t * 4 + 3];

        #pragma unroll
        for (int kk = 0; kk < 16; kk++) {
            const int kx = kk * 8;
            uint32_t af[2][4], bf[4][2];
            #pragma unroll
            for (int mt = 0; mt < 2; mt++) {
                af[mt][0] = Ps[p_off + (mt * 16    ) * 132 + kx];
                af[mt][1] = Ps[p_off + (mt * 16 + 8) * 132 + kx];
                af[mt][2] = Ps[p_off + (mt * 16    ) * 132 + kx + 4];
                af[mt][3] = Ps[p_off + (mt * 16 + 8) * 132 + kx + 4];
            }
            #pragma unroll
            for (int nt = 0; nt < 4; nt++) {
                const int n = ow_n * 32 + nt * 8 + lr;
                bf[nt][0] = Vs[(kx + lc) * 72 + n];
                bf[nt][1] = Vs[(kx + lc + 4) * 72 + n];
            }
            #pragma unroll
            for (int mt = 0; mt < 2; mt++)
                #pragma unroll
                for (int nt = 0; nt < 4; nt++)
                    mma_tf32(acc_o[mt][nt], af[mt], bf[nt]);
        }
        __syncthreads();
    }

    #pragma unroll
    for (int mt = 0; mt < 2; mt++) {
        const int row0 = ow_m * 32 + mt * 16 + lr;
        const float i0 = 1.f / l_s[row0], i1 = 1.f / l_s[row0 + 8];
        #pragma unroll
        for (int nt = 0; nt < 4; nt++) {
            const int col = ow_n * 32 + nt * 8 + lc * 2;
            float* o0 = out + (size_t)(b * Sseq + q0 + row0) * Dm + h * 64 + col;
            float* o1 = out + (size_t)(b * Sseq + q0 + row0 + 8) * Dm + h * 64 + col;
            *(float2*)o0 = make_float2(acc_o[mt][nt][0] * i0, acc_o[mt][nt][1] * i0);
            *(float2*)o1 = make_float2(acc_o[mt][nt][2] * i1, acc_o[mt][nt][3] * i1);
        }
    }
}

// ---------------- block reduction helper -----------------------------------------
__device__ __forceinline__ float block_sum256(float v, float* red) {
    #pragma unroll
    for (int o = 16; o > 0; o >>= 1) v += __shfl_xor_sync(0xffffffffu, v, o);
    if ((threadIdx.x & 31) == 0) red[threadIdx.x >> 5] = v;
    __syncthreads();
    float s = red[0];
    #pragma unroll
    for (int i = 1; i < 8; i++) s += red[i];
    __syncthreads();
    return s;
}

// ---------------- residual add + layernorm ---------------------------------------
__global__ __launch_bounds__(256) void add_ln(
    const float* __restrict__ a, const float* __restrict__ b,
    const float* __restrict__ gamma, const float* __restrict__ beta,
    float* __restrict__ out)
{
    __shared__ float red[8];
    const int t = threadIdx.x;
    const size_t base = (size_t)blockIdx.x * Dm;
    float4 va = ((const float4*)(a + base))[t];
    float4 vb = ((const float4*)(b + base))[t];
    float4 s = make_float4(va.x+vb.x, va.y+vb.y, va.z+vb.z, va.w+vb.w);
    float tot = block_sum256(s.x + s.y + s.z + s.w, red);
    float mu = tot * (1.f / Dm);
    float lq = (s.x-mu)*(s.x-mu) + (s.y-mu)*(s.y-mu) + (s.z-mu)*(s.z-mu) + (s.w-mu)*(s.w-mu);
    float var = block_sum256(lq, red) * (1.f / Dm);
    float rstd = rsqrtf(var + EPSV);
    float4 gg = ((const float4*)gamma)[t];
    float4 bt = ((const float4*)beta)[t];
    float4 o;
    o.x = (s.x - mu) * rstd * gg.x + bt.x;
    o.y = (s.y - mu) * rstd * gg.y + bt.y;
    o.z = (s.z - mu) * rstd * gg.z + bt.z;
    o.w = (s.w - mu) * rstd * gg.w + bt.w;
    ((float4*)(out + base))[t] = o;
}

// ---------------- gate coefficients ----------------------------------------------
__global__ __launch_bounds__(256) void gate_coef(
    const float* __restrict__ xn, const float* __restrict__ gw, float* __restrict__ coef)
{
    __shared__ float red[16][9];
    const int t = threadIdx.x, tkn = blockIdx.x;
    float acc[16];
    #pragma unroll
    for (int ge = 0; ge < 16; ge++) acc[ge] = 0.f;
    for (int d = t; d < Dm; d += 256) {
        float xv = xn[(size_t)tkn*Dm + d];
        #pragma unroll
        for (int ge = 0; ge < 16; ge++)
            acc[ge] = fmaf(xv, gw[(size_t)(ge >> 3)*Dm*Ee + (size_t)d*Ee + (ge & 7)], acc[ge]);
    }
    #pragma unroll
    for (int ge = 0; ge < 16; ge++) {
        float v = acc[ge];
        #pragma unroll
        for (int o = 16; o > 0; o >>= 1) v += __shfl_xor_sync(0xffffffffu, v, o);
        if ((t & 31) == 0) red[ge][t >> 5] = v;
    }
    __syncthreads();
    if (t == 0) {
        float logits[16];
        #pragma unroll
        for (int ge = 0; ge < 16; ge++) {
            float s = 0.f;
            #pragma unroll
            for (int w2 = 0; w2 < 8; w2++) s += red[ge][w2];
            logits[ge] = s;
        }
        float c[8];
        #pragma unroll
        for (int e2 = 0; e2 < 8; e2++) c[e2] = 0.f;
        #pragma unroll
        for (int g = 0; g < 2; g++) {
            float m = logits[g*8];
            #pragma unroll
            for (int e2 = 1; e2 < 8; e2++) m = fmaxf(m, logits[g*8+e2]);
            float s = 0.f, pe[8];
            #pragma unroll
            for (int e2 = 0; e2 < 8; e2++) { pe[e2] = __expf(logits[g*8+e2] - m); s += pe[e2]; }
            float inv = 1.f / s;
            #pragma unroll
            for (int e2 = 0; e2 < 8; e2++) c[e2] += pe[e2] * inv;
        }
        #pragma unroll
        for (int e2 = 0; e2 < 8; e2++) coef[(size_t)tkn*8 + e2] = c[e2] * 0.5f;
    }
}

// ---------------- combine + residual + LN2 ---------------------------------------
__global__ __launch_bounds__(256) void combine_ln(
    const float* __restrict__ eo, const float* __restrict__ coef,
    const float* __restrict__ xn,
    const float* __restrict__ gamma, const float* __restrict__ beta,
    float* __restrict__ out)
{
    __shared__ float red[8];
    __shared__ float cf[8];
    const int t = threadIdx.x, tkn = blockIdx.x;
    if (t < 8) cf[t] = coef[(size_t)tkn*8 + t];
    __syncthreads();
    const size_t base = (size_t)tkn * Dm;
    float4 s = ((const float4*)(xn + base))[t];
    #pragma unroll
    for (int e2 = 0; e2 < 8; e2++) {
        float4 v = ((const float4*)(eo + ((size_t)e2*TOK + tkn)*Dm))[t];
        float c = cf[e2];
        s.x = fmaf(c, v.x, s.x); s.y = fmaf(c, v.y, s.y);
        s.z = fmaf(c, v.z, s.z); s.w = fmaf(c, v.w, s.w);
    }
    float tot = block_sum256(s.x + s.y + s.z + s.w, red);
    float mu = tot * (1.f / Dm);
    float lq = (s.x-mu)*(s.x-mu) + (s.y-mu)*(s.y-mu) + (s.z-mu)*(s.z-mu) + (s.w-mu)*(s.w-mu);
    float var = block_sum256(lq, red) * (1.f / Dm);
    float rstd = rsqrtf(var + EPSV);
    float4 gg = ((const float4*)gamma)[t];
    float4 bt = ((const float4*)beta)[t];
    float4 o;
    o.x = (s.x - mu) * rstd * gg.x + bt.x;
    o.y = (s.y - mu) * rstd * gg.y + bt.y;
    o.z = (s.z - mu) * rstd * gg.z + bt.z;
    o.w = (s.w - mu) * rstd * gg.w + bt.w;
    ((float4*)(out + base))[t] = o;
}

// ---------------- launch ----------------------------------------------------------
extern "C" void kernel_launch(void* const* d_in, const int* in_sizes, int n_in,
                              void* d_out, int out_size)
{
    const float* x     = (const float*)d_in[0];
    const float* wq    = (const float*)d_in[1];
    const float* bq    = (const float*)d_in[2];
    const float* wk    = (const float*)d_in[3];
    const float* bk    = (const float*)d_in[4];
    const float* wv    = (const float*)d_in[5];
    const float* bv    = (const float*)d_in[6];
    const float* wo    = (const float*)d_in[7];
    const float* bo    = (const float*)d_in[8];
    const float* ln1g  = (const float*)d_in[9];
    const float* ln1b  = (const float*)d_in[10];
    const float* ln2g  = (const float*)d_in[11];
    const float* ln2b  = (const float*)d_in[12];
    const float* gatew = (const float*)d_in[13];
    const float* ew1   = (const float*)d_in[14];
    const float* eb1   = (const float*)d_in[15];
    const float* ew2   = (const float*)d_in[16];
    const float* eb2   = (const float*)d_in[17];
    float* out = (float*)d_out;

    float *qkv, *attn, *proj, *normed, *h, *eo, *coef;
    float *wqkvt, *bqkv, *wot, *w1t, *w2t;
    cudaGetSymbolAddress((void**)&qkv,    g_qkv);
    cudaGetSymbolAddress((void**)&attn,   g_attn);
    cudaGetSymbolAddress((void**)&proj,   g_proj);
    cudaGetSymbolAddress((void**)&normed, g_normed);
    cudaGetSymbolAddress((void**)&h,      g_h);
    cudaGetSymbolAddress((void**)&eo,     g_eo);
    cudaGetSymbolAddress((void**)&coef,   g_coef);
    cudaGetSymbolAddress((void**)&wqkvt,  g_wqkvt);
    cudaGetSymbolAddress((void**)&bqkv,   g_bqkv);
    cudaGetSymbolAddress((void**)&wot,    g_wot);
    cudaGetSymbolAddress((void**)&w1t,    g_w1t);
    cudaGetSymbolAddress((void**)&w2t,    g_w2t);

    cudaFuncSetAttribute(mma_gemm<false>, cudaFuncAttributeMaxDynamicSharedMemorySize, SMEM_GEMM_BYTES);
    cudaFuncSetAttribute(mma_gemm<true>,  cudaFuncAttributeMaxDynamicSharedMemorySize, SMEM_GEMM_BYTES);
    cudaFuncSetAttribute(fused_attn,      cudaFuncAttributeMaxDynamicSharedMemorySize, FA_BYTES);

    dim3 blk(256);

    // weight transposes + bias concat
    transpose64<<<dim3(16, 16, 1), blk>>>(wq, wqkvt,           Dm, Dm);
    transpose64<<<dim3(16, 16, 1), blk>>>(wk, wqkvt + Dm*Dm,   Dm, Dm);
    transpose64<<<dim3(16, 16, 1), blk>>>(wv, wqkvt + 2*Dm*Dm, Dm, Dm);
    concat3<<<4, 256>>>(bq, bk, bv, bqkv, Dm);
    transpose64<<<dim3(16, 16, 1), blk>>>(wo, wot,             Dm, Dm);

    // batched QKV GEMM (fp16 mma)
    mma_gemm<false><<<dim3(8, 16, 3), blk, SMEM_GEMM_BYTES>>>(
        x, wqkvt, bqkv, qkv, TOK, Dm, Dm,
        0, (long long)Dm*Dm, (long long)Dm, (long long)TOK*Dm);

    // MoE weight transposes (independent)
    transpose64<<<dim3(Vv/64, Dm/64, Ee), blk>>>(ew1, w1t, Dm, Vv);
    transpose64<<<dim3(Dm/64, Vv/64, Ee), blk>>>(ew2, w2t, Vv, Dm);

    // fused flash attention (tf32)
    fused_attn<<<dim3(8, 32), blk, FA_BYTES>>>(
        qkv, qkv + (size_t)TOK*Dm, qkv + (size_t)2*TOK*Dm, attn);

    // output projection + residual + LN1
    mma_gemm<false><<<dim3(8, 16, 1), blk, SMEM_GEMM_BYTES>>>(
        attn, wot, bo, proj, TOK, Dm, Dm, 0, 0, 0, 0);
    add_ln<<<TOK, blk>>>(proj, x, ln1g, ln1b, normed);

    // MoE (fp16 mma)
    gate_coef<<<TOK, blk>>>(normed, gatew, coef);
    mma_gemm<true><<<dim3(32, 16, Ee), blk, SMEM_GEMM_BYTES>>>(
        normed, w1t, eb1, h, TOK, Vv, Dm,
        0, (long long)Vv*Dm, (long long)Vv, (long long)TOK*Vv);
    mma_gemm<false><<<dim3(8, 16, Ee), blk, SMEM_GEMM_BYTES>>>(
        h, w2t, eb2, eo, TOK, Dm, Vv,
        (long long)TOK*Vv, (long long)Dm*Vv, (long long)Dm, (long long)TOK*Dm);

    // combine + residual + LN2
    combine_ln<<<TOK, blk>>>(eo, coef, normed, ln2g, ln2b, out);
}

// round 15
// speedup vs baseline: 1.6988x; 1.0008x over previous
#include <cuda_runtime.h>
#include <math.h>
#include <stdint.h>

// Problem dims
#define Dm   1024
#define Sseq 1024
#define Bb   2
#define Hh   16
#define Ee   8
#define Vv   4096
#define TOK  (Bb*Sseq)
#define EPSV 1e-5f

// ---------------- device scratch ------------------------------------------------
__device__ float g_qkv[3*TOK*Dm];
__device__ float g_attn[TOK*Dm];
__device__ float g_proj[TOK*Dm];
__device__ float g_normed[TOK*Dm];
__device__ float g_h[(size_t)Ee*TOK*Vv];
__device__ float g_eo[(size_t)Ee*TOK*Dm];
__device__ float g_coef[TOK*Ee];
// transposed weights (N-major: Wt[n][k])
__device__ float g_wqkvt[3*Dm*Dm];
__device__ float g_bqkv[3*Dm];
__device__ float g_wot[Dm*Dm];
__device__ float g_w1t[(size_t)Ee*Vv*Dm];
__device__ float g_w2t[(size_t)Ee*Dm*Vv];

// ---------------- helpers -------------------------------------------------------
__device__ __forceinline__ uint32_t f2tf(float f) {
    uint32_t u; asm("cvt.rna.tf32.f32 %0, %1;" : "=r"(u) : "f"(f)); return u;
}
// pack (lo, hi) floats into f16x2 (lo in low half)
__device__ __forceinline__ uint32_t f2h2(float lo, float hi) {
    uint32_t u; asm("cvt.rn.f16x2.f32 %0, %1, %2;" : "=r"(u) : "f"(hi), "f"(lo)); return u;
}
__device__ __forceinline__ void mma_tf32(float* c, const uint32_t* a, const uint32_t* b) {
    asm volatile("mma.sync.aligned.m16n8k8.row.col.f32.tf32.tf32.f32 "
        "{%0,%1,%2,%3}, {%4,%5,%6,%7}, {%8,%9}, {%0,%1,%2,%3};"
        : "+f"(c[0]), "+f"(c[1]), "+f"(c[2]), "+f"(c[3])
        : "r"(a[0]), "r"(a[1]), "r"(a[2]), "r"(a[3]), "r"(b[0]), "r"(b[1]));
}
__device__ __forceinline__ void mma_f16(float* c, const uint32_t* a, const uint32_t* b) {
    asm volatile("mma.sync.aligned.m16n8k16.row.col.f32.f16.f16.f32 "
        "{%0,%1,%2,%3}, {%4,%5,%6,%7}, {%8,%9}, {%0,%1,%2,%3};"
        : "+f"(c[0]), "+f"(c[1]), "+f"(c[2]), "+f"(c[3])
        : "r"(a[0]), "r"(a[1]), "r"(a[2]), "r"(a[3]), "r"(b[0]), "r"(b[1]));
}

// SMEM geometry for fp16 mma_gemm: K-chunk 64 halves = 32 words + pad -> stride 36.
#define LDS_STRIDE 36
#define TILE_WORDS (128 * LDS_STRIDE)            // 4608 words per matrix buffer
#define SMEM_GEMM_BYTES (4 * TILE_WORDS * 4)     // 2 bufs x (A+B) = 73728

// ---------------- tensor-core fp16 GEMM: C[M,N] = A[M,K] @ Bt[N,K]^T + bias -----
// 128x128 tile, K-chunk 64, m16n8k16 f16 mma (fp32 accum), register-staged
// prefetch, double-buffered smem, 256 threads.
template<bool RELU>
__global__ __launch_bounds__(256) void mma_gemm(
    const float* __restrict__ A, const float* __restrict__ Bt,
    const float* __restrict__ bias, float* __restrict__ C,
    int M, int N, int K,
    long long sA, long long sB, long long sBias, long long sC)
{
    extern __shared__ uint32_t sh[];
    uint32_t* Asm = sh;                    // [2][TILE_WORDS]
    uint32_t* Bsm = sh + 2 * TILE_WORDS;   // [2][TILE_WORDS]

    const int t = threadIdx.x;
    const int lane = t & 31, w = t >> 5;
    const int warp_m = w >> 2;
    const int warp_n = w & 3;
    const int lr = lane >> 2;
    const int lc = lane & 3;

    const int eb = blockIdx.z;
    A    += (size_t)eb * sA;
    Bt   += (size_t)eb * sB;
    bias += (size_t)eb * sBias;
    C    += (size_t)eb * sC;
    const int n0 = blockIdx.x * 128, m0 = blockIdx.y * 128;

    // copy mapping: 16 threads/row, 4 floats each -> 64 k-floats; rows r0+16i
    const int kc = (t & 15) * 4;          // float col within 64-chunk
    const int r0 = t >> 4;
    const float* Ag = A  + (size_t)(m0 + r0) * K + kc;
    const float* Bg = Bt + (size_t)(n0 + r0) * K + kc;
    const int sts_base = r0 * LDS_STRIDE + (t & 15) * 2;   // word offset (2 words per thread)

    float acc[4][4][4];
    #pragma unroll
    for (int mt = 0; mt < 4; mt++)
        #pragma unroll
        for (int nt = 0; nt < 4; nt++)
            #pragma unroll
            for (int i = 0; i < 4; i++) acc[mt][nt][i] = 0.f;

    const int nst = K >> 6;

    // stage 0 -> buf 0
    {
        float4 pa[8], pb[8];
        #pragma unroll
        for (int i = 0; i < 8; i++) {
            pa[i] = *(const float4*)(Ag + (size_t)(16 * i) * K);
            pb[i] = *(const float4*)(Bg + (size_t)(16 * i) * K);
        }
        #pragma unroll
        for (int i = 0; i < 8; i++) {
            uint2 ha = make_uint2(f2h2(pa[i].x, pa[i].y), f2h2(pa[i].z, pa[i].w));
            uint2 hb = make_uint2(f2h2(pb[i].x, pb[i].y), f2h2(pb[i].z, pb[i].w));
            *(uint2*)(Asm + sts_base + i * 16 * LDS_STRIDE) = ha;
            *(uint2*)(Bsm + sts_base + i * 16 * LDS_STRIDE) = hb;
        }
    }
    __syncthreads();

    const int a_off = (warp_m * 64 + lr) * LDS_STRIDE + lc;
    const int b_off = (warp_n * 32 + lr) * LDS_STRIDE + lc;

    for (int s = 0; s < nst; s++) {
        const int buf = s & 1;
        const bool more = (s + 1) < nst;
        float4 pa[8], pb[8];
        if (more) {
            const float* ag = Ag + (size_t)(64 * (s + 1));
            const float* bg = Bg + (size_t)(64 * (s + 1));
            #pragma unroll
            for (int i = 0; i < 8; i++) {
                pa[i] = *(const float4*)(ag + (size_t)(16 * i) * K);
                pb[i] = *(const float4*)(bg + (size_t)(16 * i) * K);
            }
        }

        const uint32_t* Apt = Asm + buf * TILE_WORDS + a_off;
        const uint32_t* Bpt = Bsm + buf * TILE_WORDS + b_off;
        #pragma unroll
        for (int ks = 0; ks < 4; ks++) {
            const int k = ks * 8;
            uint32_t af[4][4], bf[4][2];
            #pragma unroll
            for (int mt = 0; mt < 4; mt++) {
                af[mt][0] = Apt[(mt * 16    ) * LDS_STRIDE + k];
                af[mt][1] = Apt[(mt * 16 + 8) * LDS_STRIDE + k];
                af[mt][2] = Apt[(mt * 16    ) * LDS_STRIDE + k + 4];
                af[mt][3] = Apt[(mt * 16 + 8) * LDS_STRIDE + k + 4];
            }
            #pragma unroll
            for (int nt = 0; nt < 4; nt++) {
                bf[nt][0] = Bpt[(nt * 8) * LDS_STRIDE + k];
                bf[nt][1] = Bpt[(nt * 8) * LDS_STRIDE + k + 4];
            }
            #pragma unroll
            for (int mt = 0; mt < 4; mt++)
                #pragma unroll
                for (int nt = 0; nt < 4; nt++)
                    mma_f16(acc[mt][nt], af[mt], bf[nt]);
        }

        if (more) {
            const int nb = (s + 1) & 1;
            #pragma unroll
            for (int i = 0; i < 8; i++) {
                uint2 ha = make_uint2(f2h2(pa[i].x, pa[i].y), f2h2(pa[i].z, pa[i].w));
                uint2 hb = make_uint2(f2h2(pb[i].x, pb[i].y), f2h2(pb[i].z, pb[i].w));
                *(uint2*)(Asm + nb * TILE_WORDS + sts_base + i * 16 * LDS_STRIDE) = ha;
                *(uint2*)(Bsm + nb * TILE_WORDS + sts_base + i * 16 * LDS_STRIDE) = hb;
            }
        }
        __syncthreads();
    }

    #pragma unroll
    for (int mt = 0; mt < 4; mt++) {
        const int m = m0 + warp_m * 64 + mt * 16 + lr;
        #pragma unroll
        for (int nt = 0; nt < 4; nt++) {
            const int n = n0 + warp_n * 32 + nt * 8 + lc * 2;
            const float b0 = bias[n], b1 = bias[n + 1];
            float o0 = acc[mt][nt][0] + b0, o1 = acc[mt][nt][1] + b1;
            float o2 = acc[mt][nt][2] + b0, o3 = acc[mt][nt][3] + b1;
            if (RELU) {
                o0 = fmaxf(o0, 0.f); o1 = fmaxf(o1, 0.f);
                o2 = fmaxf(o2, 0.f); o3 = fmaxf(o3, 0.f);
            }
            *(float2*)(C + (size_t)m * N + n)       = make_float2(o0, o1);
            *(float2*)(C + (size_t)(m + 8) * N + n) = make_float2(o2, o3);
        }
    }
}

// ---------------- fast transpose: out[C,R] = in[R,C]^T, float4 both sides --------
__global__ __launch_bounds__(256) void transpose64(
    const float* __restrict__ in, float* __restrict__ out, int R, int C)
{
    __shared__ float s[64][68];
    const size_t eoff = (size_t)blockIdx.z * (size_t)R * C;
    in += eoff; out += eoff;
    const int c0 = blockIdx.x * 64, r0 = blockIdx.y * 64;
    const int t = threadIdx.x;
    #pragma unroll
    for (int i = 0; i < 4; i++) {
        int idx = t + 256 * i;
        int row = idx >> 4, cx = (idx & 15) * 4;
        float4 v = *(const float4*)(in + (size_t)(r0 + row) * C + c0 + cx);
        s[cx + 0][row] = v.x; s[cx + 1][row] = v.y;
        s[cx + 2][row] = v.z; s[cx + 3][row] = v.w;
    }
    __syncthreads();
    #pragma unroll
    for (int i = 0; i < 4; i++) {
        int idx = t + 256 * i;
        int orow = idx >> 4, rx = (idx & 15) * 4;
        float4 o = *(float4*)&s[orow][rx];
        *(float4*)(out + (size_t)(c0 + orow) * R + r0 + rx) = o;
    }
}

// ---------------- concat 3 bias vectors ------------------------------------------
__global__ void concat3(const float* __restrict__ a, const float* __restrict__ b,
                        const float* __restrict__ c, float* __restrict__ o, int n)
{
    int i = blockIdx.x * 256 + threadIdx.x;
    if (i < n) { o[i] = a[i]; o[i + n] = b[i]; o[i + 2 * n] = c[i]; }
}

// ---------------- fused flash attention (tf32 mma, unchanged) --------------------
#define FA_QS   0                  // [128][68]
#define FA_KS   8704               // [128][68]
#define FA_VS   17408              // [128][72]
#define FA_PS   26624              // [128][132]
#define FA_RED  43520              // [128][4]
#define FA_MS   44032
#define FA_LS   44160
#define FA_AL   44288
#define FA_WORDS 44416
#define FA_BYTES (FA_WORDS * 4)

__global__ __launch_bounds__(256) void fused_attn(
    const float* __restrict__ q, const float* __restrict__ k,
    const float* __restrict__ v, float* __restrict__ out)
{
    extern __shared__ float fsh[];
    uint32_t* Qs = (uint32_t*)(fsh + FA_QS);
    uint32_t* Ks = (uint32_t*)(fsh + FA_KS);
    uint32_t* Vs = (uint32_t*)(fsh + FA_VS);
    uint32_t* Ps = (uint32_t*)(fsh + FA_PS);
    float* red   = fsh + FA_RED;
    float* m_s   = fsh + FA_MS;
    float* l_s   = fsh + FA_LS;
    float* al_s  = fsh + FA_AL;

    const int t = threadIdx.x;
    const int lane = t & 31, w = t >> 5;
    const int warp_m = w >> 2;
    const int warp_n = w & 3;
    const int ow_m = w >> 1;
    const int ow_n = w & 1;
    const int lr = lane >> 2, lc = lane & 3;

    const int q0 = blockIdx.x * 128;
    const int bh = blockIdx.y, b = bh >> 4, h = bh & 15;
    const size_t qbase = (size_t)(b * Sseq + q0) * Dm + h * 64;
    const size_t kvbase = (size_t)(b * Sseq) * Dm + h * 64;

    #pragma unroll
    for (int i = 0; i < 8; i++) {
        int idx = t + 256 * i;
        int row = idx >> 4, c4 = (idx & 15) * 4;
        float4 qv = *(const float4*)(q + qbase + (size_t)row * Dm + c4);
        uint32_t* d = Qs + row * 68 + c4;
        d[0] = f2tf(qv.x); d[1] = f2tf(qv.y); d[2] = f2tf(qv.z); d[3] = f2tf(qv.w);
    }
    if (t < 128) { m_s[t] = -1e30f; l_s[t] = 0.f; }

    float acc_o[2][4][4];
    #pragma unroll
    for (int mt = 0; mt < 2; mt++)
        #pragma unroll
        for (int nt = 0; nt < 4; nt++)
            #pragma unroll
            for (int i = 0; i < 4; i++) acc_o[mt][nt][i] = 0.f;

    const int a_off = (warp_m * 64 + lr) * 68 + lc;
    const int b_off = (warp_n * 32 + lr) * 68 + lc;
    const int p_off = (ow_m * 32 + lr) * 132 + lc;

    for (int kt = 0; kt < 8; kt++) {
        const size_t kb = kvbase + (size_t)(kt * 128) * Dm;
        #pragma unroll
        for (int i = 0; i < 8; i++) {
            int idx = t + 256 * i;
            int row = idx >> 4, c4 = (idx & 15) * 4;
            float4 kv = *(const float4*)(k + kb + (size_t)row * Dm + c4);
            float4 vv = *(const float4*)(v + kb + (size_t)row * Dm + c4);
            uint32_t* dk = Ks + row * 68 + c4;
            uint32_t* dv = Vs + row * 72 + c4;
            dk[0] = f2tf(kv.x); dk[1] = f2tf(kv.y); dk[2] = f2tf(kv.z); dk[3] = f2tf(kv.w);
            dv[0] = f2tf(vv.x); dv[1] = f2tf(vv.y); dv[2] = f2tf(vv.z); dv[3] = f2tf(vv.w);
        }
        __syncthreads();

        float acc_s[4][4][4];
        #pragma unroll
        for (int mt = 0; mt < 4; mt++)
            #pragma unroll
            for (int nt = 0; nt < 4; nt++)
                #pragma unroll
                for (int i = 0; i < 4; i++) acc_s[mt][nt][i] = 0.f;
        #pragma unroll
        for (int kk = 0; kk < 8; kk++) {
            const int kx = kk * 8;
            uint32_t af[4][4], bf[4][2];
            #pragma unroll
            for (int mt = 0; mt < 4; mt++) {
                af[mt][0] = Qs[a_off + (mt * 16    ) * 68 + kx];
                af[mt][1] = Qs[a_off + (mt * 16 + 8) * 68 + kx];
                af[mt][2] = Qs[a_off + (mt * 16    ) * 68 + kx + 4];
                af[mt][3] = Qs[a_off + (mt * 16 + 8) * 68 + kx + 4];
            }
            #pragma unroll
            for (int nt = 0; nt < 4; nt++) {
                bf[nt][0] = Ks[b_off + (nt * 8) * 68 + kx];
                bf[nt][1] = Ks[b_off + (nt * 8) * 68 + kx + 4];
            }
            #pragma unroll
            for (int mt = 0; mt < 4; mt++)
                #pragma unroll
                for (int nt = 0; nt < 4; nt++)
                    mma_tf32(acc_s[mt][nt], af[mt], bf[nt]);
        }

        #pragma unroll
        for (int mt = 0; mt < 4; mt++) {
            #pragma unroll
            for (int half = 0; half < 2; half++) {
                float pm = -1e30f;
                #pragma unroll
                for (int nt = 0; nt < 4; nt++) {
                    pm = fmaxf(pm, acc_s[mt][nt][half * 2]);
                    pm = fmaxf(pm, acc_s[mt][nt][half * 2 + 1]);
                }
                pm = fmaxf(pm, __shfl_xor_sync(0xffffffffu, pm, 1));
                pm = fmaxf(pm, __shfl_xor_sync(0xffffffffu, pm, 2));
                if (lc == 0)
                    red[(warp_m * 64 + mt * 16 + half * 8 + lr) * 4 + warp_n] = pm;
            }
        }
        __syncthreads();

        if (t < 128) {
            float tm = fmaxf(fmaxf(red[t * 4 + 0], red[t * 4 + 1]),
                             fmaxf(red[t * 4 + 2], red[t * 4 + 3])) * 0.125f;
            float mo = m_s[t];
            float mn = fmaxf(mo, tm);
            al_s[t] = __expf(mo - mn);
            m_s[t]  = mn;
        }
        __syncthreads();

        #pragma unroll
        for (int mt = 0; mt < 4; mt++) {
            #pragma unroll
            for (int half = 0; half < 2; half++) {
                const int row = warp_m * 64 + mt * 16 + half * 8 + lr;
                const float mrow = m_s[row];
                float ps = 0.f;
                #pragma unroll
                for (int nt = 0; nt < 4; nt++) {
                    const int col = warp_n * 32 + nt * 8 + lc * 2;
                    float p0 = __expf(acc_s[mt][nt][half * 2]     * 0.125f - mrow);
                    float p1 = __expf(acc_s[mt][nt][half * 2 + 1] * 0.125f - mrow);
                    ps += p0 + p1;
                    Ps[row * 132 + col]     = f2tf(p0);
                    Ps[row * 132 + col + 1] = f2tf(p1);
                }
                ps += __shfl_xor_sync(0xffffffffu, ps, 1);
                ps += __shfl_xor_sync(0xffffffffu, ps, 2);
                if (lc == 0) red[row * 4 + warp_n] = ps;
            }
        }
        #pragma unroll
        for (int mt = 0; mt < 2; mt++) {
            const int row0 = ow_m * 32 + mt * 16 + lr;
            const float a0 = al_s[row0], a1 = al_s[row0 + 8];
            #pragma unroll
            for (int nt = 0; nt < 4; nt++) {
                acc_o[mt][nt][0] *= a0; acc_o[mt][nt][1] *= a0;
                acc_o[mt][nt][2] *= a1; acc_o[mt][nt][3] *= a1;
            }
        }
        __syncthreads();

        if (t < 128)
            l_s[t] = l_s[t] * al_s[t]
                   + red[t * 4 + 0] + red[t * 4 + 1] + red[t * 4 + 2] + red[t * 4 + 3];

        #pragma unroll
        for (int kk = 0; kk < 16; kk++) {
            const int kx = kk * 8;
            uint32_t af[2][4], bf[4][2];
            #pragma unroll
            for (int mt = 0; mt < 2; mt++) {
                af[mt][0] = Ps[p_off + (mt * 16    ) * 132 + kx];
                af[mt][1] = Ps[p_off + (mt * 16 + 8) * 132 + kx];
                af[mt][2] = Ps[p_off + (mt * 16    ) * 132 + kx + 4];
                af[mt][3] = Ps[p_off + (mt * 16 + 8) * 132 + kx + 4];
            }
            #pragma unroll
            for (int nt = 0; nt < 4; nt++) {
                const int n = ow_n * 32 + nt * 8 + lr;
                bf[nt][0] = Vs[(kx + lc) * 72 + n];
                bf[nt][1] = Vs[(kx + lc + 4) * 72 + n];
            }
            #pragma unroll
            for (int mt = 0; mt < 2; mt++)
                #pragma unroll
                for (int nt = 0; nt < 4; nt++)
                    mma_tf32(acc_o[mt][nt], af[mt], bf[nt]);
        }
        __syncthreads();
    }

    #pragma unroll
    for (int mt = 0; mt < 2; mt++) {
        const int row0 = ow_m * 32 + mt * 16 + lr;
        const float i0 = 1.f / l_s[row0], i1 = 1.f / l_s[row0 + 8];
        #pragma unroll
        for (int nt = 0; nt < 4; nt++) {
            const int col = ow_n * 32 + nt * 8 + lc * 2;
            float* o0 = out + (size_t)(b * Sseq + q0 + row0) * Dm + h * 64 + col;
            float* o1 = out + (size_t)(b * Sseq + q0 + row0 + 8) * Dm + h * 64 + col;
            *(float2*)o0 = make_float2(acc_o[mt][nt][0] * i0, acc_o[mt][nt][1] * i0);
            *(float2*)o1 = make_float2(acc_o[mt][nt][2] * i1, acc_o[mt][nt][3] * i1);
        }
    }
}

// ---------------- block reduction helper -----------------------------------------
__device__ __forceinline__ float block_sum256(float v, float* red) {
    #pragma unroll
    for (int o = 16; o > 0; o >>= 1) v += __shfl_xor_sync(0xffffffffu, v, o);
    if ((threadIdx.x & 31) == 0) red[threadIdx.x >> 5] = v;
    __syncthreads();
    float s = red[0];
    #pragma unroll
    for (int i = 1; i < 8; i++) s += red[i];
    __syncthreads();
    return s;
}

// ---------------- residual add + layernorm ---------------------------------------
__global__ __launch_bounds__(256) void add_ln(
    const float* __restrict__ a, const float* __restrict__ b,
    const float* __restrict__ gamma, const float* __restrict__ beta,
    float* __restrict__ out)
{
    __shared__ float red[8];
    const int t = threadIdx.x;
    const size_t base = (size_t)blockIdx.x * Dm;
    float4 va = ((const float4*)(a + base))[t];
    float4 vb = ((const float4*)(b + base))[t];
    float4 s = make_float4(va.x+vb.x, va.y+vb.y, va.z+vb.z, va.w+vb.w);
    float tot = block_sum256(s.x + s.y + s.z + s.w, red);
    float mu = tot * (1.f / Dm);
    float lq = (s.x-mu)*(s.x-mu) + (s.y-mu)*(s.y-mu) + (s.z-mu)*(s.z-mu) + (s.w-mu)*(s.w-mu);
    float var = block_sum256(lq, red) * (1.f / Dm);
    float rstd = rsqrtf(var + EPSV);
    float4 gg = ((const float4*)gamma)[t];
    float4 bt = ((const float4*)beta)[t];
    float4 o;
    o.x = (s.x - mu) * rstd * gg.x + bt.x;
    o.y = (s.y - mu) * rstd * gg.y + bt.y;
    o.z = (s.z - mu) * rstd * gg.z + bt.z;
    o.w = (s.w - mu) * rstd * gg.w + bt.w;
    ((float4*)(out + base))[t] = o;
}

// ---------------- gate coefficients ----------------------------------------------
__global__ __launch_bounds__(256) void gate_coef(
    const float* __restrict__ xn, const float* __restrict__ gw, float* __restrict__ coef)
{
    __shared__ float red[16][9];
    const int t = threadIdx.x, tkn = blockIdx.x;
    float acc[16];
    #pragma unroll
    for (int ge = 0; ge < 16; ge++) acc[ge] = 0.f;
    for (int d = t; d < Dm; d += 256) {
        float xv = xn[(size_t)tkn*Dm + d];
        #pragma unroll
        for (int ge = 0; ge < 16; ge++)
            acc[ge] = fmaf(xv, gw[(size_t)(ge >> 3)*Dm*Ee + (size_t)d*Ee + (ge & 7)], acc[ge]);
    }
    #pragma unroll
    for (int ge = 0; ge < 16; ge++) {
        float v = acc[ge];
        #pragma unroll
        for (int o = 16; o > 0; o >>= 1) v += __shfl_xor_sync(0xffffffffu, v, o);
        if ((t & 31) == 0) red[ge][t >> 5] = v;
    }
    __syncthreads();
    if (t == 0) {
        float logits[16];
        #pragma unroll
        for (int ge = 0; ge < 16; ge++) {
            float s = 0.f;
            #pragma unroll
            for (int w2 = 0; w2 < 8; w2++) s += red[ge][w2];
            logits[ge] = s;
        }
        float c[8];
        #pragma unroll
        for (int e2 = 0; e2 < 8; e2++) c[e2] = 0.f;
        #pragma unroll
        for (int g = 0; g < 2; g++) {
            float m = logits[g*8];
            #pragma unroll
            for (int e2 = 1; e2 < 8; e2++) m = fmaxf(m, logits[g*8+e2]);
            float s = 0.f, pe[8];
            #pragma unroll
            for (int e2 = 0; e2 < 8; e2++) { pe[e2] = __expf(logits[g*8+e2] - m); s += pe[e2]; }
            float inv = 1.f / s;
            #pragma unroll
            for (int e2 = 0; e2 < 8; e2++) c[e2] += pe[e2] * inv;
        }
        #pragma unroll
        for (int e2 = 0; e2 < 8; e2++) coef[(size_t)tkn*8 + e2] = c[e2] * 0.5f;
    }
}

// ---------------- combine + residual + LN2 ---------------------------------------
__global__ __launch_bounds__(256) void combine_ln(
    const float* __restrict__ eo, const float* __restrict__ coef,
    const float* __restrict__ xn,
    const float* __restrict__ gamma, const float* __restrict__ beta,
    float* __restrict__ out)
{
    __shared__ float red[8];
    __shared__ float cf[8];
    const int t = threadIdx.x, tkn = blockIdx.x;
    if (t < 8) cf[t] = coef[(size_t)tkn*8 + t];
    __syncthreads();
    const size_t base = (size_t)tkn * Dm;
    float4 s = ((const float4*)(xn + base))[t];
    #pragma unroll
    for (int e2 = 0; e2 < 8; e2++) {
        float4 v = ((const float4*)(eo + ((size_t)e2*TOK + tkn)*Dm))[t];
        float c = cf[e2];
        s.x = fmaf(c, v.x, s.x); s.y = fmaf(c, v.y, s.y);
        s.z = fmaf(c, v.z, s.z); s.w = fmaf(c, v.w, s.w);
    }
    float tot = block_sum256(s.x + s.y + s.z + s.w, red);
    float mu = tot * (1.f / Dm);
    float lq = (s.x-mu)*(s.x-mu) + (s.y-mu)*(s.y-mu) + (s.z-mu)*(s.z-mu) + (s.w-mu)*(s.w-mu);
    float var = block_sum256(lq, red) * (1.f / Dm);
    float rstd = rsqrtf(var + EPSV);
    float4 gg = ((const float4*)gamma)[t];
    float4 bt = ((const float4*)beta)[t];
    float4 o;
    o.x = (s.x - mu) * rstd * gg.x + bt.x;
    o.y = (s.y - mu) * rstd * gg.y + bt.y;
    o.z = (s.z - mu) * rstd * gg.z + bt.z;
    o.w = (s.w - mu) * rstd * gg.w + bt.w;
    ((float4*)(out + base))[t] = o;
}

// ---------------- launch ----------------------------------------------------------
extern "C" void kernel_launch(void* const* d_in, const int* in_sizes, int n_in,
                              void* d_out, int out_size)
{
    const float* x     = (const float*)d_in[0];
    const float* wq    = (const float*)d_in[1];
    const float* bq    = (const float*)d_in[2];
    const float* wk    = (const float*)d_in[3];
    const float* bk    = (const float*)d_in[4];
    const float* wv    = (const float*)d_in[5];
    const float* bv    = (const float*)d_in[6];
    const float* wo    = (const float*)d_in[7];
    const float* bo    = (const float*)d_in[8];
    const float* ln1g  = (const float*)d_in[9];
    const float* ln1b  = (const float*)d_in[10];
    const float* ln2g  = (const float*)d_in[11];
    const float* ln2b  = (const float*)d_in[12];
    const float* gatew = (const float*)d_in[13];
    const float* ew1   = (const float*)d_in[14];
    const float* eb1   = (const float*)d_in[15];
    const float* ew2   = (const float*)d_in[16];
    const float* eb2   = (const float*)d_in[17];
    float* out = (float*)d_out;

    float *qkv, *attn, *proj, *normed, *h, *eo, *coef;
    float *wqkvt, *bqkv, *wot, *w1t, *w2t;
    cudaGetSymbolAddress((void**)&qkv,    g_qkv);
    cudaGetSymbolAddress((void**)&attn,   g_attn);
    cudaGetSymbolAddress((void**)&proj,   g_proj);
    cudaGetSymbolAddress((void**)&normed, g_normed);
    cudaGetSymbolAddress((void**)&h,      g_h);
    cudaGetSymbolAddress((void**)&eo,     g_eo);
    cudaGetSymbolAddress((void**)&coef,   g_coef);
    cudaGetSymbolAddress((void**)&wqkvt,  g_wqkvt);
    cudaGetSymbolAddress((void**)&bqkv,   g_bqkv);
    cudaGetSymbolAddress((void**)&wot,    g_wot);
    cudaGetSymbolAddress((void**)&w1t,    g_w1t);
    cudaGetSymbolAddress((void**)&w2t,    g_w2t);

    cudaFuncSetAttribute(mma_gemm<false>, cudaFuncAttributeMaxDynamicSharedMemorySize, SMEM_GEMM_BYTES);
    cudaFuncSetAttribute(mma_gemm<true>,  cudaFuncAttributeMaxDynamicSharedMemorySize, SMEM_GEMM_BYTES);
    cudaFuncSetAttribute(fused_attn,      cudaFuncAttributeMaxDynamicSharedMemorySize, FA_BYTES);

    dim3 blk(256);

    // weight transposes + bias concat
    transpose64<<<dim3(16, 16, 1), blk>>>(wq, wqkvt,           Dm, Dm);
    transpose64<<<dim3(16, 16, 1), blk>>>(wk, wqkvt + Dm*Dm,   Dm, Dm);
    transpose64<<<dim3(16, 16, 1), blk>>>(wv, wqkvt + 2*Dm*Dm, Dm, Dm);
    concat3<<<4, 256>>>(bq, bk, bv, bqkv, Dm);
    transpose64<<<dim3(16, 16, 1), blk>>>(wo, wot,             Dm, Dm);

    // batched QKV GEMM (fp16 mma)
    mma_gemm<false><<<dim3(8, 16, 3), blk, SMEM_GEMM_BYTES>>>(
        x, wqkvt, bqkv, qkv, TOK, Dm, Dm,
        0, (long long)Dm*Dm, (long long)Dm, (long long)TOK*Dm);

    // MoE weight transposes (independent)
    transpose64<<<dim3(Vv/64, Dm/64, Ee), blk>>>(ew1, w1t, Dm, Vv);
    transpose64<<<dim3(Dm/64, Vv/64, Ee), blk>>>(ew2, w2t, Vv, Dm);

    // fused flash attention (tf32)
    fused_attn<<<dim3(8, 32), blk, FA_BYTES>>>(
        qkv, qkv + (size_t)TOK*Dm, qkv + (size_t)2*TOK*Dm, attn);

    // output projection + residual + LN1
    mma_gemm<false><<<dim3(8, 16, 1), blk, SMEM_GEMM_BYTES>>>(
        attn, wot, bo, proj, TOK, Dm, Dm, 0, 0, 0, 0);
    add_ln<<<TOK, blk>>>(proj, x, ln1g, ln1b, normed);

    // MoE (fp16 mma)
    gate_coef<<<TOK, blk>>>(normed, gatew, coef);
    mma_gemm<true><<<dim3(32, 16, Ee), blk, SMEM_GEMM_BYTES>>>(
        normed, w1t, eb1, h, TOK, Vv, Dm,
        0, (long long)Vv*Dm, (long long)Vv, (long long)TOK*Vv);
    mma_gemm<false><<<dim3(8, 16, Ee), blk, SMEM_GEMM_BYTES>>>(
        h, w2t, eb2, eo, TOK, Dm, Vv,
        (long long)TOK*Vv, (long long)Dm*Vv, (long long)Dm, (long long)TOK*Dm);

    // combine + residual + LN2
    combine_ln<<<TOK, blk>>>(eo, coef, normed, ln2g, ln2b, out);
}

// round 16
// speedup vs baseline: 1.8575x; 1.0934x over previous
#include <cuda_runtime.h>
#include <cuda_fp16.h>
#include <math.h>
#include <stdint.h>

// Problem dims
#define Dm   1024
#define Sseq 1024
#define Bb   2
#define Hh   16
#define Ee   8
#define Vv   4096
#define TOK  (Bb*Sseq)
#define EPSV 1e-5f

// ---------------- device scratch ------------------------------------------------
__device__ float  g_qkv[3*TOK*Dm];
__device__ float  g_attn[TOK*Dm];
__device__ float  g_proj[TOK*Dm];
__device__ float  g_normed[TOK*Dm];
__device__ __half g_h[(size_t)Ee*TOK*Vv];
__device__ float  g_eo[(size_t)Ee*TOK*Dm];
__device__ float  g_coef[TOK*Ee];
// transposed weights, fp16 (N-major: Wt[n][k])
__device__ __half g_wqkvt[3*Dm*Dm];
__device__ float  g_bqkv[3*Dm];
__device__ __half g_wot[Dm*Dm];
__device__ __half g_w1t[(size_t)Ee*Vv*Dm];
__device__ __half g_w2t[(size_t)Ee*Dm*Vv];

// ---------------- helpers -------------------------------------------------------
__device__ __forceinline__ uint32_t f2tf(float f) {
    uint32_t u; asm("cvt.rna.tf32.f32 %0, %1;" : "=r"(u) : "f"(f)); return u;
}
// pack (lo, hi) floats into f16x2 (lo in low half)
__device__ __forceinline__ uint32_t f2h2(float lo, float hi) {
    uint32_t u; asm("cvt.rn.f16x2.f32 %0, %1, %2;" : "=r"(u) : "f"(hi), "f"(lo)); return u;
}
__device__ __forceinline__ void mma_tf32(float* c, const uint32_t* a, const uint32_t* b) {
    asm volatile("mma.sync.aligned.m16n8k8.row.col.f32.tf32.tf32.f32 "
        "{%0,%1,%2,%3}, {%4,%5,%6,%7}, {%8,%9}, {%0,%1,%2,%3};"
        : "+f"(c[0]), "+f"(c[1]), "+f"(c[2]), "+f"(c[3])
        : "r"(a[0]), "r"(a[1]), "r"(a[2]), "r"(a[3]), "r"(b[0]), "r"(b[1]));
}
__device__ __forceinline__ void mma_f16(float* c, const uint32_t* a, const uint32_t* b) {
    asm volatile("mma.sync.aligned.m16n8k16.row.col.f32.f16.f16.f32 "
        "{%0,%1,%2,%3}, {%4,%5,%6,%7}, {%8,%9}, {%0,%1,%2,%3};"
        : "+f"(c[0]), "+f"(c[1]), "+f"(c[2]), "+f"(c[3])
        : "r"(a[0]), "r"(a[1]), "r"(a[2]), "r"(a[3]), "r"(b[0]), "r"(b[1]));
}

// SMEM geometry: K-chunk 64 halves = 32 words + pad -> stride 36.
#define LDS_STRIDE 36
#define TILE_WORDS (128 * LDS_STRIDE)            // 4608 words per matrix buffer
#define SMEM_GEMM_BYTES (4 * TILE_WORDS * 4)     // 2 bufs x (A+B) = 73728

// ---------------- tensor-core fp16 GEMM: C[M,N] = A[M,K] @ Bt[N,K]^T + bias -----
// B (and optionally A) read as fp16 from global; optional fp16 output.
template<bool RELU, bool A_HALF, bool OUT_HALF>
__global__ __launch_bounds__(256) void mma_gemm(
    const void* __restrict__ Av, const __half* __restrict__ Btw,
    const float* __restrict__ bias, void* __restrict__ Cv,
    int M, int N, int K,
    long long sA, long long sB, long long sBias, long long sC)
{
    extern __shared__ uint32_t sh[];
    uint32_t* Asm = sh;                    // [2][TILE_WORDS]
    uint32_t* Bsm = sh + 2 * TILE_WORDS;   // [2][TILE_WORDS]

    const int t = threadIdx.x;
    const int lane = t & 31, w = t >> 5;
    const int warp_m = w >> 2;
    const int warp_n = w & 3;
    const int lr = lane >> 2;
    const int lc = lane & 3;

    const int eb = blockIdx.z;
    const float*  Af = (const float*)Av  + (A_HALF ? 0 : (size_t)eb * sA);
    const __half* Ah = (const __half*)Av + (A_HALF ? (size_t)eb * sA : 0);
    const __half* Bt = Btw + (size_t)eb * sB;
    bias += (size_t)eb * sBias;
    float*  Cf = (float*)Cv  + (OUT_HALF ? 0 : (size_t)eb * sC);
    __half* Ch = (__half*)Cv + (OUT_HALF ? (size_t)eb * sC : 0);
    const int n0 = blockIdx.x * 128, m0 = blockIdx.y * 128;

    // copy mapping: 16 threads/row, 4 elements each -> 64 k-elements; rows r0+16i
    const int kc = (t & 15) * 4;
    const int r0 = t >> 4;
    const float*  Agf = Af + (size_t)(m0 + r0) * K + kc;
    const __half* Agh = Ah + (size_t)(m0 + r0) * K + kc;
    const __half* Bg  = Bt + (size_t)(n0 + r0) * K + kc;
    const int sts_base = r0 * LDS_STRIDE + (t & 15) * 2;

    float acc[4][4][4];
    #pragma unroll
    for (int mt = 0; mt < 4; mt++)
        #pragma unroll
        for (int nt = 0; nt < 4; nt++)
            #pragma unroll
            for (int i = 0; i < 4; i++) acc[mt][nt][i] = 0.f;

    const int nst = K >> 6;

    // stage 0 -> buf 0
    {
        uint2 ha[8], hb[8];
        #pragma unroll
        for (int i = 0; i < 8; i++) {
            if (A_HALF) {
                ha[i] = *(const uint2*)(Agh + (size_t)(16 * i) * K);
            } else {
                float4 v = *(const float4*)(Agf + (size_t)(16 * i) * K);
                ha[i] = make_uint2(f2h2(v.x, v.y), f2h2(v.z, v.w));
            }
            hb[i] = *(const uint2*)(Bg + (size_t)(16 * i) * K);
        }
        #pragma unroll
        for (int i = 0; i < 8; i++) {
            *(uint2*)(Asm + sts_base + i * 16 * LDS_STRIDE) = ha[i];
            *(uint2*)(Bsm + sts_base + i * 16 * LDS_STRIDE) = hb[i];
        }
    }
    __syncthreads();

    const int a_off = (warp_m * 64 + lr) * LDS_STRIDE + lc;
    const int b_off = (warp_n * 32 + lr) * LDS_STRIDE + lc;

    for (int s = 0; s < nst; s++) {
        const int buf = s & 1;
        const bool more = (s + 1) < nst;
        uint2 pa[8], pb[8];
        if (more) {
            const int koff = 64 * (s + 1);
            #pragma unroll
            for (int i = 0; i < 8; i++) {
                if (A_HALF) {
                    pa[i] = *(const uint2*)(Agh + koff + (size_t)(16 * i) * K);
                } else {
                    float4 v = *(const float4*)(Agf + koff + (size_t)(16 * i) * K);
                    pa[i] = make_uint2(f2h2(v.x, v.y), f2h2(v.z, v.w));
                }
                pb[i] = *(const uint2*)(Bg + koff + (size_t)(16 * i) * K);
            }
        }

        const uint32_t* Apt = Asm + buf * TILE_WORDS + a_off;
        const uint32_t* Bpt = Bsm + buf * TILE_WORDS + b_off;
        #pragma unroll
        for (int ks = 0; ks < 4; ks++) {
            const int k = ks * 8;
            uint32_t af[4][4], bf[4][2];
            #pragma unroll
            for (int mt = 0; mt < 4; mt++) {
                af[mt][0] = Apt[(mt * 16    ) * LDS_STRIDE + k];
                af[mt][1] = Apt[(mt * 16 + 8) * LDS_STRIDE + k];
                af[mt][2] = Apt[(mt * 16    ) * LDS_STRIDE + k + 4];
                af[mt][3] = Apt[(mt * 16 + 8) * LDS_STRIDE + k + 4];
            }
            #pragma unroll
            for (int nt = 0; nt < 4; nt++) {
                bf[nt][0] = Bpt[(nt * 8) * LDS_STRIDE + k];
                bf[nt][1] = Bpt[(nt * 8) * LDS_STRIDE + k + 4];
            }
            #pragma unroll
            for (int mt = 0; mt < 4; mt++)
                #pragma unroll
                for (int nt = 0; nt < 4; nt++)
                    mma_f16(acc[mt][nt], af[mt], bf[nt]);
        }

        if (more) {
            const int nb = (s + 1) & 1;
            #pragma unroll
            for (int i = 0; i < 8; i++) {
                *(uint2*)(Asm + nb * TILE_WORDS + sts_base + i * 16 * LDS_STRIDE) = pa[i];
                *(uint2*)(Bsm + nb * TILE_WORDS + sts_base + i * 16 * LDS_STRIDE) = pb[i];
            }
        }
        __syncthreads();
    }

    #pragma unroll
    for (int mt = 0; mt < 4; mt++) {
        const int m = m0 + warp_m * 64 + mt * 16 + lr;
        #pragma unroll
        for (int nt = 0; nt < 4; nt++) {
            const int n = n0 + warp_n * 32 + nt * 8 + lc * 2;
            const float b0 = bias[n], b1 = bias[n + 1];
            float o0 = acc[mt][nt][0] + b0, o1 = acc[mt][nt][1] + b1;
            float o2 = acc[mt][nt][2] + b0, o3 = acc[mt][nt][3] + b1;
            if (RELU) {
                o0 = fmaxf(o0, 0.f); o1 = fmaxf(o1, 0.f);
                o2 = fmaxf(o2, 0.f); o3 = fmaxf(o3, 0.f);
            }
            if (OUT_HALF) {
                *(__half2*)(Ch + (size_t)m * N + n)       = __floats2half2_rn(o0, o1);
                *(__half2*)(Ch + (size_t)(m + 8) * N + n) = __floats2half2_rn(o2, o3);
            } else {
                *(float2*)(Cf + (size_t)m * N + n)       = make_float2(o0, o1);
                *(float2*)(Cf + (size_t)(m + 8) * N + n) = make_float2(o2, o3);
            }
        }
    }
}

// ---------------- transpose fp32 -> fp16: out[C,R] = half(in[R,C]^T) -------------
__global__ __launch_bounds__(256) void transpose64h(
    const float* __restrict__ in, __half* __restrict__ out, int R, int C)
{
    __shared__ float s[64][68];
    in  += (size_t)blockIdx.z * (size_t)R * C;
    out += (size_t)blockIdx.z * (size_t)R * C;
    const int c0 = blockIdx.x * 64, r0 = blockIdx.y * 64;
    const int t = threadIdx.x;
    #pragma unroll
    for (int i = 0; i < 4; i++) {
        int idx = t + 256 * i;
        int row = idx >> 4, cx = (idx & 15) * 4;
        float4 v = *(const float4*)(in + (size_t)(r0 + row) * C + c0 + cx);
        s[cx + 0][row] = v.x; s[cx + 1][row] = v.y;
        s[cx + 2][row] = v.z; s[cx + 3][row] = v.w;
    }
    __syncthreads();
    #pragma unroll
    for (int i = 0; i < 4; i++) {
        int idx = t + 256 * i;
        int orow = idx >> 4, rx = (idx & 15) * 4;
        float4 v = *(float4*)&s[orow][rx];
        uint2 o = make_uint2(f2h2(v.x, v.y), f2h2(v.z, v.w));
        *(uint2*)(out + (size_t)(c0 + orow) * R + r0 + rx) = o;
    }
}

// ---------------- concat 3 bias vectors ------------------------------------------
__global__ void concat3(const float* __restrict__ a, const float* __restrict__ b,
                        const float* __restrict__ c, float* __restrict__ o, int n)
{
    int i = blockIdx.x * 256 + threadIdx.x;
    if (i < n) { o[i] = a[i]; o[i + n] = b[i]; o[i + 2 * n] = c[i]; }
}

// ---------------- fused flash attention (tf32 mma, unchanged) --------------------
#define FA_QS   0                  // [128][68]
#define FA_KS   8704               // [128][68]
#define FA_VS   17408              // [128][72]
#define FA_PS   26624              // [128][132]
#define FA_RED  43520              // [128][4]
#define FA_MS   44032
#define FA_LS   44160
#define FA_AL   44288
#define FA_WORDS 44416
#define FA_BYTES (FA_WORDS * 4)

__global__ __launch_bounds__(256) void fused_attn(
    const float* __restrict__ q, const float* __restrict__ k,
    const float* __restrict__ v, float* __restrict__ out)
{
    extern __shared__ float fsh[];
    uint32_t* Qs = (uint32_t*)(fsh + FA_QS);
    uint32_t* Ks = (uint32_t*)(fsh + FA_KS);
    uint32_t* Vs = (uint32_t*)(fsh + FA_VS);
    uint32_t* Ps = (uint32_t*)(fsh + FA_PS);
    float* red   = fsh + FA_RED;
    float* m_s   = fsh + FA_MS;
    float* l_s   = fsh + FA_LS;
    float* al_s  = fsh + FA_AL;

    const int t = threadIdx.x;
    const int lane = t & 31, w = t >> 5;
    const int warp_m = w >> 2;
    const int warp_n = w & 3;
    const int ow_m = w >> 1;
    const int ow_n = w & 1;
    const int lr = lane >> 2, lc = lane & 3;

    const int q0 = blockIdx.x * 128;
    const int bh = blockIdx.y, b = bh >> 4, h = bh & 15;
    const size_t qbase = (size_t)(b * Sseq + q0) * Dm + h * 64;
    const size_t kvbase = (size_t)(b * Sseq) * Dm + h * 64;

    #pragma unroll
    for (int i = 0; i < 8; i++) {
        int idx = t + 256 * i;
        int row = idx >> 4, c4 = (idx & 15) * 4;
        float4 qv = *(const float4*)(q + qbase + (size_t)row * Dm + c4);
        uint32_t* d = Qs + row * 68 + c4;
        d[0] = f2tf(qv.x); d[1] = f2tf(qv.y); d[2] = f2tf(qv.z); d[3] = f2tf(qv.w);
    }
    if (t < 128) { m_s[t] = -1e30f; l_s[t] = 0.f; }

    float acc_o[2][4][4];
    #pragma unroll
    for (int mt = 0; mt < 2; mt++)
        #pragma unroll
        for (int nt = 0; nt < 4; nt++)
            #pragma unroll
            for (int i = 0; i < 4; i++) acc_o[mt][nt][i] = 0.f;

    const int a_off = (warp_m * 64 + lr) * 68 + lc;
    const int b_off = (warp_n * 32 + lr) * 68 + lc;
    const int p_off = (ow_m * 32 + lr) * 132 + lc;

    for (int kt = 0; kt < 8; kt++) {
        const size_t kb = kvbase + (size_t)(kt * 128) * Dm;
        #pragma unroll
        for (int i = 0; i < 8; i++) {
            int idx = t + 256 * i;
            int row = idx >> 4, c4 = (idx & 15) * 4;
            float4 kv = *(const float4*)(k + kb + (size_t)row * Dm + c4);
            float4 vv = *(const float4*)(v + kb + (size_t)row * Dm + c4);
            uint32_t* dk = Ks + row * 68 + c4;
            uint32_t* dv = Vs + row * 72 + c4;
            dk[0] = f2tf(kv.x); dk[1] = f2tf(kv.y); dk[2] = f2tf(kv.z); dk[3] = f2tf(kv.w);
            dv[0] = f2tf(vv.x); dv[1] = f2tf(vv.y); dv[2] = f2tf(vv.z); dv[3] = f2tf(vv.w);
        }
        __syncthreads();

        float acc_s[4][4][4];
        #pragma unroll
        for (int mt = 0; mt < 4; mt++)
            #pragma unroll
            for (int nt = 0; nt < 4; nt++)
                #pragma unroll
                for (int i = 0; i < 4; i++) acc_s[mt][nt][i] = 0.f;
        #pragma unroll
        for (int kk = 0; kk < 8; kk++) {
            const int kx = kk * 8;
            uint32_t af[4][4], bf[4][2];
            #pragma unroll
            for (int mt = 0; mt < 4; mt++) {
                af[mt][0] = Qs[a_off + (mt * 16    ) * 68 + kx];
                af[mt][1] = Qs[a_off + (mt * 16 + 8) * 68 + kx];
                af[mt][2] = Qs[a_off + (mt * 16    ) * 68 + kx + 4];
                af[mt][3] = Qs[a_off + (mt * 16 + 8) * 68 + kx + 4];
            }
            #pragma unroll
            for (int nt = 0; nt < 4; nt++) {
                bf[nt][0] = Ks[b_off + (nt * 8) * 68 + kx];
                bf[nt][1] = Ks[b_off + (nt * 8) * 68 + kx + 4];
            }
            #pragma unroll
            for (int mt = 0; mt < 4; mt++)
                #pragma unroll
                for (int nt = 0; nt < 4; nt++)
                    mma_tf32(acc_s[mt][nt], af[mt], bf[nt]);
        }

        #pragma unroll
        for (int mt = 0; mt < 4; mt++) {
            #pragma unroll
            for (int half = 0; half < 2; half++) {
                float pm = -1e30f;
                #pragma unroll
                for (int nt = 0; nt < 4; nt++) {
                    pm = fmaxf(pm, acc_s[mt][nt][half * 2]);
                    pm = fmaxf(pm, acc_s[mt][nt][half * 2 + 1]);
                }
                pm = fmaxf(pm, __shfl_xor_sync(0xffffffffu, pm, 1));
                pm = fmaxf(pm, __shfl_xor_sync(0xffffffffu, pm, 2));
                if (lc == 0)
                    red[(warp_m * 64 + mt * 16 + half * 8 + lr) * 4 + warp_n] = pm;
            }
        }
        __syncthreads();

        if (t < 128) {
            float tm = fmaxf(fmaxf(red[t * 4 + 0], red[t * 4 + 1]),
                             fmaxf(red[t * 4 + 2], red[t * 4 + 3])) * 0.125f;
            float mo = m_s[t];
            float mn = fmaxf(mo, tm);
            al_s[t] = __expf(mo - mn);
            m_s[t]  = mn;
        }
        __syncthreads();

        #pragma unroll
        for (int mt = 0; mt < 4; mt++) {
            #pragma unroll
            for (int half = 0; half < 2; half++) {
                const int row = warp_m * 64 + mt * 16 + half * 8 + lr;
                const float mrow = m_s[row];
                float ps = 0.f;
                #pragma unroll
                for (int nt = 0; nt < 4; nt++) {
                    const int col = warp_n * 32 + nt * 8 + lc * 2;
                    float p0 = __expf(acc_s[mt][nt][half * 2]     * 0.125f - mrow);
                    float p1 = __expf(acc_s[mt][nt][half * 2 + 1] * 0.125f - mrow);
                    ps += p0 + p1;
                    Ps[row * 132 + col]     = f2tf(p0);
                    Ps[row * 132 + col + 1] = f2tf(p1);
                }
                ps += __shfl_xor_sync(0xffffffffu, ps, 1);
                ps += __shfl_xor_sync(0xffffffffu, ps, 2);
                if (lc == 0) red[row * 4 + warp_n] = ps;
            }
        }
        #pragma unroll
        for (int mt = 0; mt < 2; mt++) {
            const int row0 = ow_m * 32 + mt * 16 + lr;
            const float a0 = al_s[row0], a1 = al_s[row0 + 8];
            #pragma unroll
            for (int nt = 0; nt < 4; nt++) {
                acc_o[mt][nt][0] *= a0; acc_o[mt][nt][1] *= a0;
                acc_o[mt][nt][2] *= a1; acc_o[mt][nt][3] *= a1;
            }
        }
        __syncthreads();

        if (t < 128)
            l_s[t] = l_s[t] * al_s[t]
                   + red[t * 4 + 0] + red[t * 4 + 1] + red[t * 4 + 2] + red[t * 4 + 3];

        #pragma unroll
        for (int kk = 0; kk < 16; kk++) {
            const int kx = kk * 8;
            uint32_t af[2][4], bf[4][2];
            #pragma unroll
            for (int mt = 0; mt < 2; mt++) {
                af[mt][0] = Ps[p_off + (mt * 16    ) * 132 + kx];
                af[mt][1] = Ps[p_off + (mt * 16 + 8) * 132 + kx];
                af[mt][2] = Ps[p_off + (mt * 16    ) * 132 + kx + 4];
                af[mt][3] = Ps[p_off + (mt * 16 + 8) * 132 + kx + 4];
            }
            #pragma unroll
            for (int nt = 0; nt < 4; nt++) {
                const int n = ow_n * 32 + nt * 8 + lr;
                bf[nt][0] = Vs[(kx + lc) * 72 + n];
                bf[nt][1] = Vs[(kx + lc + 4) * 72 + n];
            }
            #pragma unroll
            for (int mt = 0; mt < 2; mt++)
                #pragma unroll
                for (int nt = 0; nt < 4; nt++)
                    mma_tf32(acc_o[mt][nt], af[mt], bf[nt]);
        }
        __syncthreads();
    }

    #pragma unroll
    for (int mt = 0; mt < 2; mt++) {
        const int row0 = ow_m * 32 + mt * 16 + lr;
        const float i0 = 1.f / l_s[row0], i1 = 1.f / l_s[row0 + 8];
        #pragma unroll
        for (int nt = 0; nt < 4; nt++) {
            const int col = ow_n * 32 + nt * 8 + lc * 2;
            float* o0 = out + (size_t)(b * Sseq + q0 + row0) * Dm + h * 64 + col;
            float* o1 = out + (size_t)(b * Sseq + q0 + row0 + 8) * Dm + h * 64 + col;
            *(float2*)o0 = make_float2(acc_o[mt][nt][0] * i0, acc_o[mt][nt][1] * i0);
            *(float2*)o1 = make_float2(acc_o[mt][nt][2] * i1, acc_o[mt][nt][3] * i1);
        }
    }
}

// ---------------- block reduction helper -----------------------------------------
__device__ __forceinline__ float block_sum256(float v, float* red) {
    #pragma unroll
    for (int o = 16; o > 0; o >>= 1) v += __shfl_xor_sync(0xffffffffu, v, o);
    if ((threadIdx.x & 31) == 0) red[threadIdx.x >> 5] = v;
    __syncthreads();
    float s = red[0];
    #pragma unroll
    for (int i = 1; i < 8; i++) s += red[i];
    __syncthreads();
    return s;
}

// ---------------- residual add + layernorm ---------------------------------------
__global__ __launch_bounds__(256) void add_ln(
    const float* __restrict__ a, const float* __restrict__ b,
    const float* __restrict__ gamma, const float* __restrict__ beta,
    float* __restrict__ out)
{
    __shared__ float red[8];
    const int t = threadIdx.x;
    const size_t base = (size_t)blockIdx.x * Dm;
    float4 va = ((const float4*)(a + base))[t];
    float4 vb = ((const float4*)(b + base))[t];
    float4 s = make_float4(va.x+vb.x, va.y+vb.y, va.z+vb.z, va.w+vb.w);
    float tot = block_sum256(s.x + s.y + s.z + s.w, red);
    float mu = tot * (1.f / Dm);
    float lq = (s.x-mu)*(s.x-mu) + (s.y-mu)*(s.y-mu) + (s.z-mu)*(s.z-mu) + (s.w-mu)*(s.w-mu);
    float var = block_sum256(lq, red) * (1.f / Dm);
    float rstd = rsqrtf(var + EPSV);
    float4 gg = ((const float4*)gamma)[t];
    float4 bt = ((const float4*)beta)[t];
    float4 o;
    o.x = (s.x - mu) * rstd * gg.x + bt.x;
    o.y = (s.y - mu) * rstd * gg.y + bt.y;
    o.z = (s.z - mu) * rstd * gg.z + bt.z;
    o.w = (s.w - mu) * rstd * gg.w + bt.w;
    ((float4*)(out + base))[t] = o;
}

// ---------------- gate coefficients ----------------------------------------------
__global__ __launch_bounds__(256) void gate_coef(
    const float* __restrict__ xn, const float* __restrict__ gw, float* __restrict__ coef)
{
    __shared__ float red[16][9];
    const int t = threadIdx.x, tkn = blockIdx.x;
    float acc[16];
    #pragma unroll
    for (int ge = 0; ge < 16; ge++) acc[ge] = 0.f;
    for (int d = t; d < Dm; d += 256) {
        float xv = xn[(size_t)tkn*Dm + d];
        #pragma unroll
        for (int ge = 0; ge < 16; ge++)
            acc[ge] = fmaf(xv, gw[(size_t)(ge >> 3)*Dm*Ee + (size_t)d*Ee + (ge & 7)], acc[ge]);
    }
    #pragma unroll
    for (int ge = 0; ge < 16; ge++) {
        float v = acc[ge];
        #pragma unroll
        for (int o = 16; o > 0; o >>= 1) v += __shfl_xor_sync(0xffffffffu, v, o);
        if ((t & 31) == 0) red[ge][t >> 5] = v;
    }
    __syncthreads();
    if (t == 0) {
        float logits[16];
        #pragma unroll
        for (int ge = 0; ge < 16; ge++) {
            float s = 0.f;
            #pragma unroll
            for (int w2 = 0; w2 < 8; w2++) s += red[ge][w2];
            logits[ge] = s;
        }
        float c[8];
        #pragma unroll
        for (int e2 = 0; e2 < 8; e2++) c[e2] = 0.f;
        #pragma unroll
        for (int g = 0; g < 2; g++) {
            float m = logits[g*8];
            #pragma unroll
            for (int e2 = 1; e2 < 8; e2++) m = fmaxf(m, logits[g*8+e2]);
            float s = 0.f, pe[8];
            #pragma unroll
            for (int e2 = 0; e2 < 8; e2++) { pe[e2] = __expf(logits[g*8+e2] - m); s += pe[e2]; }
            float inv = 1.f / s;
            #pragma unroll
            for (int e2 = 0; e2 < 8; e2++) c[e2] += pe[e2] * inv;
        }
        #pragma unroll
        for (int e2 = 0; e2 < 8; e2++) coef[(size_t)tkn*8 + e2] = c[e2] * 0.5f;
    }
}

// ---------------- combine + residual + LN2 ---------------------------------------
__global__ __launch_bounds__(256) void combine_ln(
    const float* __restrict__ eo, const float* __restrict__ coef,
    const float* __restrict__ xn,
    const float* __restrict__ gamma, const float* __restrict__ beta,
    float* __restrict__ out)
{
    __shared__ float red[8];
    __shared__ float cf[8];
    const int t = threadIdx.x, tkn = blockIdx.x;
    if (t < 8) cf[t] = coef[(size_t)tkn*8 + t];
    __syncthreads();
    const size_t base = (size_t)tkn * Dm;
    float4 s = ((const float4*)(xn + base))[t];
    #pragma unroll
    for (int e2 = 0; e2 < 8; e2++) {
        float4 v = ((const float4*)(eo + ((size_t)e2*TOK + tkn)*Dm))[t];
        float c = cf[e2];
        s.x = fmaf(c, v.x, s.x); s.y = fmaf(c, v.y, s.y);
        s.z = fmaf(c, v.z, s.z); s.w = fmaf(c, v.w, s.w);
    }
    float tot = block_sum256(s.x + s.y + s.z + s.w, red);
    float mu = tot * (1.f / Dm);
    float lq = (s.x-mu)*(s.x-mu) + (s.y-mu)*(s.y-mu) + (s.z-mu)*(s.z-mu) + (s.w-mu)*(s.w-mu);
    float var = block_sum256(lq, red) * (1.f / Dm);
    float rstd = rsqrtf(var + EPSV);
    float4 gg = ((const float4*)gamma)[t];
    float4 bt = ((const float4*)beta)[t];
    float4 o;
    o.x = (s.x - mu) * rstd * gg.x + bt.x;
    o.y = (s.y - mu) * rstd * gg.y + bt.y;
    o.z = (s.z - mu) * rstd * gg.z + bt.z;
    o.w = (s.w - mu) * rstd * gg.w + bt.w;
    ((float4*)(out + base))[t] = o;
}

// ---------------- launch ----------------------------------------------------------
extern "C" void kernel_launch(void* const* d_in, const int* in_sizes, int n_in,
                              void* d_out, int out_size)
{
    const float* x     = (const float*)d_in[0];
    const float* wq    = (const float*)d_in[1];
    const float* bq    = (const float*)d_in[2];
    const float* wk    = (const float*)d_in[3];
    const float* bk    = (const float*)d_in[4];
    const float* wv    = (const float*)d_in[5];
    const float* bv    = (const float*)d_in[6];
    const float* wo    = (const float*)d_in[7];
    const float* bo    = (const float*)d_in[8];
    const float* ln1g  = (const float*)d_in[9];
    const float* ln1b  = (const float*)d_in[10];
    const float* ln2g  = (const float*)d_in[11];
    const float* ln2b  = (const float*)d_in[12];
    const float* gatew = (const float*)d_in[13];
    const float* ew1   = (const float*)d_in[14];
    const float* eb1   = (const float*)d_in[15];
    const float* ew2   = (const float*)d_in[16];
    const float* eb2   = (const float*)d_in[17];
    float* out = (float*)d_out;

    float *qkv, *attn, *proj, *normed, *eo, *coef, *bqkv;
    __half *h, *wqkvt, *wot, *w1t, *w2t;
    cudaGetSymbolAddress((void**)&qkv,    g_qkv);
    cudaGetSymbolAddress((void**)&attn,   g_attn);
    cudaGetSymbolAddress((void**)&proj,   g_proj);
    cudaGetSymbolAddress((void**)&normed, g_normed);
    cudaGetSymbolAddress((void**)&h,      g_h);
    cudaGetSymbolAddress((void**)&eo,     g_eo);
    cudaGetSymbolAddress((void**)&coef,   g_coef);
    cudaGetSymbolAddress((void**)&wqkvt,  g_wqkvt);
    cudaGetSymbolAddress((void**)&bqkv,   g_bqkv);
    cudaGetSymbolAddress((void**)&wot,    g_wot);
    cudaGetSymbolAddress((void**)&w1t,    g_w1t);
    cudaGetSymbolAddress((void**)&w2t,    g_w2t);

    cudaFuncSetAttribute((const void*)mma_gemm<false,false,false>,
                         cudaFuncAttributeMaxDynamicSharedMemorySize, SMEM_GEMM_BYTES);
    cudaFuncSetAttribute((const void*)mma_gemm<true,false,true>,
                         cudaFuncAttributeMaxDynamicSharedMemorySize, SMEM_GEMM_BYTES);
    cudaFuncSetAttribute((const void*)mma_gemm<false,true,false>,
                         cudaFuncAttributeMaxDynamicSharedMemorySize, SMEM_GEMM_BYTES);
    cudaFuncSetAttribute((const void*)fused_attn,
                         cudaFuncAttributeMaxDynamicSharedMemorySize, FA_BYTES);

    dim3 blk(256);

    // weight transposes (fp32 -> fp16) + bias concat
    transpose64h<<<dim3(16, 16, 1), blk>>>(wq, wqkvt,           Dm, Dm);
    transpose64h<<<dim3(16, 16, 1), blk>>>(wk, wqkvt + Dm*Dm,   Dm, Dm);
    transpose64h<<<dim3(16, 16, 1), blk>>>(wv, wqkvt + 2*Dm*Dm, Dm, Dm);
    concat3<<<4, 256>>>(bq, bk, bv, bqkv, Dm);
    transpose64h<<<dim3(16, 16, 1), blk>>>(wo, wot,             Dm, Dm);

    // batched QKV GEMM (fp16 mma, fp16 weights)
    mma_gemm<false,false,false><<<dim3(8, 16, 3), blk, SMEM_GEMM_BYTES>>>(
        x, wqkvt, bqkv, qkv, TOK, Dm, Dm,
        0, (long long)Dm*Dm, (long long)Dm, (long long)TOK*Dm);

    // MoE weight transposes (independent)
    transpose64h<<<dim3(Vv/64, Dm/64, Ee), blk>>>(ew1, w1t, Dm, Vv);
    transpose64h<<<dim3(Dm/64, Vv/64, Ee), blk>>>(ew2, w2t, Vv, Dm);

    // fused flash attention (tf32)
    fused_attn<<<dim3(8, 32), blk, FA_BYTES>>>(
        qkv, qkv + (size_t)TOK*Dm, qkv + (size_t)2*TOK*Dm, attn);

    // output projection + residual + LN1
    mma_gemm<false,false,false><<<dim3(8, 16, 1), blk, SMEM_GEMM_BYTES>>>(
        attn, wot, bo, proj, TOK, Dm, Dm, 0, 0, 0, 0);
    add_ln<<<TOK, blk>>>(proj, x, ln1g, ln1b, normed);

    // MoE: w1 (fp16 out h), w2 (fp16 in h)
    gate_coef<<<TOK, blk>>>(normed, gatew, coef);
    mma_gemm<true,false,true><<<dim3(32, 16, Ee), blk, SMEM_GEMM_BYTES>>>(
        normed, w1t, eb1, h, TOK, Vv, Dm,
        0, (long long)Vv*Dm, (long long)Vv, (long long)TOK*Vv);
    mma_gemm<false,true,false><<<dim3(8, 16, Ee), blk, SMEM_GEMM_BYTES>>>(
        h, w2t, eb2, eo, TOK, Dm, Vv,
        (long long)TOK*Vv, (long long)Dm*Vv, (long long)Dm, (long long)TOK*Dm);

    // combine + residual + LN2
    combine_ln<<<TOK, blk>>>(eo, coef, normed, ln2g, ln2b, out);
}

// round 17
// speedup vs baseline: 2.0396x; 1.0980x over previous
#include <cuda_runtime.h>
#include <cuda_fp16.h>
#include <math.h>
#include <stdint.h>

// Problem dims
#define Dm   1024
#define Sseq 1024
#define Bb   2
#define Hh   16
#define Ee   8
#define Vv   4096
#define TOK  (Bb*Sseq)
#define EPSV 1e-5f

// ---------------- device scratch ------------------------------------------------
__device__ float  g_qkv[3*TOK*Dm];
__device__ float  g_attn[TOK*Dm];
__device__ float  g_proj[TOK*Dm];
__device__ float  g_normed[TOK*Dm];
__device__ __half g_h[(size_t)Ee*TOK*Vv];
__device__ float  g_eo[(size_t)Ee*TOK*Dm];
__device__ float  g_coef[TOK*Ee];
// transposed weights, fp16 (N-major: Wt[n][k])
__device__ __half g_wqkvt[3*Dm*Dm];
__device__ float  g_bqkv[3*Dm];
__device__ __half g_wot[Dm*Dm];
__device__ __half g_w1t[(size_t)Ee*Vv*Dm];
__device__ __half g_w2t[(size_t)Ee*Dm*Vv];

// ---------------- helpers -------------------------------------------------------
__device__ __forceinline__ uint32_t f2tf(float f) {
    uint32_t u; asm("cvt.rna.tf32.f32 %0, %1;" : "=r"(u) : "f"(f)); return u;
}
// pack (lo, hi) floats into f16x2 (lo in low half)
__device__ __forceinline__ uint32_t f2h2(float lo, float hi) {
    uint32_t u; asm("cvt.rn.f16x2.f32 %0, %1, %2;" : "=r"(u) : "f"(hi), "f"(lo)); return u;
}
__device__ __forceinline__ void mma_tf32(float* c, const uint32_t* a, const uint32_t* b) {
    asm volatile("mma.sync.aligned.m16n8k8.row.col.f32.tf32.tf32.f32 "
        "{%0,%1,%2,%3}, {%4,%5,%6,%7}, {%8,%9}, {%0,%1,%2,%3};"
        : "+f"(c[0]), "+f"(c[1]), "+f"(c[2]), "+f"(c[3])
        : "r"(a[0]), "r"(a[1]), "r"(a[2]), "r"(a[3]), "r"(b[0]), "r"(b[1]));
}
__device__ __forceinline__ void mma_f16(float* c, const uint32_t* a, const uint32_t* b) {
    asm volatile("mma.sync.aligned.m16n8k16.row.col.f32.f16.f16.f32 "
        "{%0,%1,%2,%3}, {%4,%5,%6,%7}, {%8,%9}, {%0,%1,%2,%3};"
        : "+f"(c[0]), "+f"(c[1]), "+f"(c[2]), "+f"(c[3])
        : "r"(a[0]), "r"(a[1]), "r"(a[2]), "r"(a[3]), "r"(b[0]), "r"(b[1]));
}

// SMEM geometry: K-chunk 64 halves = 32 words + pad -> stride 36.
#define LDS_STRIDE 36
#define TILE_WORDS (128 * LDS_STRIDE)            // 4608 words per matrix buffer
#define SMEM_GEMM_BYTES (4 * TILE_WORDS * 4)     // 2 bufs x (A+B) = 73728

// ---------------- tensor-core fp16 GEMM: C[M,N] = A[M,K] @ Bt[N,K]^T + bias -----
// B (and optionally A) read as fp16 from global; optional fp16 output.
// 2 CTAs/SM (uint2 prefetch keeps regs under the 128 cap).
template<bool RELU, bool A_HALF, bool OUT_HALF>
__global__ __launch_bounds__(256, 2) void mma_gemm(
    const void* __restrict__ Av, const __half* __restrict__ Btw,
    const float* __restrict__ bias, void* __restrict__ Cv,
    int M, int N, int K,
    long long sA, long long sB, long long sBias, long long sC)
{
    extern __shared__ uint32_t sh[];
    uint32_t* Asm = sh;                    // [2][TILE_WORDS]
    uint32_t* Bsm = sh + 2 * TILE_WORDS;   // [2][TILE_WORDS]

    const int t = threadIdx.x;
    const int lane = t & 31, w = t >> 5;
    const int warp_m = w >> 2;
    const int warp_n = w & 3;
    const int lr = lane >> 2;
    const int lc = lane & 3;

    const int eb = blockIdx.z;
    const float*  Af = (const float*)Av  + (A_HALF ? 0 : (size_t)eb * sA);
    const __half* Ah = (const __half*)Av + (A_HALF ? (size_t)eb * sA : 0);
    const __half* Bt = Btw + (size_t)eb * sB;
    bias += (size_t)eb * sBias;
    float*  Cf = (float*)Cv  + (OUT_HALF ? 0 : (size_t)eb * sC);
    __half* Ch = (__half*)Cv + (OUT_HALF ? (size_t)eb * sC : 0);
    const int n0 = blockIdx.x * 128, m0 = blockIdx.y * 128;

    // copy mapping: 16 threads/row, 4 elements each -> 64 k-elements; rows r0+16i
    const int kc = (t & 15) * 4;
    const int r0 = t >> 4;
    const float*  Agf = Af + (size_t)(m0 + r0) * K + kc;
    const __half* Agh = Ah + (size_t)(m0 + r0) * K + kc;
    const __half* Bg  = Bt + (size_t)(n0 + r0) * K + kc;
    const int sts_base = r0 * LDS_STRIDE + (t & 15) * 2;

    float acc[4][4][4];
    #pragma unroll
    for (int mt = 0; mt < 4; mt++)
        #pragma unroll
        for (int nt = 0; nt < 4; nt++)
            #pragma unroll
            for (int i = 0; i < 4; i++) acc[mt][nt][i] = 0.f;

    const int nst = K >> 6;

    // stage 0 -> buf 0
    {
        uint2 ha[8], hb[8];
        #pragma unroll
        for (int i = 0; i < 8; i++) {
            if (A_HALF) {
                ha[i] = *(const uint2*)(Agh + (size_t)(16 * i) * K);
            } else {
                float4 v = *(const float4*)(Agf + (size_t)(16 * i) * K);
                ha[i] = make_uint2(f2h2(v.x, v.y), f2h2(v.z, v.w));
            }
            hb[i] = *(const uint2*)(Bg + (size_t)(16 * i) * K);
        }
        #pragma unroll
        for (int i = 0; i < 8; i++) {
            *(uint2*)(Asm + sts_base + i * 16 * LDS_STRIDE) = ha[i];
            *(uint2*)(Bsm + sts_base + i * 16 * LDS_STRIDE) = hb[i];
        }
    }
    __syncthreads();

    const int a_off = (warp_m * 64 + lr) * LDS_STRIDE + lc;
    const int b_off = (warp_n * 32 + lr) * LDS_STRIDE + lc;

    for (int s = 0; s < nst; s++) {
        const int buf = s & 1;
        const bool more = (s + 1) < nst;
        uint2 pa[8], pb[8];
        if (more) {
            const int koff = 64 * (s + 1);
            #pragma unroll
            for (int i = 0; i < 8; i++) {
                if (A_HALF) {
                    pa[i] = *(const uint2*)(Agh + koff + (size_t)(16 * i) * K);
                } else {
                    float4 v = *(const float4*)(Agf + koff + (size_t)(16 * i) * K);
                    pa[i] = make_uint2(f2h2(v.x, v.y), f2h2(v.z, v.w));
                }
                pb[i] = *(const uint2*)(Bg + koff + (size_t)(16 * i) * K);
            }
        }

        const uint32_t* Apt = Asm + buf * TILE_WORDS + a_off;
        const uint32_t* Bpt = Bsm + buf * TILE_WORDS + b_off;
        #pragma unroll
        for (int ks = 0; ks < 4; ks++) {
            const int k = ks * 8;
            uint32_t af[4][4], bf[4][2];
            #pragma unroll
            for (int mt = 0; mt < 4; mt++) {
                af[mt][0] = Apt[(mt * 16    ) * LDS_STRIDE + k];
                af[mt][1] = Apt[(mt * 16 + 8) * LDS_STRIDE + k];
                af[mt][2] = Apt[(mt * 16    ) * LDS_STRIDE + k + 4];
                af[mt][3] = Apt[(mt * 16 + 8) * LDS_STRIDE + k + 4];
            }
            #pragma unroll
            for (int nt = 0; nt < 4; nt++) {
                bf[nt][0] = Bpt[(nt * 8) * LDS_STRIDE + k];
                bf[nt][1] = Bpt[(nt * 8) * LDS_STRIDE + k + 4];
            }
            #pragma unroll
            for (int mt = 0; mt < 4; mt++)
                #pragma unroll
                for (int nt = 0; nt < 4; nt++)
                    mma_f16(acc[mt][nt], af[mt], bf[nt]);
        }

        if (more) {
            const int nb = (s + 1) & 1;
            #pragma unroll
            for (int i = 0; i < 8; i++) {
                *(uint2*)(Asm + nb * TILE_WORDS + sts_base + i * 16 * LDS_STRIDE) = pa[i];
                *(uint2*)(Bsm + nb * TILE_WORDS + sts_base + i * 16 * LDS_STRIDE) = pb[i];
            }
        }
        __syncthreads();
    }

    #pragma unroll
    for (int mt = 0; mt < 4; mt++) {
        const int m = m0 + warp_m * 64 + mt * 16 + lr;
        #pragma unroll
        for (int nt = 0; nt < 4; nt++) {
            const int n = n0 + warp_n * 32 + nt * 8 + lc * 2;
            const float b0 = bias[n], b1 = bias[n + 1];
            float o0 = acc[mt][nt][0] + b0, o1 = acc[mt][nt][1] + b1;
            float o2 = acc[mt][nt][2] + b0, o3 = acc[mt][nt][3] + b1;
            if (RELU) {
                o0 = fmaxf(o0, 0.f); o1 = fmaxf(o1, 0.f);
                o2 = fmaxf(o2, 0.f); o3 = fmaxf(o3, 0.f);
            }
            if (OUT_HALF) {
                *(__half2*)(Ch + (size_t)m * N + n)       = __floats2half2_rn(o0, o1);
                *(__half2*)(Ch + (size_t)(m + 8) * N + n) = __floats2half2_rn(o2, o3);
            } else {
                *(float2*)(Cf + (size_t)m * N + n)       = make_float2(o0, o1);
                *(float2*)(Cf + (size_t)(m + 8) * N + n) = make_float2(o2, o3);
            }
        }
    }
}

// ---------------- transpose fp32 -> fp16: out[C,R] = half(in[R,C]^T) -------------
__global__ __launch_bounds__(256) void transpose64h(
    const float* __restrict__ in, __half* __restrict__ out, int R, int C)
{
    __shared__ float s[64][68];
    in  += (size_t)blockIdx.z * (size_t)R * C;
    out += (size_t)blockIdx.z * (size_t)R * C;
    const int c0 = blockIdx.x * 64, r0 = blockIdx.y * 64;
    const int t = threadIdx.x;
    #pragma unroll
    for (int i = 0; i < 4; i++) {
        int idx = t + 256 * i;
        int row = idx >> 4, cx = (idx & 15) * 4;
        float4 v = *(const float4*)(in + (size_t)(r0 + row) * C + c0 + cx);
        s[cx + 0][row] = v.x; s[cx + 1][row] = v.y;
        s[cx + 2][row] = v.z; s[cx + 3][row] = v.w;
    }
    __syncthreads();
    #pragma unroll
    for (int i = 0; i < 4; i++) {
        int idx = t + 256 * i;
        int orow = idx >> 4, rx = (idx & 15) * 4;
        float4 v = *(float4*)&s[orow][rx];
        uint2 o = make_uint2(f2h2(v.x, v.y), f2h2(v.z, v.w));
        *(uint2*)(out + (size_t)(c0 + orow) * R + r0 + rx) = o;
    }
}

// ---------------- concat 3 bias vectors ------------------------------------------
__global__ void concat3(const float* __restrict__ a, const float* __restrict__ b,
                        const float* __restrict__ c, float* __restrict__ o, int n)
{
    int i = blockIdx.x * 256 + threadIdx.x;
    if (i < n) { o[i] = a[i]; o[i + n] = b[i]; o[i + 2 * n] = c[i]; }
}

// ---------------- fused flash attention (tf32 mma, unchanged) --------------------
#define FA_QS   0                  // [128][68]
#define FA_KS   8704               // [128][68]
#define FA_VS   17408              // [128][72]
#define FA_PS   26624              // [128][132]
#define FA_RED  43520              // [128][4]
#define FA_MS   44032
#define FA_LS   44160
#define FA_AL   44288
#define FA_WORDS 44416
#define FA_BYTES (FA_WORDS * 4)

__global__ __launch_bounds__(256) void fused_attn(
    const float* __restrict__ q, const float* __restrict__ k,
    const float* __restrict__ v, float* __restrict__ out)
{
    extern __shared__ float fsh[];
    uint32_t* Qs = (uint32_t*)(fsh + FA_QS);
    uint32_t* Ks = (uint32_t*)(fsh + FA_KS);
    uint32_t* Vs = (uint32_t*)(fsh + FA_VS);
    uint32_t* Ps = (uint32_t*)(fsh + FA_PS);
    float* red   = fsh + FA_RED;
    float* m_s   = fsh + FA_MS;
    float* l_s   = fsh + FA_LS;
    float* al_s  = fsh + FA_AL;

    const int t = threadIdx.x;
    const int lane = t & 31, w = t >> 5;
    const int warp_m = w >> 2;
    const int warp_n = w & 3;
    const int ow_m = w >> 1;
    const int ow_n = w & 1;
    const int lr = lane >> 2, lc = lane & 3;

    const int q0 = blockIdx.x * 128;
    const int bh = blockIdx.y, b = bh >> 4, h = bh & 15;
    const size_t qbase = (size_t)(b * Sseq + q0) * Dm + h * 64;
    const size_t kvbase = (size_t)(b * Sseq) * Dm + h * 64;

    #pragma unroll
    for (int i = 0; i < 8; i++) {
        int idx = t + 256 * i;
        int row = idx >> 4, c4 = (idx & 15) * 4;
        float4 qv = *(const float4*)(q + qbase + (size_t)row * Dm + c4);
        uint32_t* d = Qs + row * 68 + c4;
        d[0] = f2tf(qv.x); d[1] = f2tf(qv.y); d[2] = f2tf(qv.z); d[3] = f2tf(qv.w);
    }
    if (t < 128) { m_s[t] = -1e30f; l_s[t] = 0.f; }

    float acc_o[2][4][4];
    #pragma unroll
    for (int mt = 0; mt < 2; mt++)
        #pragma unroll
        for (int nt = 0; nt < 4; nt++)
            #pragma unroll
            for (int i = 0; i < 4; i++) acc_o[mt][nt][i] = 0.f;

    const int a_off = (warp_m * 64 + lr) * 68 + lc;
    const int b_off = (warp_n * 32 + lr) * 68 + lc;
    const int p_off = (ow_m * 32 + lr) * 132 + lc;

    for (int kt = 0; kt < 8; kt++) {
        const size_t kb = kvbase + (size_t)(kt * 128) * Dm;
        #pragma unroll
        for (int i = 0; i < 8; i++) {
            int idx = t + 256 * i;
            int row = idx >> 4, c4 = (idx & 15) * 4;
            float4 kv = *(const float4*)(k + kb + (size_t)row * Dm + c4);
            float4 vv = *(const float4*)(v + kb + (size_t)row * Dm + c4);
            uint32_t* dk = Ks + row * 68 + c4;
            uint32_t* dv = Vs + row * 72 + c4;
            dk[0] = f2tf(kv.x); dk[1] = f2tf(kv.y); dk[2] = f2tf(kv.z); dk[3] = f2tf(kv.w);
            dv[0] = f2tf(vv.x); dv[1] = f2tf(vv.y); dv[2] = f2tf(vv.z); dv[3] = f2tf(vv.w);
        }
        __syncthreads();

        float acc_s[4][4][4];
        #pragma unroll
        for (int mt = 0; mt < 4; mt++)
            #pragma unroll
            for (int nt = 0; nt < 4; nt++)
                #pragma unroll
                for (int i = 0; i < 4; i++) acc_s[mt][nt][i] = 0.f;
        #pragma unroll
        for (int kk = 0; kk < 8; kk++) {
            const int kx = kk * 8;
            uint32_t af[4][4], bf[4][2];
            #pragma unroll
            for (int mt = 0; mt < 4; mt++) {
                af[mt][0] = Qs[a_off + (mt * 16    ) * 68 + kx];
                af[mt][1] = Qs[a_off + (mt * 16 + 8) * 68 + kx];
                af[mt][2] = Qs[a_off + (mt * 16    ) * 68 + kx + 4];
                af[mt][3] = Qs[a_off + (mt * 16 + 8) * 68 + kx + 4];
            }
            #pragma unroll
            for (int nt = 0; nt < 4; nt++) {
                bf[nt][0] = Ks[b_off + (nt * 8) * 68 + kx];
                bf[nt][1] = Ks[b_off + (nt * 8) * 68 + kx + 4];
            }
            #pragma unroll
            for (int mt = 0; mt < 4; mt++)
                #pragma unroll
                for (int nt = 0; nt < 4; nt++)
                    mma_tf32(acc_s[mt][nt], af[mt], bf[nt]);
        }

        #pragma unroll
        for (int mt = 0; mt < 4; mt++) {
            #pragma unroll
            for (int half = 0; half < 2; half++) {
                float pm = -1e30f;
                #pragma unroll
                for (int nt = 0; nt < 4; nt++) {
                    pm = fmaxf(pm, acc_s[mt][nt][half * 2]);
                    pm = fmaxf(pm, acc_s[mt][nt][half * 2 + 1]);
                }
                pm = fmaxf(pm, __shfl_xor_sync(0xffffffffu, pm, 1));
                pm = fmaxf(pm, __shfl_xor_sync(0xffffffffu, pm, 2));
                if (lc == 0)
                    red[(warp_m * 64 + mt * 16 + half * 8 + lr) * 4 + warp_n] = pm;
            }
        }
        __syncthreads();

        if (t < 128) {
            float tm = fmaxf(fmaxf(red[t * 4 + 0], red[t * 4 + 1]),
                             fmaxf(red[t * 4 + 2], red[t * 4 + 3])) * 0.125f;
            float mo = m_s[t];
            float mn = fmaxf(mo, tm);
            al_s[t] = __expf(mo - mn);
            m_s[t]  = mn;
        }
        __syncthreads();

        #pragma unroll
        for (int mt = 0; mt < 4; mt++) {
            #pragma unroll
            for (int half = 0; half < 2; half++) {
                const int row = warp_m * 64 + mt * 16 + half * 8 + lr;
                const float mrow = m_s[row];
                float ps = 0.f;
                #pragma unroll
                for (int nt = 0; nt < 4; nt++) {
                    const int col = warp_n * 32 + nt * 8 + lc * 2;
                    float p0 = __expf(acc_s[mt][nt][half * 2]     * 0.125f - mrow);
                    float p1 = __expf(acc_s[mt][nt][half * 2 + 1] * 0.125f - mrow);
                    ps += p0 + p1;
                    Ps[row * 132 + col]     = f2tf(p0);
                    Ps[row * 132 + col + 1] = f2tf(p1);
                }
                ps += __shfl_xor_sync(0xffffffffu, ps, 1);
                ps += __shfl_xor_sync(0xffffffffu, ps, 2);
                if (lc == 0) red[row * 4 + warp_n] = ps;
            }
        }
        #pragma unroll
        for (int mt = 0; mt < 2; mt++) {
            const int row0 = ow_m * 32 + mt * 16 + lr;
            const float a0 = al_s[row0], a1 = al_s[row0 + 8];
            #pragma unroll
            for (int nt = 0; nt < 4; nt++) {
                acc_o[mt][nt][0] *= a0; acc_o[mt][nt][1] *= a0;
                acc_o[mt][nt][2] *= a1; acc_o[mt][nt][3] *= a1;
            }
        }
        __syncthreads();

        if (t < 128)
            l_s[t] = l_s[t] * al_s[t]
                   + red[t * 4 + 0] + red[t * 4 + 1] + red[t * 4 + 2] + red[t * 4 + 3];

        #pragma unroll
        for (int kk = 0; kk < 16; kk++) {
            const int kx = kk * 8;
            uint32_t af[2][4], bf[4][2];
            #pragma unroll
            for (int mt = 0; mt < 2; mt++) {
                af[mt][0] = Ps[p_off + (mt * 16    ) * 132 + kx];
                af[mt][1] = Ps[p_off + (mt * 16 + 8) * 132 + kx];
                af[mt][2] = Ps[p_off + (mt * 16    ) * 132 + kx + 4];
                af[mt][3] = Ps[p_off + (mt * 16 + 8) * 132 + kx + 4];
            }
            #pragma unroll
            for (int nt = 0; nt < 4; nt++) {
                const int n = ow_n * 32 + nt * 8 + lr;
                bf[nt][0] = Vs[(kx + lc) * 72 + n];
                bf[nt][1] = Vs[(kx + lc + 4) * 72 + n];
            }
            #pragma unroll
            for (int mt = 0; mt < 2; mt++)
                #pragma unroll
                for (int nt = 0; nt < 4; nt++)
                    mma_tf32(acc_o[mt][nt], af[mt], bf[nt]);
        }
        __syncthreads();
    }

    #pragma unroll
    for (int mt = 0; mt < 2; mt++) {
        const int row0 = ow_m * 32 + mt * 16 + lr;
        const float i0 = 1.f / l_s[row0], i1 = 1.f / l_s[row0 + 8];
        #pragma unroll
        for (int nt = 0; nt < 4; nt++) {
            const int col = ow_n * 32 + nt * 8 + lc * 2;
            float* o0 = out + (size_t)(b * Sseq + q0 + row0) * Dm + h * 64 + col;
            float* o1 = out + (size_t)(b * Sseq + q0 + row0 + 8) * Dm + h * 64 + col;
            *(float2*)o0 = make_float2(acc_o[mt][nt][0] * i0, acc_o[mt][nt][1] * i0);
            *(float2*)o1 = make_float2(acc_o[mt][nt][2] * i1, acc_o[mt][nt][3] * i1);
        }
    }
}

// ---------------- block reduction helper -----------------------------------------
__device__ __forceinline__ float block_sum256(float v, float* red) {
    #pragma unroll
    for (int o = 16; o > 0; o >>= 1) v += __shfl_xor_sync(0xffffffffu, v, o);
    if ((threadIdx.x & 31) == 0) red[threadIdx.x >> 5] = v;
    __syncthreads();
    float s = red[0];
    #pragma unroll
    for (int i = 1; i < 8; i++) s += red[i];
    __syncthreads();
    return s;
}

// ---------------- residual add + layernorm ---------------------------------------
__global__ __launch_bounds__(256) void add_ln(
    const float* __restrict__ a, const float* __restrict__ b,
    const float* __restrict__ gamma, const float* __restrict__ beta,
    float* __restrict__ out)
{
    __shared__ float red[8];
    const int t = threadIdx.x;
    const size_t base = (size_t)blockIdx.x * Dm;
    float4 va = ((const float4*)(a + base))[t];
    float4 vb = ((const float4*)(b + base))[t];
    float4 s = make_float4(va.x+vb.x, va.y+vb.y, va.z+vb.z, va.w+vb.w);
    float tot = block_sum256(s.x + s.y + s.z + s.w, red);
    float mu = tot * (1.f / Dm);
    float lq = (s.x-mu)*(s.x-mu) + (s.y-mu)*(s.y-mu) + (s.z-mu)*(s.z-mu) + (s.w-mu)*(s.w-mu);
    float var = block_sum256(lq, red) * (1.f / Dm);
    float rstd = rsqrtf(var + EPSV);
    float4 gg = ((const float4*)gamma)[t];
    float4 bt = ((const float4*)beta)[t];
    float4 o;
    o.x = (s.x - mu) * rstd * gg.x + bt.x;
    o.y = (s.y - mu) * rstd * gg.y + bt.y;
    o.z = (s.z - mu) * rstd * gg.z + bt.z;
    o.w = (s.w - mu) * rstd * gg.w + bt.w;
    ((float4*)(out + base))[t] = o;
}

// ---------------- gate coefficients ----------------------------------------------
__global__ __launch_bounds__(256) void gate_coef(
    const float* __restrict__ xn, const float* __restrict__ gw, float* __restrict__ coef)
{
    __shared__ float red[16][9];
    const int t = threadIdx.x, tkn = blockIdx.x;
    float acc[16];
    #pragma unroll
    for (int ge = 0; ge < 16; ge++) acc[ge] = 0.f;
    for (int d = t; d < Dm; d += 256) {
        float xv = xn[(size_t)tkn*Dm + d];
        #pragma unroll
        for (int ge = 0; ge < 16; ge++)
            acc[ge] = fmaf(xv, gw[(size_t)(ge >> 3)*Dm*Ee + (size_t)d*Ee + (ge & 7)], acc[ge]);
    }
    #pragma unroll
    for (int ge = 0; ge < 16; ge++) {
        float v = acc[ge];
        #pragma unroll
        for (int o = 16; o > 0; o >>= 1) v += __shfl_xor_sync(0xffffffffu, v, o);
        if ((t & 31) == 0) red[ge][t >> 5] = v;
    }
    __syncthreads();
    if (t == 0) {
        float logits[16];
        #pragma unroll
        for (int ge = 0; ge < 16; ge++) {
            float s = 0.f;
            #pragma unroll
            for (int w2 = 0; w2 < 8; w2++) s += red[ge][w2];
            logits[ge] = s;
        }
        float c[8];
        #pragma unroll
        for (int e2 = 0; e2 < 8; e2++) c[e2] = 0.f;
        #pragma unroll
        for (int g = 0; g < 2; g++) {
            float m = logits[g*8];
            #pragma unroll
            for (int e2 = 1; e2 < 8; e2++) m = fmaxf(m, logits[g*8+e2]);
            float s = 0.f, pe[8];
            #pragma unroll
            for (int e2 = 0; e2 < 8; e2++) { pe[e2] = __expf(logits[g*8+e2] - m); s += pe[e2]; }
            float inv = 1.f / s;
            #pragma unroll
            for (int e2 = 0; e2 < 8; e2++) c[e2] += pe[e2] * inv;
        }
        #pragma unroll
        for (int e2 = 0; e2 < 8; e2++) coef[(size_t)tkn*8 + e2] = c[e2] * 0.5f;
    }
}

// ---------------- combine + residual + LN2 ---------------------------------------
__global__ __launch_bounds__(256) void combine_ln(
    const float* __restrict__ eo, const float* __restrict__ coef,
    const float* __restrict__ xn,
    const float* __restrict__ gamma, const float* __restrict__ beta,
    float* __restrict__ out)
{
    __shared__ float red[8];
    __shared__ float cf[8];
    const int t = threadIdx.x, tkn = blockIdx.x;
    if (t < 8) cf[t] = coef[(size_t)tkn*8 + t];
    __syncthreads();
    const size_t base = (size_t)tkn * Dm;
    float4 s = ((const float4*)(xn + base))[t];
    #pragma unroll
    for (int e2 = 0; e2 < 8; e2++) {
        float4 v = ((const float4*)(eo + ((size_t)e2*TOK + tkn)*Dm))[t];
        float c = cf[e2];
        s.x = fmaf(c, v.x, s.x); s.y = fmaf(c, v.y, s.y);
        s.z = fmaf(c, v.z, s.z); s.w = fmaf(c, v.w, s.w);
    }
    float tot = block_sum256(s.x + s.y + s.z + s.w, red);
    float mu = tot * (1.f / Dm);
    float lq = (s.x-mu)*(s.x-mu) + (s.y-mu)*(s.y-mu) + (s.z-mu)*(s.z-mu) + (s.w-mu)*(s.w-mu);
    float var = block_sum256(lq, red) * (1.f / Dm);
    float rstd = rsqrtf(var + EPSV);
    float4 gg = ((const float4*)gamma)[t];
    float4 bt = ((const float4*)beta)[t];
    float4 o;
    o.x = (s.x - mu) * rstd * gg.x + bt.x;
    o.y = (s.y - mu) * rstd * gg.y + bt.y;
    o.z = (s.z - mu) * rstd * gg.z + bt.z;
    o.w = (s.w - mu) * rstd * gg.w + bt.w;
    ((float4*)(out + base))[t] = o;
}

// ---------------- launch ----------------------------------------------------------
extern "C" void kernel_launch(void* const* d_in, const int* in_sizes, int n_in,
                              void* d_out, int out_size)
{
    const float* x     = (const float*)d_in[0];
    const float* wq    = (const float*)d_in[1];
    const float* bq    = (const float*)d_in[2];
    const float* wk    = (const float*)d_in[3];
    const float* bk    = (const float*)d_in[4];
    const float* wv    = (const float*)d_in[5];
    const float* bv    = (const float*)d_in[6];
    const float* wo    = (const float*)d_in[7];
    const float* bo    = (const float*)d_in[8];
    const float* ln1g  = (const float*)d_in[9];
    const float* ln1b  = (const float*)d_in[10];
    const float* ln2g  = (const float*)d_in[11];
    const float* ln2b  = (const float*)d_in[12];
    const float* gatew = (const float*)d_in[13];
    const float* ew1   = (const float*)d_in[14];
    const float* eb1   = (const float*)d_in[15];
    const float* ew2   = (const float*)d_in[16];
    const float* eb2   = (const float*)d_in[17];
    float* out = (float*)d_out;

    float *qkv, *attn, *proj, *normed, *eo, *coef, *bqkv;
    __half *h, *wqkvt, *wot, *w1t, *w2t;
    cudaGetSymbolAddress((void**)&qkv,    g_qkv);
    cudaGetSymbolAddress((void**)&attn,   g_attn);
    cudaGetSymbolAddress((void**)&proj,   g_proj);
    cudaGetSymbolAddress((void**)&normed, g_normed);
    cudaGetSymbolAddress((void**)&h,      g_h);
    cudaGetSymbolAddress((void**)&eo,     g_eo);
    cudaGetSymbolAddress((void**)&coef,   g_coef);
    cudaGetSymbolAddress((void**)&wqkvt,  g_wqkvt);
    cudaGetSymbolAddress((void**)&bqkv,   g_bqkv);
    cudaGetSymbolAddress((void**)&wot,    g_wot);
    cudaGetSymbolAddress((void**)&w1t,    g_w1t);
    cudaGetSymbolAddress((void**)&w2t,    g_w2t);

    cudaFuncSetAttribute((const void*)mma_gemm<false,false,false>,
                         cudaFuncAttributeMaxDynamicSharedMemorySize, SMEM_GEMM_BYTES);
    cudaFuncSetAttribute((const void*)mma_gemm<true,false,true>,
                         cudaFuncAttributeMaxDynamicSharedMemorySize, SMEM_GEMM_BYTES);
    cudaFuncSetAttribute((const void*)mma_gemm<false,true,false>,
                         cudaFuncAttributeMaxDynamicSharedMemorySize, SMEM_GEMM_BYTES);
    cudaFuncSetAttribute((const void*)fused_attn,
                         cudaFuncAttributeMaxDynamicSharedMemorySize, FA_BYTES);

    dim3 blk(256);

    // weight transposes (fp32 -> fp16) + bias concat
    transpose64h<<<dim3(16, 16, 1), blk>>>(wq, wqkvt,           Dm, Dm);
    transpose64h<<<dim3(16, 16, 1), blk>>>(wk, wqkvt + Dm*Dm,   Dm, Dm);
    transpose64h<<<dim3(16, 16, 1), blk>>>(wv, wqkvt + 2*Dm*Dm, Dm, Dm);
    concat3<<<4, 256>>>(bq, bk, bv, bqkv, Dm);
    transpose64h<<<dim3(16, 16, 1), blk>>>(wo, wot,             Dm, Dm);

    // batched QKV GEMM (fp16 mma, fp16 weights)
    mma_gemm<false,false,false><<<dim3(8, 16, 3), blk, SMEM_GEMM_BYTES>>>(
        x, wqkvt, bqkv, qkv, TOK, Dm, Dm,
        0, (long long)Dm*Dm, (long long)Dm, (long long)TOK*Dm);

    // MoE weight transposes (independent)
    transpose64h<<<dim3(Vv/64, Dm/64, Ee), blk>>>(ew1, w1t, Dm, Vv);
    transpose64h<<<dim3(Dm/64, Vv/64, Ee), blk>>>(ew2, w2t, Vv, Dm);

    // fused flash attention (tf32)
    fused_attn<<<dim3(8, 32), blk, FA_BYTES>>>(
        qkv, qkv + (size_t)TOK*Dm, qkv + (size_t)2*TOK*Dm, attn);

    // output projection + residual + LN1
    mma_gemm<false,false,false><<<dim3(8, 16, 1), blk, SMEM_GEMM_BYTES>>>(
        attn, wot, bo, proj, TOK, Dm, Dm, 0, 0, 0, 0);
    add_ln<<<TOK, blk>>>(proj, x, ln1g, ln1b, normed);

    // MoE: w1 (fp16 out h), w2 (fp16 in h)
    gate_coef<<<TOK, blk>>>(normed, gatew, coef);
    mma_gemm<true,false,true><<<dim3(32, 16, Ee), blk, SMEM_GEMM_BYTES>>>(
        normed, w1t, eb1, h, TOK, Vv, Dm,
        0, (long long)Vv*Dm, (long long)Vv, (long long)TOK*Vv);
    mma_gemm<false,true,false><<<dim3(8, 16, Ee), blk, SMEM_GEMM_BYTES>>>(
        h, w2t, eb2, eo, TOK, Dm, Vv,
        (long long)TOK*Vv, (long long)Dm*Vv, (long long)Dm, (long long)TOK*Dm);

    // combine + residual + LN2
    combine_ln<<<TOK, blk>>>(eo, coef, normed, ln2g, ln2b, out);
}